// round 9
// baseline (speedup 1.0000x reference)
#include <cuda_runtime.h>
#include <cuda_bf16.h>
#include <math.h>
#include <stdint.h>

// Problem dims
#define VOCAB 32000
#define HDIM  1024
#define EDIM  512
#define BATCH 32
#define TSEQ  64
#define IMGF  2048
#define G4    (4*HDIM)          // 4096
#define MROWS (BATCH*TSEQ)      // 2048
#define NBLK  128               // persistent recurrence CTAs
#define QMAX  16256.0f          // 127*128

// ---------------- device scratch (no allocation allowed) ----------------
__device__ float g_pre [MROWS * G4];     // time-major: [t][b][G4]
__device__ unsigned g_bar_ctr;

// bf16 hi/lo activations (A operand) + lstm-path weights
__device__ __nv_bfloat16 g_ah [MROWS * HDIM];
__device__ __nv_bfloat16 g_al [MROWS * HDIM];
__device__ __nv_bfloat16 g_w0h[G4 * EDIM];
__device__ __nv_bfloat16 g_w0l[G4 * EDIM];
__device__ __nv_bfloat16 g_w1h[G4 * HDIM];
__device__ __nv_bfloat16 g_w1l[G4 * HDIM];

// int8 Ozaki digits for FC
__device__ int8_t g_a1[MROWS * HDIM];
__device__ int8_t g_a2[MROWS * HDIM];
__device__ int8_t g_b1[VOCAB * HDIM];
__device__ int8_t g_b2[VOCAB * HDIM];
__device__ float  g_sa[MROWS];
__device__ float  g_sb[VOCAB];

// ======================= helpers =========================================
__device__ __forceinline__ uint32_t smem_u32(const void* p) {
    uint32_t a;
    asm("{ .reg .u64 t; cvta.to.shared.u64 t, %1; cvt.u32.u64 %0, t; }"
        : "=r"(a) : "l"(p));
    return a;
}
#define SWZ(x) ((x) ^ (((x) >> 3) & 0x70))

__device__ __forceinline__ void cpa16(uint32_t dst, const void* src) {
    asm volatile("cp.async.cg.shared.global [%0], [%1], 16;"
                 :: "r"(dst), "l"(src) : "memory");
}
#define CP_COMMIT() asm volatile("cp.async.commit_group;" ::: "memory")
#define CP_WAIT0()  asm volatile("cp.async.wait_group 0;" ::: "memory")
#define CP_WAIT1()  asm volatile("cp.async.wait_group 1;" ::: "memory")
#define CP_WAIT2()  asm volatile("cp.async.wait_group 2;" ::: "memory")

__device__ __forceinline__ void ldsm_x4(uint32_t* r, uint32_t addr) {
    asm volatile("ldmatrix.sync.aligned.m8n8.x4.shared.b16 {%0,%1,%2,%3}, [%4];"
                 : "=r"(r[0]), "=r"(r[1]), "=r"(r[2]), "=r"(r[3]) : "r"(addr));
}
__device__ __forceinline__ void mma_bf16(float* c, const uint32_t* a, const uint32_t* b) {
    asm volatile(
        "mma.sync.aligned.m16n8k16.row.col.f32.bf16.bf16.f32 "
        "{%0,%1,%2,%3}, {%4,%5,%6,%7}, {%8,%9}, {%0,%1,%2,%3};"
        : "+f"(c[0]), "+f"(c[1]), "+f"(c[2]), "+f"(c[3])
        : "r"(a[0]), "r"(a[1]), "r"(a[2]), "r"(a[3]), "r"(b[0]), "r"(b[1]));
}
__device__ __forceinline__ void mma_s8(int* c, const uint32_t* a, const uint32_t* b) {
    asm volatile(
        "mma.sync.aligned.m16n8k32.row.col.s32.s8.s8.s32 "
        "{%0,%1,%2,%3}, {%4,%5,%6,%7}, {%8,%9}, {%0,%1,%2,%3};"
        : "+r"(c[0]), "+r"(c[1]), "+r"(c[2]), "+r"(c[3])
        : "r"(a[0]), "r"(a[1]), "r"(a[2]), "r"(a[3]), "r"(b[0]), "r"(b[1]));
}
__device__ __forceinline__ void split_hilo(float x, __nv_bfloat16& h, __nv_bfloat16& l) {
    h = __float2bfloat16(x);
    l = __float2bfloat16(x - __bfloat162float(h));
}

// ============== fp32 -> bf16 hi/lo split conversion (weights) ============
__global__ void cvt_hilo(const float* __restrict__ x,
                         __nv_bfloat16* __restrict__ hi,
                         __nv_bfloat16* __restrict__ lo, int n)
{
    int i = (blockIdx.x * 256 + threadIdx.x) * 4;
    if (i >= n) return;
    float4 v = *(const float4*)(x + i);
    __nv_bfloat16 h0, h1, h2, h3, l0, l1, l2, l3;
    split_hilo(v.x, h0, l0); split_hilo(v.y, h1, l1);
    split_hilo(v.z, h2, l2); split_hilo(v.w, h3, l3);
    __nv_bfloat162 ph0; ph0.x = h0; ph0.y = h1;
    __nv_bfloat162 ph1; ph1.x = h2; ph1.y = h3;
    __nv_bfloat162 pl0; pl0.x = l0; pl0.y = l1;
    __nv_bfloat162 pl1; pl1.x = l2; pl1.y = l3;
    *(__nv_bfloat162*)(hi + i)     = ph0;
    *(__nv_bfloat162*)(hi + i + 2) = ph1;
    *(__nv_bfloat162*)(lo + i)     = pl0;
    *(__nv_bfloat162*)(lo + i + 2) = pl1;
}

// ============== row quantization: fp32 -> 2x int8 digits + scale ========
// one block per row of K=1024; 256 threads x 4 elems.
__device__ __forceinline__ void quant4(const float* xv, float inv, float s128,
                                       int8_t* d1o, int8_t* d2o)
{
    #pragma unroll
    for (int q = 0; q < 4; q++) {
        float qq = rintf(xv[q] * inv);              // |qq| <= 16256
        float d1 = rintf(qq * (1.0f / 128.0f));     // [-127,127]
        float d2 = qq - d1 * 128.0f;                // [-64,64]
        d1o[q] = (int8_t)__float2int_rn(d1);
        d2o[q] = (int8_t)__float2int_rn(d2);
    }
}

__global__ void quant_f32(const float* __restrict__ X,
                          int8_t* __restrict__ D1, int8_t* __restrict__ D2,
                          float* __restrict__ S)
{
    __shared__ float red[8];
    const size_t row = blockIdx.x;
    const int tid = threadIdx.x;
    const float* xr = X + row * HDIM;
    float4 v = *(const float4*)(xr + tid * 4);
    float xv[4] = {v.x, v.y, v.z, v.w};
    float m = fmaxf(fmaxf(fabsf(xv[0]), fabsf(xv[1])),
                    fmaxf(fabsf(xv[2]), fabsf(xv[3])));
    #pragma unroll
    for (int o = 16; o > 0; o >>= 1) m = fmaxf(m, __shfl_xor_sync(~0u, m, o));
    if ((tid & 31) == 0) red[tid >> 5] = m;
    __syncthreads();
    float mm = fmaxf(fmaxf(red[0], red[1]), fmaxf(red[2], red[3]));
    mm = fmaxf(mm, fmaxf(fmaxf(red[4], red[5]), fmaxf(red[6], red[7])));
    float s   = (mm > 0.f) ? mm / QMAX : 1.0f;
    float inv = (mm > 0.f) ? QMAX / mm : 0.0f;
    if (tid == 0) S[row] = s;
    int8_t d1[4], d2[4];
    quant4(xv, inv, s, d1, d2);
    *(int*)(D1 + row * HDIM + tid * 4) = *(int*)d1;
    *(int*)(D2 + row * HDIM + tid * 4) = *(int*)d2;
}

__global__ void quant_bf16pair(const __nv_bfloat16* __restrict__ AH,
                               const __nv_bfloat16* __restrict__ AL,
                               int8_t* __restrict__ D1, int8_t* __restrict__ D2,
                               float* __restrict__ S)
{
    __shared__ float red[8];
    const size_t row = blockIdx.x;
    const int tid = threadIdx.x;
    const __nv_bfloat16* hr = AH + row * HDIM + tid * 4;
    const __nv_bfloat16* lr = AL + row * HDIM + tid * 4;
    float xv[4];
    #pragma unroll
    for (int q = 0; q < 4; q++)
        xv[q] = __bfloat162float(hr[q]) + __bfloat162float(lr[q]);
    float m = fmaxf(fmaxf(fabsf(xv[0]), fabsf(xv[1])),
                    fmaxf(fabsf(xv[2]), fabsf(xv[3])));
    #pragma unroll
    for (int o = 16; o > 0; o >>= 1) m = fmaxf(m, __shfl_xor_sync(~0u, m, o));
    if ((tid & 31) == 0) red[tid >> 5] = m;
    __syncthreads();
    float mm = fmaxf(fmaxf(red[0], red[1]), fmaxf(red[2], red[3]));
    mm = fmaxf(mm, fmaxf(fmaxf(red[4], red[5]), fmaxf(red[6], red[7])));
    float s   = (mm > 0.f) ? mm / QMAX : 1.0f;
    float inv = (mm > 0.f) ? QMAX / mm : 0.0f;
    if (tid == 0) S[row] = s;
    int8_t d1[4], d2[4];
    quant4(xv, inv, s, d1, d2);
    *(int*)(D1 + row * HDIM + tid * 4) = *(int*)d1;
    *(int*)(D2 + row * HDIM + tid * 4) = *(int*)d2;
}

// ============== HMMA bf16x3 GEMM (pre-GEMMs): C = A*B^T + bias ===========
#define TEN_T 16384
#define STAGE (4*TEN_T)
__global__ void __launch_bounds__(256, 1)
gemm_bf16x3(const __nv_bfloat16* __restrict__ Ah, const __nv_bfloat16* __restrict__ Al,
            const __nv_bfloat16* __restrict__ Bh, const __nv_bfloat16* __restrict__ Bl,
            float* __restrict__ C, int M, int N, int K,
            const float* __restrict__ bias1, const float* __restrict__ bias2,
            int permute)
{
    extern __shared__ char dsm[];
    const int tid  = threadIdx.x;
    const int wid  = tid >> 5;
    const int lane = tid & 31;
    const int bm = blockIdx.x * 128;
    const int bn = blockIdx.y * 128;
    const int wm = (wid & 3) * 32;
    const int wn = (wid >> 2) * 64;
    const int nk = K >> 6;

    if (blockIdx.x == 0 && blockIdx.y == 0 && tid == 0) g_bar_ctr = 0u;

    uint32_t dyn = smem_u32(dsm);
    uint32_t sb0 = (dyn + 1023u) & ~1023u;

    float acc[2][8][4];
    #pragma unroll
    for (int i = 0; i < 2; i++)
        #pragma unroll
        for (int j = 0; j < 8; j++)
            #pragma unroll
            for (int r = 0; r < 4; r++) acc[i][j][r] = 0.f;

    auto issue_load = [&](int kt, int stg) {
        const uint32_t st = sb0 + (uint32_t)stg * STAGE;
        const size_t koff = (size_t)kt * 64;
        #pragma unroll
        for (int i = 0; i < 16; i++) {
            int id = i * 256 + tid;
            int tensor = id >> 10;
            int cid = id & 1023;
            int r = cid >> 3, c = cid & 7;
            uint32_t dst = st + tensor * TEN_T + SWZ((uint32_t)(r * 128 + c * 16));
            const __nv_bfloat16* src;
            if (tensor == 0)      src = Ah + (size_t)(bm + r) * K + koff + c * 8;
            else if (tensor == 1) src = Al + (size_t)(bm + r) * K + koff + c * 8;
            else if (tensor == 2) src = Bh + (size_t)(bn + r) * K + koff + c * 8;
            else                  src = Bl + (size_t)(bn + r) * K + koff + c * 8;
            cpa16(dst, src);
        }
        CP_COMMIT();
    };

    issue_load(0, 0);
    if (nk > 1) issue_load(1, 1);

    const int a_row = wm + (lane & 15);
    const int a_k8  = (lane >> 4) * 8;
    const int b_row = wn + ((lane >> 4) & 1) * 8 + (lane & 7);
    const int b_k8  = ((lane >> 3) & 1) * 8;

    uint32_t aH[2][2][4], aL[2][2][4], bH[2][4][4], bL[2][4][4];

    int s_cur = 0, s_nxt = 2;
    for (int kt = 0; kt < nk; kt++) {
        if (kt + 1 < nk) { CP_WAIT1(); } else { CP_WAIT0(); }
        __syncthreads();
        if (kt + 2 < nk) issue_load(kt + 2, s_nxt);

        const uint32_t st  = sb0 + (uint32_t)s_cur * STAGE;
        const uint32_t sAh = st;
        const uint32_t sAl = st + TEN_T;
        const uint32_t sBh = st + 2 * TEN_T;
        const uint32_t sBl = st + 3 * TEN_T;

        auto load_frags = [&](int buf, int ksv) {
            const int kb = ksv * 16;
            #pragma unroll
            for (int mi = 0; mi < 2; mi++) {
                uint32_t off = SWZ((uint32_t)((a_row + mi * 16) * 128 + (kb + a_k8) * 2));
                ldsm_x4(aH[buf][mi], sAh + off);
                ldsm_x4(aL[buf][mi], sAl + off);
            }
            #pragma unroll
            for (int p = 0; p < 4; p++) {
                uint32_t off = SWZ((uint32_t)((b_row + p * 16) * 128 + (kb + b_k8) * 2));
                ldsm_x4(bH[buf][p], sBh + off);
                ldsm_x4(bL[buf][p], sBl + off);
            }
        };

        load_frags(0, 0);
        #pragma unroll
        for (int ks = 0; ks < 4; ks++) {
            const int cb = ks & 1;
            if (ks < 3) load_frags(cb ^ 1, ks + 1);
            #pragma unroll
            for (int mi = 0; mi < 2; mi++)
                #pragma unroll
                for (int p = 0; p < 4; p++)
                    #pragma unroll
                    for (int j = 0; j < 2; j++)
                        mma_bf16(acc[mi][p * 2 + j], aH[cb][mi], &bH[cb][p][j * 2]);
            #pragma unroll
            for (int mi = 0; mi < 2; mi++)
                #pragma unroll
                for (int p = 0; p < 4; p++)
                    #pragma unroll
                    for (int j = 0; j < 2; j++)
                        mma_bf16(acc[mi][p * 2 + j], aH[cb][mi], &bL[cb][p][j * 2]);
            #pragma unroll
            for (int mi = 0; mi < 2; mi++)
                #pragma unroll
                for (int p = 0; p < 4; p++)
                    #pragma unroll
                    for (int j = 0; j < 2; j++)
                        mma_bf16(acc[mi][p * 2 + j], aL[cb][mi], &bH[cb][p][j * 2]);
        }

        s_cur = (s_cur == 2) ? 0 : s_cur + 1;
        s_nxt = (s_nxt == 2) ? 0 : s_nxt + 1;
    }

    #pragma unroll
    for (int nj = 0; nj < 8; nj++) {
        const int col = bn + wn + nj * 8 + (lane & 3) * 2;
        float b0 = 0.f, b1 = 0.f;
        if (bias1) { b0 += bias1[col]; b1 += bias1[col + 1]; }
        if (bias2) { b0 += bias2[col]; b1 += bias2[col + 1]; }
        #pragma unroll
        for (int mi = 0; mi < 2; mi++) {
            const int r0 = bm + wm + mi * 16 + (lane >> 2);
            const int r1 = r0 + 8;
            int o0 = permute ? ((r0 & 63) * 32 + (r0 >> 6)) : r0;
            int o1 = permute ? ((r1 & 63) * 32 + (r1 >> 6)) : r1;
            float2 v0 = make_float2(acc[mi][nj][0] + b0, acc[mi][nj][1] + b1);
            float2 v1 = make_float2(acc[mi][nj][2] + b0, acc[mi][nj][3] + b1);
            *(float2*)(C + (size_t)o0 * N + col) = v0;
            *(float2*)(C + (size_t)o1 * N + col) = v1;
        }
    }
}

// ============== IMMA int8 Ozaki GEMM (FC): C = sa*sb*(A*B^T) + bias ======
// CTA 128x128, 256 thr (8 warps 4x2), warp tile 32x64, K-chunk 128 int8.
// C = sa[m]*sb[n]*(16384*P11 + 128*(P12+P21)); P22 dropped (~8e-5 rel).
#define QT 16384                    // 128 rows x 128B int8
#define QSTAGE (4*QT)               // A1|A2|B1|B2 = 64KB
__global__ void __launch_bounds__(256, 1)
gemm_s8(const int8_t* __restrict__ A1, const int8_t* __restrict__ A2,
        const int8_t* __restrict__ B1, const int8_t* __restrict__ B2,
        const float* __restrict__ SA, const float* __restrict__ SB,
        float* __restrict__ C, int M, int N, int K,
        const float* __restrict__ bias)
{
    extern __shared__ char dsm[];
    const int tid  = threadIdx.x;
    const int wid  = tid >> 5;
    const int lane = tid & 31;
    const int bm = blockIdx.x * 128;
    const int bn = blockIdx.y * 128;
    const int wm = (wid & 3) * 32;
    const int wn = (wid >> 2) * 64;
    const int nk = K >> 7;           // 128 int8 per chunk

    uint32_t dyn = smem_u32(dsm);
    uint32_t sb0 = (dyn + 1023u) & ~1023u;

    int hi[2][8][4], md[2][8][4];
    #pragma unroll
    for (int i = 0; i < 2; i++)
        #pragma unroll
        for (int j = 0; j < 8; j++)
            #pragma unroll
            for (int r = 0; r < 4; r++) { hi[i][j][r] = 0; md[i][j][r] = 0; }

    auto issue_load = [&](int kt, int stg) {
        const uint32_t st = sb0 + (uint32_t)stg * QSTAGE;
        const size_t koff = (size_t)kt * 128;
        #pragma unroll
        for (int i = 0; i < 16; i++) {
            int id = i * 256 + tid;
            int tensor = id >> 10;              // A1 A2 B1 B2
            int cid = id & 1023;
            int r = cid >> 3, c = cid & 7;
            uint32_t dst = st + tensor * QT + SWZ((uint32_t)(r * 128 + c * 16));
            const int8_t* src;
            if (tensor == 0)      src = A1 + (size_t)(bm + r) * K + koff + c * 16;
            else if (tensor == 1) src = A2 + (size_t)(bm + r) * K + koff + c * 16;
            else if (tensor == 2) src = B1 + (size_t)(bn + r) * K + koff + c * 16;
            else                  src = B2 + (size_t)(bn + r) * K + koff + c * 16;
            cpa16(dst, src);
        }
        CP_COMMIT();
    };

    issue_load(0, 0);
    if (nk > 1) issue_load(1, 1);

    // int8 fragment addressing (byte-doubled twin of the bf16 layout)
    const int a_row  = wm + (lane & 15);
    const int a_k16  = (lane >> 4) * 16;            // byte offset
    const int b_row  = wn + ((lane >> 4) & 1) * 8 + (lane & 7);
    const int b_k16  = ((lane >> 3) & 1) * 16;      // byte offset

    uint32_t a1f[2][2][4], a2f[2][2][4], b1f[2][4][4], b2f[2][4][4];

    int s_cur = 0, s_nxt = 2;
    for (int kt = 0; kt < nk; kt++) {
        if (kt + 1 < nk) { CP_WAIT1(); } else { CP_WAIT0(); }
        __syncthreads();
        if (kt + 2 < nk) issue_load(kt + 2, s_nxt);

        const uint32_t st  = sb0 + (uint32_t)s_cur * QSTAGE;
        const uint32_t sA1 = st;
        const uint32_t sA2 = st + QT;
        const uint32_t sB1 = st + 2 * QT;
        const uint32_t sB2 = st + 3 * QT;

        auto load_frags = [&](int buf, int ksv) {
            const int kb = ksv * 32;                // bytes per k32 step
            #pragma unroll
            for (int mi = 0; mi < 2; mi++) {
                uint32_t off = SWZ((uint32_t)((a_row + mi * 16) * 128 + kb + a_k16));
                ldsm_x4(a1f[buf][mi], sA1 + off);
                ldsm_x4(a2f[buf][mi], sA2 + off);
            }
            #pragma unroll
            for (int p = 0; p < 4; p++) {
                uint32_t off = SWZ((uint32_t)((b_row + p * 16) * 128 + kb + b_k16));
                ldsm_x4(b1f[buf][p], sB1 + off);
                ldsm_x4(b2f[buf][p], sB2 + off);
            }
        };

        load_frags(0, 0);
        #pragma unroll
        for (int ks = 0; ks < 4; ks++) {
            const int cb = ks & 1;
            if (ks < 3) load_frags(cb ^ 1, ks + 1);
            #pragma unroll
            for (int mi = 0; mi < 2; mi++)
                #pragma unroll
                for (int p = 0; p < 4; p++)
                    #pragma unroll
                    for (int j = 0; j < 2; j++)
                        mma_s8(hi[mi][p * 2 + j], a1f[cb][mi], &b1f[cb][p][j * 2]);
            #pragma unroll
            for (int mi = 0; mi < 2; mi++)
                #pragma unroll
                for (int p = 0; p < 4; p++)
                    #pragma unroll
                    for (int j = 0; j < 2; j++)
                        mma_s8(md[mi][p * 2 + j], a1f[cb][mi], &b2f[cb][p][j * 2]);
            #pragma unroll
            for (int mi = 0; mi < 2; mi++)
                #pragma unroll
                for (int p = 0; p < 4; p++)
                    #pragma unroll
                    for (int j = 0; j < 2; j++)
                        mma_s8(md[mi][p * 2 + j], a2f[cb][mi], &b1f[cb][p][j * 2]);
        }

        s_cur = (s_cur == 2) ? 0 : s_cur + 1;
        s_nxt = (s_nxt == 2) ? 0 : s_nxt + 1;
    }

    #pragma unroll
    for (int nj = 0; nj < 8; nj++) {
        const int col = bn + wn + nj * 8 + (lane & 3) * 2;
        const float sb_0 = SB[col], sb_1 = SB[col + 1];
        const float bb0 = bias[col], bb1 = bias[col + 1];
        #pragma unroll
        for (int mi = 0; mi < 2; mi++) {
            const int r0 = bm + wm + mi * 16 + (lane >> 2);
            const float sa0 = SA[r0], sa1 = SA[r0 + 8];
            const int* h4 = hi[mi][nj];
            const int* m4 = md[mi][nj];
            float2 v0, v1;
            v0.x = sa0 * sb_0 * (16384.f * (float)h4[0] + 128.f * (float)m4[0]) + bb0;
            v0.y = sa0 * sb_1 * (16384.f * (float)h4[1] + 128.f * (float)m4[1]) + bb1;
            v1.x = sa1 * sb_0 * (16384.f * (float)h4[2] + 128.f * (float)m4[2]) + bb0;
            v1.y = sa1 * sb_1 * (16384.f * (float)h4[3] + 128.f * (float)m4[3]) + bb1;
            *(float2*)(C + (size_t)r0 * N + col)       = v0;
            *(float2*)(C + (size_t)(r0 + 8) * N + col) = v1;
        }
    }
}

// ---------------- linear(2048->512) + batchnorm -> bf16 hi/lo ------------
__global__ void linbn_kernel(const float* __restrict__ img,
                             const float* __restrict__ W,
                             const float* __restrict__ bias,
                             const float* __restrict__ gamma,
                             const float* __restrict__ beta,
                             __nv_bfloat16* __restrict__ ah,
                             __nv_bfloat16* __restrict__ al)
{
    const int e   = blockIdx.x;
    const int tid = threadIdx.x;
    __shared__ float wrow[IMGF];
    __shared__ float xv[BATCH];

    {
        const float* wsrc = W + (size_t)e * IMGF;
        #pragma unroll
        for (int i = 0; i < 2; i++) {
            int k = (tid + i * 256) * 4;
            *(float4*)&wrow[k] = *(const float4*)(wsrc + k);
        }
    }
    __syncthreads();

    const int lane = tid & 31, wid = tid >> 5;
    float a0 = 0.f, a1 = 0.f, a2 = 0.f, a3 = 0.f;
    for (int k = lane; k < IMGF; k += 32) {
        float wv = wrow[k];
        a0 += img[(size_t)(wid +  0) * IMGF + k] * wv;
        a1 += img[(size_t)(wid +  8) * IMGF + k] * wv;
        a2 += img[(size_t)(wid + 16) * IMGF + k] * wv;
        a3 += img[(size_t)(wid + 24) * IMGF + k] * wv;
    }
    #pragma unroll
    for (int o = 16; o > 0; o >>= 1) {
        a0 += __shfl_xor_sync(0xffffffffu, a0, o);
        a1 += __shfl_xor_sync(0xffffffffu, a1, o);
        a2 += __shfl_xor_sync(0xffffffffu, a2, o);
        a3 += __shfl_xor_sync(0xffffffffu, a3, o);
    }
    if (lane == 0) {
        float bb = bias[e];
        xv[wid +  0] = a0 + bb;
        xv[wid +  8] = a1 + bb;
        xv[wid + 16] = a2 + bb;
        xv[wid + 24] = a3 + bb;
    }
    __syncthreads();

    if (tid < 32) {
        float x = xv[tid];
        float s = x, q = x * x;
        #pragma unroll
        for (int o = 16; o > 0; o >>= 1) {
            s += __shfl_xor_sync(0xffffffffu, s, o);
            q += __shfl_xor_sync(0xffffffffu, q, o);
        }
        float mu  = s * (1.f / 32.f);
        float var = q * (1.f / 32.f) - mu * mu;
        float inv = rsqrtf(var + 1e-5f);
        float y = gamma[e] * (x - mu) * inv + beta[e];
        __nv_bfloat16 h, l;
        split_hilo(y, h, l);
        size_t idx = ((size_t)tid * TSEQ + 0) * EDIM + e;
        ah[idx] = h;
        al[idx] = l;
    }
}

// ---------------- embedding gather -> bf16 hi/lo rows t>=1 ---------------
__global__ void gather_kernel(const int* __restrict__ cap,
                              const float* __restrict__ emb,
                              __nv_bfloat16* __restrict__ ah,
                              __nv_bfloat16* __restrict__ al)
{
    const int t = blockIdx.x + 1;
    const int b = blockIdx.y;
    const int tok = cap[b * TSEQ + (t - 1)];
    const int k = threadIdx.x * 4;
    float4 v = *(const float4*)(emb + (size_t)tok * EDIM + k);
    __nv_bfloat16 h0, h1, h2, h3, l0, l1, l2, l3;
    split_hilo(v.x, h0, l0); split_hilo(v.y, h1, l1);
    split_hilo(v.z, h2, l2); split_hilo(v.w, h3, l3);
    __nv_bfloat162 ph0; ph0.x = h0; ph0.y = h1;
    __nv_bfloat162 ph1; ph1.x = h2; ph1.y = h3;
    __nv_bfloat162 pl0; pl0.x = l0; pl0.y = l1;
    __nv_bfloat162 pl1; pl1.x = l2; pl1.y = l3;
    size_t row = ((size_t)b * TSEQ + t) * EDIM + k;
    *(__nv_bfloat162*)(ah + row)     = ph0;
    *(__nv_bfloat162*)(ah + row + 2) = ph1;
    *(__nv_bfloat162*)(al + row)     = pl0;
    *(__nv_bfloat162*)(al + row + 2) = pl1;
}

// ---------------- persistent HMMA LSTM layer ------------------------------
__global__ void __launch_bounds__(256, 1)
lstm_persist(const float* __restrict__ pre,   // [T][B][G4]
             const float* __restrict__ Whh,   // [G4][HDIM]
             __nv_bfloat16* __restrict__ ah,  // [b*T+t][HDIM]
             __nv_bfloat16* __restrict__ al)
{
    extern __shared__ char sm_raw[];
    uint32_t raw = smem_u32(sm_raw);
    uint32_t sbase = (raw + 127u) & ~127u;
    char* base = sm_raw + (sbase - raw);
    const uint32_t W_HI = 0;
    const uint32_t W_LO = 65536;
    const uint32_t HBUF = 131072;            // 4 stages x 16KB
    float* g_s = (float*)(base + 196608);    // [32][33]

    const int tid  = threadIdx.x;
    const int wid  = tid >> 5;
    const int lane = tid & 31;
    const int u0   = blockIdx.x * 8;

    #pragma unroll
    for (int i = 0; i < 16; i++) {
        int cell = i * 256 + tid;
        int kt = cell >> 8;
        int r  = (cell >> 3) & 31;
        int cc = cell & 7;
        int jrow = (r >> 3) * HDIM + u0 + (r & 7);
        const float* src = Whh + (size_t)jrow * HDIM + kt * 64 + cc * 8;
        float4 v0 = *(const float4*)src;
        float4 v1 = *(const float4*)(src + 4);
        float f[8] = {v0.x, v0.y, v0.z, v0.w, v1.x, v1.y, v1.z, v1.w};
        uint32_t hi4[4], lo4[4];
        #pragma unroll
        for (int q = 0; q < 4; q++) {
            __nv_bfloat16 h0, l0, h1, l1;
            split_hilo(f[2*q],   h0, l0);
            split_hilo(f[2*q+1], h1, l1);
            __nv_bfloat162 hp; hp.x = h0; hp.y = h1;
            __nv_bfloat162 lp; lp.x = l0; lp.y = l1;
            hi4[q] = *(uint32_t*)&hp;
            lo4[q] = *(uint32_t*)&lp;
        }
        uint32_t off = kt * 4096 + SWZ((uint32_t)(r * 128 + cc * 16));
        *(uint4*)(base + W_HI + off) = make_uint4(hi4[0], hi4[1], hi4[2], hi4[3]);
        *(uint4*)(base + W_LO + off) = make_uint4(lo4[0], lo4[1], lo4[2], lo4[3]);
    }
    __syncthreads();

    const int wm = (wid & 1) * 16;
    const int wn = (wid >> 1) * 8;
    const int a_row = wm + (lane & 15);
    const int a_k8  = (lane >> 4) * 8;
    const int b_row = wn + (lane & 7);
    const int b_ku  = (lane >> 3) & 3;

    const int hr = tid >> 3;
    const int hc = tid & 7;
    const uint32_t hswz = SWZ((uint32_t)(hr * 128 + hc * 16));

    const int pb = tid >> 3;
    const int pu = tid & 7;

    const int jloc = wn + (lane & 3) * 2;
    const int jrow_e = (jloc >> 3) * HDIM + u0 + (jloc & 7);
    const int br = wm + (lane >> 2);

    float c_reg = 0.f;
    unsigned gen = 0;

    for (int t = 0; t < TSEQ; t++) {
        float acc[4] = {0.f, 0.f, 0.f, 0.f};

        const float* pt = pre + (size_t)t * BATCH * G4;
        float2 p0 = *(const float2*)(pt + (size_t)br * G4 + jrow_e);
        float2 p1 = *(const float2*)(pt + (size_t)(br + 8) * G4 + jrow_e);

        if (t > 0) {
            const size_t hrow_base = ((size_t)hr * TSEQ + (t - 1)) * HDIM + hc * 8;
            auto issue_chunk = [&](int c) {
                const uint32_t d = sbase + HBUF + (c & 3) * 16384 + hswz;
                const size_t g = hrow_base + (size_t)c * 128;
                cpa16(d,         ah + g);
                cpa16(d + 4096,  ah + g + 64);
                cpa16(d + 8192,  al + g);
                cpa16(d + 12288, al + g + 64);
                CP_COMMIT();
            };
            issue_chunk(0);
            issue_chunk(1);
            issue_chunk(2);
            for (int c = 0; c < 8; c++) {
                if (c < 6) { CP_WAIT2(); }
                else if (c == 6) { CP_WAIT1(); }
                else { CP_WAIT0(); }
                __syncthreads();
                const uint32_t stg = sbase + HBUF + (c & 3) * 16384;
                #pragma unroll
                for (int sub = 0; sub < 2; sub++) {
                    const uint32_t wc = (uint32_t)(2 * c + sub) * 4096;
                    const uint32_t hb_hi = stg + sub * 4096;
                    const uint32_t hb_lo = stg + 8192 + sub * 4096;
                    #pragma unroll
                    for (int kk2 = 0; kk2 < 2; kk2++) {
                        uint32_t bH4[4], bL4[4];
                        uint32_t boff = wc + SWZ((uint32_t)(b_row * 128 + kk2 * 64 + b_ku * 16));
                        ldsm_x4(bH4, sbase + W_HI + boff);
                        ldsm_x4(bL4, sbase + W_LO + boff);
                        #pragma unroll
                        for (int kh = 0; kh < 2; kh++) {
                            const int ks = kk2 * 2 + kh;
                            uint32_t aH4[4], aL4[4];
                            uint32_t aoff = SWZ((uint32_t)(a_row * 128 + ks * 32 + a_k8 * 2));
                            ldsm_x4(aH4, hb_hi + aoff);
                            ldsm_x4(aL4, hb_lo + aoff);
                            mma_bf16(acc, aH4, &bH4[kh * 2]);
                            mma_bf16(acc, aH4, &bL4[kh * 2]);
                            mma_bf16(acc, aL4, &bH4[kh * 2]);
                        }
                    }
                }
                if (c + 3 < 8) issue_chunk(c + 3);
            }
            __syncthreads();
        }

        g_s[jloc * 33 + br]           = acc[0] + p0.x;
        g_s[(jloc + 1) * 33 + br]     = acc[1] + p0.y;
        g_s[jloc * 33 + br + 8]       = acc[2] + p1.x;
        g_s[(jloc + 1) * 33 + br + 8] = acc[3] + p1.y;
        __syncthreads();

        {
            float gi = g_s[pu * 33 + pb];
            float gf = g_s[(8 + pu) * 33 + pb];
            float gg = g_s[(16 + pu) * 33 + pb];
            float go = g_s[(24 + pu) * 33 + pb];
            float si = 1.f / (1.f + expf(-gi));
            float sf = 1.f / (1.f + expf(-gf));
            float so = 1.f / (1.f + expf(-go));
            c_reg = sf * c_reg + si * tanhf(gg);
            float hn = so * tanhf(c_reg);
            __nv_bfloat16 hh, hl;
            split_hilo(hn, hh, hl);
            size_t orow = ((size_t)pb * TSEQ + t) * HDIM + u0 + pu;
            ah[orow] = hh;
            al[orow] = hl;
        }
        __syncthreads();

        if (t + 1 < TSEQ) {
            gen++;
            if (tid == 0) {
                asm volatile("red.release.gpu.global.add.u32 [%0], 1;"
                             :: "l"(&g_bar_ctr) : "memory");
                unsigned tgt = gen * NBLK, v;
                do {
                    asm volatile("ld.acquire.gpu.global.u32 %0, [%1];"
                                 : "=r"(v) : "l"(&g_bar_ctr) : "memory");
                } while (v < tgt);
            }
            __syncthreads();
        }
    }
}

// ---------------- host launch --------------------------------------------
extern "C" void kernel_launch(void* const* d_in, const int* in_sizes, int n_in,
                              void* d_out, int out_size)
{
    const float* image = (const float*)d_in[0];
    const int*   caps  = (const int*)  d_in[1];
    const float* lin_W = (const float*)d_in[2];
    const float* lin_b = (const float*)d_in[3];
    const float* bn_g  = (const float*)d_in[4];
    const float* bn_b  = (const float*)d_in[5];
    const float* emb   = (const float*)d_in[6];
    const float* Wih0  = (const float*)d_in[7];
    const float* Whh0  = (const float*)d_in[8];
    const float* bih0  = (const float*)d_in[9];
    const float* bhh0  = (const float*)d_in[10];
    const float* Wih1  = (const float*)d_in[11];
    const float* Whh1  = (const float*)d_in[12];
    const float* bih1  = (const float*)d_in[13];
    const float* bhh1  = (const float*)d_in[14];
    const float* fc_W  = (const float*)d_in[15];
    const float* fc_b  = (const float*)d_in[16];
    float* out = (float*)d_out;

    float *pre, *sa, *sb;
    __nv_bfloat16 *ah, *al, *w0h, *w0l, *w1h, *w1l;
    int8_t *a1, *a2, *b1, *b2;
    cudaGetSymbolAddress((void**)&pre, g_pre);
    cudaGetSymbolAddress((void**)&ah,  g_ah);
    cudaGetSymbolAddress((void**)&al,  g_al);
    cudaGetSymbolAddress((void**)&w0h, g_w0h);
    cudaGetSymbolAddress((void**)&w0l, g_w0l);
    cudaGetSymbolAddress((void**)&w1h, g_w1h);
    cudaGetSymbolAddress((void**)&w1l, g_w1l);
    cudaGetSymbolAddress((void**)&a1,  g_a1);
    cudaGetSymbolAddress((void**)&a2,  g_a2);
    cudaGetSymbolAddress((void**)&b1,  g_b1);
    cudaGetSymbolAddress((void**)&b2,  g_b2);
    cudaGetSymbolAddress((void**)&sa,  g_sa);
    cudaGetSymbolAddress((void**)&sb,  g_sb);

    static int smem_set = 0;
    const int GEMM_SMEM = 3 * STAGE + 1024;
    const int QGEMM_SMEM = 3 * QSTAGE + 1024;
    const int LSTM_SMEM = 196608 + 32 * 33 * 4 + 256;
    if (!smem_set) {
        cudaFuncSetAttribute(gemm_bf16x3,
                             cudaFuncAttributeMaxDynamicSharedMemorySize, GEMM_SMEM);
        cudaFuncSetAttribute(gemm_s8,
                             cudaFuncAttributeMaxDynamicSharedMemorySize, QGEMM_SMEM);
        cudaFuncSetAttribute(lstm_persist,
                             cudaFuncAttributeMaxDynamicSharedMemorySize, LSTM_SMEM);
        smem_set = 1;
    }

    // inputs -> ah/al rows (K=EDIM layout)
    linbn_kernel<<<EDIM, 256>>>(image, lin_W, lin_b, bn_g, bn_b, ah, al);
    gather_kernel<<<dim3(TSEQ - 1, BATCH), 128>>>(caps, emb, ah, al);

    // layer-0 input weights, then pre0 GEMM
    cvt_hilo<<<(G4 * EDIM / 4 + 255) / 256, 256>>>(Wih0, w0h, w0l, G4 * EDIM);
    gemm_bf16x3<<<dim3(MROWS / 128, G4 / 128), 256, GEMM_SMEM>>>(
        ah, al, w0h, w0l, pre, MROWS, G4, EDIM, bih0, bhh0, 1);

    // remaining weight prep: lstm1 bf16, fc int8 quant
    cvt_hilo<<<(G4 * HDIM / 4 + 255) / 256, 256>>>(Wih1, w1h, w1l, G4 * HDIM);
    quant_f32<<<VOCAB, 256>>>(fc_W, b1, b2, sb);

    // layer-0 recurrence
    lstm_persist<<<NBLK, 256, LSTM_SMEM>>>(pre, Whh0, ah, al);

    // pre1 = hs0 @ Wih1^T + biases (resets bar for lstm1)
    gemm_bf16x3<<<dim3(MROWS / 128, G4 / 128), 256, GEMM_SMEM>>>(
        ah, al, w1h, w1l, pre, MROWS, G4, HDIM, bih1, bhh1, 1);

    // layer-1 recurrence
    lstm_persist<<<NBLK, 256, LSTM_SMEM>>>(pre, Whh1, ah, al);

    // quantize hs1, then int8 FC: logits = hs1 @ fc_W^T + fc_b
    quant_bf16pair<<<MROWS, 256>>>(ah, al, a1, a2, sa);
    gemm_s8<<<dim3(MROWS / 128, VOCAB / 128), 256, QGEMM_SMEM>>>(
        a1, a2, b1, b2, sa, sb, out, MROWS, VOCAB, HDIM, fc_b);
}

// round 10
// speedup vs baseline: 1.2920x; 1.2920x over previous
#include <cuda_runtime.h>
#include <cuda_bf16.h>
#include <math.h>
#include <stdint.h>

// Problem dims
#define VOCAB 32000
#define HDIM  1024
#define EDIM  512
#define BATCH 32
#define TSEQ  64
#define IMGF  2048
#define G4    (4*HDIM)          // 4096
#define MROWS (BATCH*TSEQ)      // 2048
#define NBLK  128               // persistent recurrence CTAs

// ---------------- device scratch (no allocation allowed) ----------------
__device__ float g_pre [MROWS * G4];     // time-major: [t][b][G4]
__device__ unsigned g_bar_ctr;

__device__ __nv_bfloat16 g_ah [MROWS * HDIM];
__device__ __nv_bfloat16 g_al [MROWS * HDIM];
__device__ __nv_bfloat16 g_w0h[G4 * EDIM];
__device__ __nv_bfloat16 g_w0l[G4 * EDIM];
__device__ __nv_bfloat16 g_w1h[G4 * HDIM];
__device__ __nv_bfloat16 g_w1l[G4 * HDIM];
__device__ __nv_bfloat16 g_fh [VOCAB * HDIM];
__device__ __nv_bfloat16 g_fl [VOCAB * HDIM];

// ======================= helpers =========================================
__device__ __forceinline__ uint32_t smem_u32(const void* p) {
    uint32_t a;
    asm("{ .reg .u64 t; cvta.to.shared.u64 t, %1; cvt.u32.u64 %0, t; }"
        : "=r"(a) : "l"(p));
    return a;
}
#define SWZ(x) ((x) ^ (((x) >> 3) & 0x70))

__device__ __forceinline__ void cpa16(uint32_t dst, const void* src) {
    asm volatile("cp.async.cg.shared.global [%0], [%1], 16;"
                 :: "r"(dst), "l"(src) : "memory");
}
#define CP_COMMIT() asm volatile("cp.async.commit_group;" ::: "memory")
#define CP_WAIT0()  asm volatile("cp.async.wait_group 0;" ::: "memory")
#define CP_WAIT1()  asm volatile("cp.async.wait_group 1;" ::: "memory")
#define CP_WAIT2()  asm volatile("cp.async.wait_group 2;" ::: "memory")

__device__ __forceinline__ void ldsm_x4(uint32_t* r, uint32_t addr) {
    asm volatile("ldmatrix.sync.aligned.m8n8.x4.shared.b16 {%0,%1,%2,%3}, [%4];"
                 : "=r"(r[0]), "=r"(r[1]), "=r"(r[2]), "=r"(r[3]) : "r"(addr));
}
__device__ __forceinline__ void mma_bf16(float* c, const uint32_t* a, const uint32_t* b) {
    asm volatile(
        "mma.sync.aligned.m16n8k16.row.col.f32.bf16.bf16.f32 "
        "{%0,%1,%2,%3}, {%4,%5,%6,%7}, {%8,%9}, {%0,%1,%2,%3};"
        : "+f"(c[0]), "+f"(c[1]), "+f"(c[2]), "+f"(c[3])
        : "r"(a[0]), "r"(a[1]), "r"(a[2]), "r"(a[3]), "r"(b[0]), "r"(b[1]));
}
__device__ __forceinline__ void split_hilo(float x, __nv_bfloat16& h, __nv_bfloat16& l) {
    h = __float2bfloat16(x);
    l = __float2bfloat16(x - __bfloat162float(h));
}

// ============== fp32 -> bf16 hi/lo split conversion (weights) ============
__global__ void cvt_hilo(const float* __restrict__ x,
                         __nv_bfloat16* __restrict__ hi,
                         __nv_bfloat16* __restrict__ lo, int n)
{
    int i = (blockIdx.x * 256 + threadIdx.x) * 4;
    if (i >= n) return;
    float4 v = *(const float4*)(x + i);
    __nv_bfloat16 h0, h1, h2, h3, l0, l1, l2, l3;
    split_hilo(v.x, h0, l0); split_hilo(v.y, h1, l1);
    split_hilo(v.z, h2, l2); split_hilo(v.w, h3, l3);
    __nv_bfloat162 ph0; ph0.x = h0; ph0.y = h1;
    __nv_bfloat162 ph1; ph1.x = h2; ph1.y = h3;
    __nv_bfloat162 pl0; pl0.x = l0; pl0.y = l1;
    __nv_bfloat162 pl1; pl1.x = l2; pl1.y = l3;
    *(__nv_bfloat162*)(hi + i)     = ph0;
    *(__nv_bfloat162*)(hi + i + 2) = ph1;
    *(__nv_bfloat162*)(lo + i)     = pl0;
    *(__nv_bfloat162*)(lo + i + 2) = pl1;
}

// ============== HMMA bf16x3 GEMM (pre-GEMMs): C = A*B^T + bias ===========
// 1 CTA/SM variant: K-chunk 64, 3 stages x 64KB. (R8 proven.)
#define TEN_T 16384
#define STAGE (4*TEN_T)
__global__ void __launch_bounds__(256, 1)
gemm_bf16x3(const __nv_bfloat16* __restrict__ Ah, const __nv_bfloat16* __restrict__ Al,
            const __nv_bfloat16* __restrict__ Bh, const __nv_bfloat16* __restrict__ Bl,
            float* __restrict__ C, int M, int N, int K,
            const float* __restrict__ bias1, const float* __restrict__ bias2,
            int permute)
{
    extern __shared__ char dsm[];
    const int tid  = threadIdx.x;
    const int wid  = tid >> 5;
    const int lane = tid & 31;
    const int bm = blockIdx.x * 128;
    const int bn = blockIdx.y * 128;
    const int wm = (wid & 3) * 32;
    const int wn = (wid >> 2) * 64;
    const int nk = K >> 6;

    if (blockIdx.x == 0 && blockIdx.y == 0 && tid == 0) g_bar_ctr = 0u;

    uint32_t dyn = smem_u32(dsm);
    uint32_t sb0 = (dyn + 1023u) & ~1023u;

    float acc[2][8][4];
    #pragma unroll
    for (int i = 0; i < 2; i++)
        #pragma unroll
        for (int j = 0; j < 8; j++)
            #pragma unroll
            for (int r = 0; r < 4; r++) acc[i][j][r] = 0.f;

    auto issue_load = [&](int kt, int stg) {
        const uint32_t st = sb0 + (uint32_t)stg * STAGE;
        const size_t koff = (size_t)kt * 64;
        #pragma unroll
        for (int i = 0; i < 16; i++) {
            int id = i * 256 + tid;
            int tensor = id >> 10;
            int cid = id & 1023;
            int r = cid >> 3, c = cid & 7;
            uint32_t dst = st + tensor * TEN_T + SWZ((uint32_t)(r * 128 + c * 16));
            const __nv_bfloat16* src;
            if (tensor == 0)      src = Ah + (size_t)(bm + r) * K + koff + c * 8;
            else if (tensor == 1) src = Al + (size_t)(bm + r) * K + koff + c * 8;
            else if (tensor == 2) src = Bh + (size_t)(bn + r) * K + koff + c * 8;
            else                  src = Bl + (size_t)(bn + r) * K + koff + c * 8;
            cpa16(dst, src);
        }
        CP_COMMIT();
    };

    issue_load(0, 0);
    if (nk > 1) issue_load(1, 1);

    const int a_row = wm + (lane & 15);
    const int a_k8  = (lane >> 4) * 8;
    const int b_row = wn + ((lane >> 4) & 1) * 8 + (lane & 7);
    const int b_k8  = ((lane >> 3) & 1) * 8;

    uint32_t aH[2][2][4], aL[2][2][4], bH[2][4][4], bL[2][4][4];

    int s_cur = 0, s_nxt = 2;
    for (int kt = 0; kt < nk; kt++) {
        if (kt + 1 < nk) { CP_WAIT1(); } else { CP_WAIT0(); }
        __syncthreads();
        if (kt + 2 < nk) issue_load(kt + 2, s_nxt);

        const uint32_t st  = sb0 + (uint32_t)s_cur * STAGE;
        const uint32_t sAh = st;
        const uint32_t sAl = st + TEN_T;
        const uint32_t sBh = st + 2 * TEN_T;
        const uint32_t sBl = st + 3 * TEN_T;

        auto load_frags = [&](int buf, int ksv) {
            const int kb = ksv * 16;
            #pragma unroll
            for (int mi = 0; mi < 2; mi++) {
                uint32_t off = SWZ((uint32_t)((a_row + mi * 16) * 128 + (kb + a_k8) * 2));
                ldsm_x4(aH[buf][mi], sAh + off);
                ldsm_x4(aL[buf][mi], sAl + off);
            }
            #pragma unroll
            for (int p = 0; p < 4; p++) {
                uint32_t off = SWZ((uint32_t)((b_row + p * 16) * 128 + (kb + b_k8) * 2));
                ldsm_x4(bH[buf][p], sBh + off);
                ldsm_x4(bL[buf][p], sBl + off);
            }
        };

        load_frags(0, 0);
        #pragma unroll
        for (int ks = 0; ks < 4; ks++) {
            const int cb = ks & 1;
            if (ks < 3) load_frags(cb ^ 1, ks + 1);
            #pragma unroll
            for (int mi = 0; mi < 2; mi++)
                #pragma unroll
                for (int p = 0; p < 4; p++)
                    #pragma unroll
                    for (int j = 0; j < 2; j++)
                        mma_bf16(acc[mi][p * 2 + j], aH[cb][mi], &bH[cb][p][j * 2]);
            #pragma unroll
            for (int mi = 0; mi < 2; mi++)
                #pragma unroll
                for (int p = 0; p < 4; p++)
                    #pragma unroll
                    for (int j = 0; j < 2; j++)
                        mma_bf16(acc[mi][p * 2 + j], aH[cb][mi], &bL[cb][p][j * 2]);
            #pragma unroll
            for (int mi = 0; mi < 2; mi++)
                #pragma unroll
                for (int p = 0; p < 4; p++)
                    #pragma unroll
                    for (int j = 0; j < 2; j++)
                        mma_bf16(acc[mi][p * 2 + j], aL[cb][mi], &bH[cb][p][j * 2]);
        }

        s_cur = (s_cur == 2) ? 0 : s_cur + 1;
        s_nxt = (s_nxt == 2) ? 0 : s_nxt + 1;
    }

    #pragma unroll
    for (int nj = 0; nj < 8; nj++) {
        const int col = bn + wn + nj * 8 + (lane & 3) * 2;
        float b0 = 0.f, b1 = 0.f;
        if (bias1) { b0 += bias1[col]; b1 += bias1[col + 1]; }
        if (bias2) { b0 += bias2[col]; b1 += bias2[col + 1]; }
        #pragma unroll
        for (int mi = 0; mi < 2; mi++) {
            const int r0 = bm + wm + mi * 16 + (lane >> 2);
            const int r1 = r0 + 8;
            int o0 = permute ? ((r0 & 63) * 32 + (r0 >> 6)) : r0;
            int o1 = permute ? ((r1 & 63) * 32 + (r1 >> 6)) : r1;
            float2 v0 = make_float2(acc[mi][nj][0] + b0, acc[mi][nj][1] + b1);
            float2 v1 = make_float2(acc[mi][nj][2] + b0, acc[mi][nj][3] + b1);
            *(float2*)(C + (size_t)o0 * N + col) = v0;
            *(float2*)(C + (size_t)o1 * N + col) = v1;
        }
    }
}

// ============== FC GEMM, 2 CTAs/SM: combined hi|lo rows, K-chunk 32 ======
// smem row r (128B) = [hi row r 64B | lo row r 64B], SW128 swizzled.
// stage = A(16KB) + B(16KB) = 32KB; 3 stages = 96KB -> 2 CTAs/SM.
#define FCA_T 16384
#define FCSTAGE 32768
__global__ void __launch_bounds__(256, 2)
gemm_fc(const __nv_bfloat16* __restrict__ Ah, const __nv_bfloat16* __restrict__ Al,
        const __nv_bfloat16* __restrict__ Bh, const __nv_bfloat16* __restrict__ Bl,
        float* __restrict__ C, int M, int N, int K,
        const float* __restrict__ bias)
{
    extern __shared__ char dsm[];
    const int tid  = threadIdx.x;
    const int wid  = tid >> 5;
    const int lane = tid & 31;
    const int bm = blockIdx.x * 128;
    const int bn = blockIdx.y * 128;
    const int wm = (wid & 3) * 32;
    const int wn = (wid >> 2) * 64;
    const int nk = K >> 5;              // 32 k-elems per chunk

    uint32_t dyn = smem_u32(dsm);
    uint32_t sb0 = (dyn + 1023u) & ~1023u;

    float acc[2][8][4];
    #pragma unroll
    for (int i = 0; i < 2; i++)
        #pragma unroll
        for (int j = 0; j < 8; j++)
            #pragma unroll
            for (int r = 0; r < 4; r++) acc[i][j][r] = 0.f;

    auto issue_load = [&](int kt, int stg) {
        const uint32_t st = sb0 + (uint32_t)stg * FCSTAGE;
        const size_t koff = (size_t)kt * 32;
        #pragma unroll
        for (int i = 0; i < 8; i++) {
            int id = i * 256 + tid;
            int isB = id >> 10;
            int cid = id & 1023;
            int r = cid >> 3, c = cid & 7;     // c: 0-3 hi, 4-7 lo
            uint32_t dst = st + isB * FCA_T + SWZ((uint32_t)(r * 128 + c * 16));
            const __nv_bfloat16* src;
            if (isB == 0) src = (c < 4 ? Ah : Al) + (size_t)(bm + r) * K + koff + (c & 3) * 8;
            else          src = (c < 4 ? Bh : Bl) + (size_t)(bn + r) * K + koff + (c & 3) * 8;
            cpa16(dst, src);
        }
        CP_COMMIT();
    };

    issue_load(0, 0);
    if (nk > 1) issue_load(1, 1);

    const int a_row  = wm + (lane & 15);
    const int a_k16  = (lane >> 4) * 16;            // byte offset within 32B half
    const int b_row  = wn + ((lane >> 4) & 1) * 8 + (lane & 7);
    const int b_k16  = ((lane >> 3) & 1) * 16;

    int s_cur = 0, s_nxt = 2;
    for (int kt = 0; kt < nk; kt++) {
        if (kt + 1 < nk) { CP_WAIT1(); } else { CP_WAIT0(); }
        __syncthreads();
        if (kt + 2 < nk) issue_load(kt + 2, s_nxt);

        const uint32_t sA = sb0 + (uint32_t)s_cur * FCSTAGE;
        const uint32_t sB = sA + FCA_T;

        #pragma unroll
        for (int ks = 0; ks < 2; ks++) {            // two k16 steps per chunk
            const int kb = ks * 32;                 // byte offset in hi half
            uint32_t aH[2][4], aL[2][4];
            #pragma unroll
            for (int mi = 0; mi < 2; mi++) {
                uint32_t base = (uint32_t)((a_row + mi * 16) * 128 + kb + a_k16);
                ldsm_x4(aH[mi], sA + SWZ(base));
                ldsm_x4(aL[mi], sA + SWZ(base + 64));
            }
            #pragma unroll
            for (int p = 0; p < 4; p++) {
                uint32_t bH[4], bL[4];
                uint32_t base = (uint32_t)((b_row + p * 16) * 128 + kb + b_k16);
                ldsm_x4(bH, sB + SWZ(base));
                ldsm_x4(bL, sB + SWZ(base + 64));
                #pragma unroll
                for (int mi = 0; mi < 2; mi++)
                    #pragma unroll
                    for (int j = 0; j < 2; j++) {
                        float* a4 = acc[mi][p * 2 + j];
                        mma_bf16(a4, aH[mi], &bH[j * 2]);
                        mma_bf16(a4, aH[mi], &bL[j * 2]);
                        mma_bf16(a4, aL[mi], &bH[j * 2]);
                    }
            }
        }

        s_cur = (s_cur == 2) ? 0 : s_cur + 1;
        s_nxt = (s_nxt == 2) ? 0 : s_nxt + 1;
    }

    #pragma unroll
    for (int nj = 0; nj < 8; nj++) {
        const int col = bn + wn + nj * 8 + (lane & 3) * 2;
        const float b0 = bias[col], b1 = bias[col + 1];
        #pragma unroll
        for (int mi = 0; mi < 2; mi++) {
            const int r0 = bm + wm + mi * 16 + (lane >> 2);
            float2 v0 = make_float2(acc[mi][nj][0] + b0, acc[mi][nj][1] + b1);
            float2 v1 = make_float2(acc[mi][nj][2] + b0, acc[mi][nj][3] + b1);
            *(float2*)(C + (size_t)r0 * N + col)       = v0;
            *(float2*)(C + (size_t)(r0 + 8) * N + col) = v1;
        }
    }
}

// ---------------- linear(2048->512) + batchnorm -> bf16 hi/lo ------------
__global__ void linbn_kernel(const float* __restrict__ img,
                             const float* __restrict__ W,
                             const float* __restrict__ bias,
                             const float* __restrict__ gamma,
                             const float* __restrict__ beta,
                             __nv_bfloat16* __restrict__ ah,
                             __nv_bfloat16* __restrict__ al)
{
    const int e   = blockIdx.x;
    const int tid = threadIdx.x;
    __shared__ float wrow[IMGF];
    __shared__ float xv[BATCH];

    {
        const float* wsrc = W + (size_t)e * IMGF;
        #pragma unroll
        for (int i = 0; i < 2; i++) {
            int k = (tid + i * 256) * 4;
            *(float4*)&wrow[k] = *(const float4*)(wsrc + k);
        }
    }
    __syncthreads();

    const int lane = tid & 31, wid = tid >> 5;
    float a0 = 0.f, a1 = 0.f, a2 = 0.f, a3 = 0.f;
    for (int k = lane; k < IMGF; k += 32) {
        float wv = wrow[k];
        a0 += img[(size_t)(wid +  0) * IMGF + k] * wv;
        a1 += img[(size_t)(wid +  8) * IMGF + k] * wv;
        a2 += img[(size_t)(wid + 16) * IMGF + k] * wv;
        a3 += img[(size_t)(wid + 24) * IMGF + k] * wv;
    }
    #pragma unroll
    for (int o = 16; o > 0; o >>= 1) {
        a0 += __shfl_xor_sync(0xffffffffu, a0, o);
        a1 += __shfl_xor_sync(0xffffffffu, a1, o);
        a2 += __shfl_xor_sync(0xffffffffu, a2, o);
        a3 += __shfl_xor_sync(0xffffffffu, a3, o);
    }
    if (lane == 0) {
        float bb = bias[e];
        xv[wid +  0] = a0 + bb;
        xv[wid +  8] = a1 + bb;
        xv[wid + 16] = a2 + bb;
        xv[wid + 24] = a3 + bb;
    }
    __syncthreads();

    if (tid < 32) {
        float x = xv[tid];
        float s = x, q = x * x;
        #pragma unroll
        for (int o = 16; o > 0; o >>= 1) {
            s += __shfl_xor_sync(0xffffffffu, s, o);
            q += __shfl_xor_sync(0xffffffffu, q, o);
        }
        float mu  = s * (1.f / 32.f);
        float var = q * (1.f / 32.f) - mu * mu;
        float inv = rsqrtf(var + 1e-5f);
        float y = gamma[e] * (x - mu) * inv + beta[e];
        __nv_bfloat16 h, l;
        split_hilo(y, h, l);
        size_t idx = ((size_t)tid * TSEQ + 0) * EDIM + e;
        ah[idx] = h;
        al[idx] = l;
    }
}

// ---------------- embedding gather -> bf16 hi/lo rows t>=1 ---------------
__global__ void gather_kernel(const int* __restrict__ cap,
                              const float* __restrict__ emb,
                              __nv_bfloat16* __restrict__ ah,
                              __nv_bfloat16* __restrict__ al)
{
    const int t = blockIdx.x + 1;
    const int b = blockIdx.y;
    const int tok = cap[b * TSEQ + (t - 1)];
    const int k = threadIdx.x * 4;
    float4 v = *(const float4*)(emb + (size_t)tok * EDIM + k);
    __nv_bfloat16 h0, h1, h2, h3, l0, l1, l2, l3;
    split_hilo(v.x, h0, l0); split_hilo(v.y, h1, l1);
    split_hilo(v.z, h2, l2); split_hilo(v.w, h3, l3);
    __nv_bfloat162 ph0; ph0.x = h0; ph0.y = h1;
    __nv_bfloat162 ph1; ph1.x = h2; ph1.y = h3;
    __nv_bfloat162 pl0; pl0.x = l0; pl0.y = l1;
    __nv_bfloat162 pl1; pl1.x = l2; pl1.y = l3;
    size_t row = ((size_t)b * TSEQ + t) * EDIM + k;
    *(__nv_bfloat162*)(ah + row)     = ph0;
    *(__nv_bfloat162*)(ah + row + 2) = ph1;
    *(__nv_bfloat162*)(al + row)     = pl0;
    *(__nv_bfloat162*)(al + row + 2) = pl1;
}

// ---------------- persistent HMMA LSTM layer (R8 proven) ------------------
__global__ void __launch_bounds__(256, 1)
lstm_persist(const float* __restrict__ pre,   // [T][B][G4]
             const float* __restrict__ Whh,   // [G4][HDIM]
             __nv_bfloat16* __restrict__ ah,  // [b*T+t][HDIM]
             __nv_bfloat16* __restrict__ al)
{
    extern __shared__ char sm_raw[];
    uint32_t raw = smem_u32(sm_raw);
    uint32_t sbase = (raw + 127u) & ~127u;
    char* base = sm_raw + (sbase - raw);
    const uint32_t W_HI = 0;
    const uint32_t W_LO = 65536;
    const uint32_t HBUF = 131072;            // 4 stages x 16KB
    float* g_s = (float*)(base + 196608);    // [32][33]

    const int tid  = threadIdx.x;
    const int wid  = tid >> 5;
    const int lane = tid & 31;
    const int u0   = blockIdx.x * 8;

    #pragma unroll
    for (int i = 0; i < 16; i++) {
        int cell = i * 256 + tid;
        int kt = cell >> 8;
        int r  = (cell >> 3) & 31;
        int cc = cell & 7;
        int jrow = (r >> 3) * HDIM + u0 + (r & 7);
        const float* src = Whh + (size_t)jrow * HDIM + kt * 64 + cc * 8;
        float4 v0 = *(const float4*)src;
        float4 v1 = *(const float4*)(src + 4);
        float f[8] = {v0.x, v0.y, v0.z, v0.w, v1.x, v1.y, v1.z, v1.w};
        uint32_t hi4[4], lo4[4];
        #pragma unroll
        for (int q = 0; q < 4; q++) {
            __nv_bfloat16 h0, l0, h1, l1;
            split_hilo(f[2*q],   h0, l0);
            split_hilo(f[2*q+1], h1, l1);
            __nv_bfloat162 hp; hp.x = h0; hp.y = h1;
            __nv_bfloat162 lp; lp.x = l0; lp.y = l1;
            hi4[q] = *(uint32_t*)&hp;
            lo4[q] = *(uint32_t*)&lp;
        }
        uint32_t off = kt * 4096 + SWZ((uint32_t)(r * 128 + cc * 16));
        *(uint4*)(base + W_HI + off) = make_uint4(hi4[0], hi4[1], hi4[2], hi4[3]);
        *(uint4*)(base + W_LO + off) = make_uint4(lo4[0], lo4[1], lo4[2], lo4[3]);
    }
    __syncthreads();

    const int wm = (wid & 1) * 16;
    const int wn = (wid >> 1) * 8;
    const int a_row = wm + (lane & 15);
    const int a_k8  = (lane >> 4) * 8;
    const int b_row = wn + (lane & 7);
    const int b_ku  = (lane >> 3) & 3;

    const int hr = tid >> 3;
    const int hc = tid & 7;
    const uint32_t hswz = SWZ((uint32_t)(hr * 128 + hc * 16));

    const int pb = tid >> 3;
    const int pu = tid & 7;

    const int jloc = wn + (lane & 3) * 2;
    const int jrow_e = (jloc >> 3) * HDIM + u0 + (jloc & 7);
    const int br = wm + (lane >> 2);

    float c_reg = 0.f;
    unsigned gen = 0;

    for (int t = 0; t < TSEQ; t++) {
        float acc[4] = {0.f, 0.f, 0.f, 0.f};

        const float* pt = pre + (size_t)t * BATCH * G4;
        float2 p0 = *(const float2*)(pt + (size_t)br * G4 + jrow_e);
        float2 p1 = *(const float2*)(pt + (size_t)(br + 8) * G4 + jrow_e);

        if (t > 0) {
            const size_t hrow_base = ((size_t)hr * TSEQ + (t - 1)) * HDIM + hc * 8;
            auto issue_chunk = [&](int c) {
                const uint32_t d = sbase + HBUF + (c & 3) * 16384 + hswz;
                const size_t g = hrow_base + (size_t)c * 128;
                cpa16(d,         ah + g);
                cpa16(d + 4096,  ah + g + 64);
                cpa16(d + 8192,  al + g);
                cpa16(d + 12288, al + g + 64);
                CP_COMMIT();
            };
            issue_chunk(0);
            issue_chunk(1);
            issue_chunk(2);
            for (int c = 0; c < 8; c++) {
                if (c < 6) { CP_WAIT2(); }
                else if (c == 6) { CP_WAIT1(); }
                else { CP_WAIT0(); }
                __syncthreads();
                const uint32_t stg = sbase + HBUF + (c & 3) * 16384;
                #pragma unroll
                for (int sub = 0; sub < 2; sub++) {
                    const uint32_t wc = (uint32_t)(2 * c + sub) * 4096;
                    const uint32_t hb_hi = stg + sub * 4096;
                    const uint32_t hb_lo = stg + 8192 + sub * 4096;
                    #pragma unroll
                    for (int kk2 = 0; kk2 < 2; kk2++) {
                        uint32_t bH4[4], bL4[4];
                        uint32_t boff = wc + SWZ((uint32_t)(b_row * 128 + kk2 * 64 + b_ku * 16));
                        ldsm_x4(bH4, sbase + W_HI + boff);
                        ldsm_x4(bL4, sbase + W_LO + boff);
                        #pragma unroll
                        for (int kh = 0; kh < 2; kh++) {
                            const int ks = kk2 * 2 + kh;
                            uint32_t aH4[4], aL4[4];
                            uint32_t aoff = SWZ((uint32_t)(a_row * 128 + ks * 32 + a_k8 * 2));
                            ldsm_x4(aH4, hb_hi + aoff);
                            ldsm_x4(aL4, hb_lo + aoff);
                            mma_bf16(acc, aH4, &bH4[kh * 2]);
                            mma_bf16(acc, aH4, &bL4[kh * 2]);
                            mma_bf16(acc, aL4, &bH4[kh * 2]);
                        }
                    }
                }
                if (c + 3 < 8) issue_chunk(c + 3);
            }
            __syncthreads();
        }

        g_s[jloc * 33 + br]           = acc[0] + p0.x;
        g_s[(jloc + 1) * 33 + br]     = acc[1] + p0.y;
        g_s[jloc * 33 + br + 8]       = acc[2] + p1.x;
        g_s[(jloc + 1) * 33 + br + 8] = acc[3] + p1.y;
        __syncthreads();

        {
            float gi = g_s[pu * 33 + pb];
            float gf = g_s[(8 + pu) * 33 + pb];
            float gg = g_s[(16 + pu) * 33 + pb];
            float go = g_s[(24 + pu) * 33 + pb];
            float si = 1.f / (1.f + expf(-gi));
            float sf = 1.f / (1.f + expf(-gf));
            float so = 1.f / (1.f + expf(-go));
            c_reg = sf * c_reg + si * tanhf(gg);
            float hn = so * tanhf(c_reg);
            __nv_bfloat16 hh, hl;
            split_hilo(hn, hh, hl);
            size_t orow = ((size_t)pb * TSEQ + t) * HDIM + u0 + pu;
            ah[orow] = hh;
            al[orow] = hl;
        }
        __syncthreads();

        if (t + 1 < TSEQ) {
            gen++;
            if (tid == 0) {
                asm volatile("red.release.gpu.global.add.u32 [%0], 1;"
                             :: "l"(&g_bar_ctr) : "memory");
                unsigned tgt = gen * NBLK, v;
                do {
                    asm volatile("ld.acquire.gpu.global.u32 %0, [%1];"
                                 : "=r"(v) : "l"(&g_bar_ctr) : "memory");
                } while (v < tgt);
            }
            __syncthreads();
        }
    }
}

// ---------------- host launch --------------------------------------------
extern "C" void kernel_launch(void* const* d_in, const int* in_sizes, int n_in,
                              void* d_out, int out_size)
{
    const float* image = (const float*)d_in[0];
    const int*   caps  = (const int*)  d_in[1];
    const float* lin_W = (const float*)d_in[2];
    const float* lin_b = (const float*)d_in[3];
    const float* bn_g  = (const float*)d_in[4];
    const float* bn_b  = (const float*)d_in[5];
    const float* emb   = (const float*)d_in[6];
    const float* Wih0  = (const float*)d_in[7];
    const float* Whh0  = (const float*)d_in[8];
    const float* bih0  = (const float*)d_in[9];
    const float* bhh0  = (const float*)d_in[10];
    const float* Wih1  = (const float*)d_in[11];
    const float* Whh1  = (const float*)d_in[12];
    const float* bih1  = (const float*)d_in[13];
    const float* bhh1  = (const float*)d_in[14];
    const float* fc_W  = (const float*)d_in[15];
    const float* fc_b  = (const float*)d_in[16];
    float* out = (float*)d_out;

    float *pre;
    __nv_bfloat16 *ah, *al, *w0h, *w0l, *w1h, *w1l, *fh, *fl;
    cudaGetSymbolAddress((void**)&pre, g_pre);
    cudaGetSymbolAddress((void**)&ah,  g_ah);
    cudaGetSymbolAddress((void**)&al,  g_al);
    cudaGetSymbolAddress((void**)&w0h, g_w0h);
    cudaGetSymbolAddress((void**)&w0l, g_w0l);
    cudaGetSymbolAddress((void**)&w1h, g_w1h);
    cudaGetSymbolAddress((void**)&w1l, g_w1l);
    cudaGetSymbolAddress((void**)&fh,  g_fh);
    cudaGetSymbolAddress((void**)&fl,  g_fl);

    static int smem_set = 0;
    const int GEMM_SMEM = 3 * STAGE + 1024;          // ~193KB (1 CTA/SM)
    const int FC_SMEM   = 3 * FCSTAGE + 1024;        // ~97KB  (2 CTAs/SM)
    const int LSTM_SMEM = 196608 + 32 * 33 * 4 + 256;
    if (!smem_set) {
        cudaFuncSetAttribute(gemm_bf16x3,
                             cudaFuncAttributeMaxDynamicSharedMemorySize, GEMM_SMEM);
        cudaFuncSetAttribute(gemm_fc,
                             cudaFuncAttributeMaxDynamicSharedMemorySize, FC_SMEM);
        cudaFuncSetAttribute(lstm_persist,
                             cudaFuncAttributeMaxDynamicSharedMemorySize, LSTM_SMEM);
        smem_set = 1;
    }

    // inputs -> ah/al rows (K=EDIM layout)
    linbn_kernel<<<EDIM, 256>>>(image, lin_W, lin_b, bn_g, bn_b, ah, al);
    gather_kernel<<<dim3(TSEQ - 1, BATCH), 128>>>(caps, emb, ah, al);

    // layer-0 input weights, then pre0 GEMM (resets bar for lstm0)
    cvt_hilo<<<(G4 * EDIM / 4 + 255) / 256, 256>>>(Wih0, w0h, w0l, G4 * EDIM);
    gemm_bf16x3<<<dim3(MROWS / 128, G4 / 128), 256, GEMM_SMEM>>>(
        ah, al, w0h, w0l, pre, MROWS, G4, EDIM, bih0, bhh0, 1);

    // remaining weight conversions
    cvt_hilo<<<(G4 * HDIM / 4 + 255) / 256, 256>>>(Wih1, w1h, w1l, G4 * HDIM);
    cvt_hilo<<<(VOCAB * HDIM / 4 + 255) / 256, 256>>>(fc_W, fh, fl, VOCAB * HDIM);

    // layer-0 recurrence
    lstm_persist<<<NBLK, 256, LSTM_SMEM>>>(pre, Whh0, ah, al);

    // pre1 = hs0 @ Wih1^T + biases (resets bar for lstm1)
    gemm_bf16x3<<<dim3(MROWS / 128, G4 / 128), 256, GEMM_SMEM>>>(
        ah, al, w1h, w1l, pre, MROWS, G4, HDIM, bih1, bhh1, 1);

    // layer-1 recurrence
    lstm_persist<<<NBLK, 256, LSTM_SMEM>>>(pre, Whh1, ah, al);

    // logits = hs1 @ fc_W^T + fc_b  (2 CTAs/SM FC kernel)
    gemm_fc<<<dim3(MROWS / 128, VOCAB / 128), 256, FC_SMEM>>>(
        ah, al, fh, fl, out, MROWS, VOCAB, HDIM, fc_b);
}

// round 11
// speedup vs baseline: 2.1999x; 1.7027x over previous
#include <cuda_runtime.h>
#include <cuda_bf16.h>
#include <cuda_fp16.h>
#include <math.h>
#include <stdint.h>

// Problem dims
#define VOCAB 32000
#define HDIM  1024
#define EDIM  512
#define BATCH 32
#define TSEQ  64
#define IMGF  2048
#define G4    (4*HDIM)          // 4096
#define MROWS (BATCH*TSEQ)      // 2048
#define NBLK  128               // persistent recurrence CTAs

// ---------------- device scratch (no allocation allowed) ----------------
__device__ float g_pre [MROWS * G4];     // time-major: [t][b][G4]
__device__ unsigned g_bar_ctr;

__device__ __nv_bfloat16 g_ah [MROWS * HDIM];
__device__ __nv_bfloat16 g_al [MROWS * HDIM];
__device__ __nv_bfloat16 g_w0h[G4 * EDIM];
__device__ __nv_bfloat16 g_w0l[G4 * EDIM];
__device__ __nv_bfloat16 g_w1h[G4 * HDIM];
__device__ __nv_bfloat16 g_w1l[G4 * HDIM];

// fp16 path for FC: hs1 hi/lo + fc_W single
__device__ __half g_ph [MROWS * HDIM];
__device__ __half g_pl [MROWS * HDIM];
__device__ __half g_fw [VOCAB * HDIM];

// ======================= helpers =========================================
__device__ __forceinline__ uint32_t smem_u32(const void* p) {
    uint32_t a;
    asm("{ .reg .u64 t; cvta.to.shared.u64 t, %1; cvt.u32.u64 %0, t; }"
        : "=r"(a) : "l"(p));
    return a;
}
#define SWZ(x) ((x) ^ (((x) >> 3) & 0x70))

__device__ __forceinline__ void cpa16(uint32_t dst, const void* src) {
    asm volatile("cp.async.cg.shared.global [%0], [%1], 16;"
                 :: "r"(dst), "l"(src) : "memory");
}
#define CP_COMMIT() asm volatile("cp.async.commit_group;" ::: "memory")
#define CP_WAIT0()  asm volatile("cp.async.wait_group 0;" ::: "memory")
#define CP_WAIT1()  asm volatile("cp.async.wait_group 1;" ::: "memory")
#define CP_WAIT2()  asm volatile("cp.async.wait_group 2;" ::: "memory")

__device__ __forceinline__ void ldsm_x4(uint32_t* r, uint32_t addr) {
    asm volatile("ldmatrix.sync.aligned.m8n8.x4.shared.b16 {%0,%1,%2,%3}, [%4];"
                 : "=r"(r[0]), "=r"(r[1]), "=r"(r[2]), "=r"(r[3]) : "r"(addr));
}
__device__ __forceinline__ void mma_bf16(float* c, const uint32_t* a, const uint32_t* b) {
    asm volatile(
        "mma.sync.aligned.m16n8k16.row.col.f32.bf16.bf16.f32 "
        "{%0,%1,%2,%3}, {%4,%5,%6,%7}, {%8,%9}, {%0,%1,%2,%3};"
        : "+f"(c[0]), "+f"(c[1]), "+f"(c[2]), "+f"(c[3])
        : "r"(a[0]), "r"(a[1]), "r"(a[2]), "r"(a[3]), "r"(b[0]), "r"(b[1]));
}
__device__ __forceinline__ void mma_fp16(float* c, const uint32_t* a, const uint32_t* b) {
    asm volatile(
        "mma.sync.aligned.m16n8k16.row.col.f32.f16.f16.f32 "
        "{%0,%1,%2,%3}, {%4,%5,%6,%7}, {%8,%9}, {%0,%1,%2,%3};"
        : "+f"(c[0]), "+f"(c[1]), "+f"(c[2]), "+f"(c[3])
        : "r"(a[0]), "r"(a[1]), "r"(a[2]), "r"(a[3]), "r"(b[0]), "r"(b[1]));
}
__device__ __forceinline__ void split_hilo(float x, __nv_bfloat16& h, __nv_bfloat16& l) {
    h = __float2bfloat16(x);
    l = __float2bfloat16(x - __bfloat162float(h));
}
__device__ __forceinline__ void split_hilo_f16(float x, __half& h, __half& l) {
    h = __float2half(x);
    l = __float2half(x - __half2float(h));
}

// ============== fp32 -> bf16 hi/lo split conversion (weights) ============
__global__ void cvt_hilo(const float* __restrict__ x,
                         __nv_bfloat16* __restrict__ hi,
                         __nv_bfloat16* __restrict__ lo, int n)
{
    int i = (blockIdx.x * 256 + threadIdx.x) * 4;
    if (i >= n) return;
    float4 v = *(const float4*)(x + i);
    __nv_bfloat16 h0, h1, h2, h3, l0, l1, l2, l3;
    split_hilo(v.x, h0, l0); split_hilo(v.y, h1, l1);
    split_hilo(v.z, h2, l2); split_hilo(v.w, h3, l3);
    __nv_bfloat162 ph0; ph0.x = h0; ph0.y = h1;
    __nv_bfloat162 ph1; ph1.x = h2; ph1.y = h3;
    __nv_bfloat162 pl0; pl0.x = l0; pl0.y = l1;
    __nv_bfloat162 pl1; pl1.x = l2; pl1.y = l3;
    *(__nv_bfloat162*)(hi + i)     = ph0;
    *(__nv_bfloat162*)(hi + i + 2) = ph1;
    *(__nv_bfloat162*)(lo + i)     = pl0;
    *(__nv_bfloat162*)(lo + i + 2) = pl1;
}

// ============== fp32 -> fp16 conversion (fc weights) =====================
__global__ void cvt_f16(const float* __restrict__ x, __half* __restrict__ y, int n)
{
    int i = (blockIdx.x * 256 + threadIdx.x) * 4;
    if (i >= n) return;
    float4 v = *(const float4*)(x + i);
    __half2 p0; p0.x = __float2half(v.x); p0.y = __float2half(v.y);
    __half2 p1; p1.x = __float2half(v.z); p1.y = __float2half(v.w);
    *(__half2*)(y + i)     = p0;
    *(__half2*)(y + i + 2) = p1;
}

// ============== HMMA bf16x3 GEMM (pre-GEMMs): C = A*B^T + bias ===========
// 1 CTA/SM: K-chunk 64, 3 stages x 64KB. (R8 proven.)
#define TEN_T 16384
#define STAGE (4*TEN_T)
__global__ void __launch_bounds__(256, 1)
gemm_bf16x3(const __nv_bfloat16* __restrict__ Ah, const __nv_bfloat16* __restrict__ Al,
            const __nv_bfloat16* __restrict__ Bh, const __nv_bfloat16* __restrict__ Bl,
            float* __restrict__ C, int M, int N, int K,
            const float* __restrict__ bias1, const float* __restrict__ bias2,
            int permute)
{
    extern __shared__ char dsm[];
    const int tid  = threadIdx.x;
    const int wid  = tid >> 5;
    const int lane = tid & 31;
    const int bm = blockIdx.x * 128;
    const int bn = blockIdx.y * 128;
    const int wm = (wid & 3) * 32;
    const int wn = (wid >> 2) * 64;
    const int nk = K >> 6;

    if (blockIdx.x == 0 && blockIdx.y == 0 && tid == 0) g_bar_ctr = 0u;

    uint32_t dyn = smem_u32(dsm);
    uint32_t sb0 = (dyn + 1023u) & ~1023u;

    float acc[2][8][4];
    #pragma unroll
    for (int i = 0; i < 2; i++)
        #pragma unroll
        for (int j = 0; j < 8; j++)
            #pragma unroll
            for (int r = 0; r < 4; r++) acc[i][j][r] = 0.f;

    auto issue_load = [&](int kt, int stg) {
        const uint32_t st = sb0 + (uint32_t)stg * STAGE;
        const size_t koff = (size_t)kt * 64;
        #pragma unroll
        for (int i = 0; i < 16; i++) {
            int id = i * 256 + tid;
            int tensor = id >> 10;
            int cid = id & 1023;
            int r = cid >> 3, c = cid & 7;
            uint32_t dst = st + tensor * TEN_T + SWZ((uint32_t)(r * 128 + c * 16));
            const __nv_bfloat16* src;
            if (tensor == 0)      src = Ah + (size_t)(bm + r) * K + koff + c * 8;
            else if (tensor == 1) src = Al + (size_t)(bm + r) * K + koff + c * 8;
            else if (tensor == 2) src = Bh + (size_t)(bn + r) * K + koff + c * 8;
            else                  src = Bl + (size_t)(bn + r) * K + koff + c * 8;
            cpa16(dst, src);
        }
        CP_COMMIT();
    };

    issue_load(0, 0);
    if (nk > 1) issue_load(1, 1);

    const int a_row = wm + (lane & 15);
    const int a_k8  = (lane >> 4) * 8;
    const int b_row = wn + ((lane >> 4) & 1) * 8 + (lane & 7);
    const int b_k8  = ((lane >> 3) & 1) * 8;

    uint32_t aH[2][2][4], aL[2][2][4], bH[2][4][4], bL[2][4][4];

    int s_cur = 0, s_nxt = 2;
    for (int kt = 0; kt < nk; kt++) {
        if (kt + 1 < nk) { CP_WAIT1(); } else { CP_WAIT0(); }
        __syncthreads();
        if (kt + 2 < nk) issue_load(kt + 2, s_nxt);

        const uint32_t st  = sb0 + (uint32_t)s_cur * STAGE;
        const uint32_t sAh = st;
        const uint32_t sAl = st + TEN_T;
        const uint32_t sBh = st + 2 * TEN_T;
        const uint32_t sBl = st + 3 * TEN_T;

        auto load_frags = [&](int buf, int ksv) {
            const int kb = ksv * 16;
            #pragma unroll
            for (int mi = 0; mi < 2; mi++) {
                uint32_t off = SWZ((uint32_t)((a_row + mi * 16) * 128 + (kb + a_k8) * 2));
                ldsm_x4(aH[buf][mi], sAh + off);
                ldsm_x4(aL[buf][mi], sAl + off);
            }
            #pragma unroll
            for (int p = 0; p < 4; p++) {
                uint32_t off = SWZ((uint32_t)((b_row + p * 16) * 128 + (kb + b_k8) * 2));
                ldsm_x4(bH[buf][p], sBh + off);
                ldsm_x4(bL[buf][p], sBl + off);
            }
        };

        load_frags(0, 0);
        #pragma unroll
        for (int ks = 0; ks < 4; ks++) {
            const int cb = ks & 1;
            if (ks < 3) load_frags(cb ^ 1, ks + 1);
            #pragma unroll
            for (int mi = 0; mi < 2; mi++)
                #pragma unroll
                for (int p = 0; p < 4; p++)
                    #pragma unroll
                    for (int j = 0; j < 2; j++)
                        mma_bf16(acc[mi][p * 2 + j], aH[cb][mi], &bH[cb][p][j * 2]);
            #pragma unroll
            for (int mi = 0; mi < 2; mi++)
                #pragma unroll
                for (int p = 0; p < 4; p++)
                    #pragma unroll
                    for (int j = 0; j < 2; j++)
                        mma_bf16(acc[mi][p * 2 + j], aH[cb][mi], &bL[cb][p][j * 2]);
            #pragma unroll
            for (int mi = 0; mi < 2; mi++)
                #pragma unroll
                for (int p = 0; p < 4; p++)
                    #pragma unroll
                    for (int j = 0; j < 2; j++)
                        mma_bf16(acc[mi][p * 2 + j], aL[cb][mi], &bH[cb][p][j * 2]);
        }

        s_cur = (s_cur == 2) ? 0 : s_cur + 1;
        s_nxt = (s_nxt == 2) ? 0 : s_nxt + 1;
    }

    #pragma unroll
    for (int nj = 0; nj < 8; nj++) {
        const int col = bn + wn + nj * 8 + (lane & 3) * 2;
        float b0 = 0.f, b1 = 0.f;
        if (bias1) { b0 += bias1[col]; b1 += bias1[col + 1]; }
        if (bias2) { b0 += bias2[col]; b1 += bias2[col + 1]; }
        #pragma unroll
        for (int mi = 0; mi < 2; mi++) {
            const int r0 = bm + wm + mi * 16 + (lane >> 2);
            const int r1 = r0 + 8;
            int o0 = permute ? ((r0 & 63) * 32 + (r0 >> 6)) : r0;
            int o1 = permute ? ((r1 & 63) * 32 + (r1 >> 6)) : r1;
            float2 v0 = make_float2(acc[mi][nj][0] + b0, acc[mi][nj][1] + b1);
            float2 v1 = make_float2(acc[mi][nj][2] + b0, acc[mi][nj][3] + b1);
            *(float2*)(C + (size_t)o0 * N + col) = v0;
            *(float2*)(C + (size_t)o1 * N + col) = v1;
        }
    }
}

// ============== fp16 2-term FC GEMM: C = (Ah+Al)*B^T + bias ==============
// A fp16 hi/lo, B single fp16. K-chunk 64, 3 tensors x 16KB = 48KB/stage.
#define FSTAGE (3*TEN_T)
__global__ void __launch_bounds__(256, 1)
gemm_fc_f16(const __half* __restrict__ Ah, const __half* __restrict__ Al,
            const __half* __restrict__ B,
            float* __restrict__ C, int M, int N, int K,
            const float* __restrict__ bias)
{
    extern __shared__ char dsm[];
    const int tid  = threadIdx.x;
    const int wid  = tid >> 5;
    const int lane = tid & 31;
    const int bm = blockIdx.x * 128;
    const int bn = blockIdx.y * 128;
    const int wm = (wid & 3) * 32;
    const int wn = (wid >> 2) * 64;
    const int nk = K >> 6;

    uint32_t dyn = smem_u32(dsm);
    uint32_t sb0 = (dyn + 1023u) & ~1023u;

    float acc[2][8][4];
    #pragma unroll
    for (int i = 0; i < 2; i++)
        #pragma unroll
        for (int j = 0; j < 8; j++)
            #pragma unroll
            for (int r = 0; r < 4; r++) acc[i][j][r] = 0.f;

    auto issue_load = [&](int kt, int stg) {
        const uint32_t st = sb0 + (uint32_t)stg * FSTAGE;
        const size_t koff = (size_t)kt * 64;
        #pragma unroll
        for (int i = 0; i < 12; i++) {          // 3 tensors x 1024 chunks
            int id = i * 256 + tid;
            int tensor = id >> 10;
            int cid = id & 1023;
            int r = cid >> 3, c = cid & 7;
            uint32_t dst = st + tensor * TEN_T + SWZ((uint32_t)(r * 128 + c * 16));
            const __half* src;
            if (tensor == 0)      src = Ah + (size_t)(bm + r) * K + koff + c * 8;
            else if (tensor == 1) src = Al + (size_t)(bm + r) * K + koff + c * 8;
            else                  src = B  + (size_t)(bn + r) * K + koff + c * 8;
            cpa16(dst, src);
        }
        CP_COMMIT();
    };

    issue_load(0, 0);
    if (nk > 1) issue_load(1, 1);

    const int a_row = wm + (lane & 15);
    const int a_k8  = (lane >> 4) * 8;
    const int b_row = wn + ((lane >> 4) & 1) * 8 + (lane & 7);
    const int b_k8  = ((lane >> 3) & 1) * 8;

    uint32_t aH[2][2][4], aL[2][2][4], bF[2][4][4];

    int s_cur = 0, s_nxt = 2;
    for (int kt = 0; kt < nk; kt++) {
        if (kt + 1 < nk) { CP_WAIT1(); } else { CP_WAIT0(); }
        __syncthreads();
        if (kt + 2 < nk) issue_load(kt + 2, s_nxt);

        const uint32_t st  = sb0 + (uint32_t)s_cur * FSTAGE;
        const uint32_t sAh = st;
        const uint32_t sAl = st + TEN_T;
        const uint32_t sB  = st + 2 * TEN_T;

        auto load_frags = [&](int buf, int ksv) {
            const int kb = ksv * 16;
            #pragma unroll
            for (int mi = 0; mi < 2; mi++) {
                uint32_t off = SWZ((uint32_t)((a_row + mi * 16) * 128 + (kb + a_k8) * 2));
                ldsm_x4(aH[buf][mi], sAh + off);
                ldsm_x4(aL[buf][mi], sAl + off);
            }
            #pragma unroll
            for (int p = 0; p < 4; p++) {
                uint32_t off = SWZ((uint32_t)((b_row + p * 16) * 128 + (kb + b_k8) * 2));
                ldsm_x4(bF[buf][p], sB + off);
            }
        };

        load_frags(0, 0);
        #pragma unroll
        for (int ks = 0; ks < 4; ks++) {
            const int cb = ks & 1;
            if (ks < 3) load_frags(cb ^ 1, ks + 1);
            #pragma unroll
            for (int mi = 0; mi < 2; mi++)
                #pragma unroll
                for (int p = 0; p < 4; p++)
                    #pragma unroll
                    for (int j = 0; j < 2; j++)
                        mma_fp16(acc[mi][p * 2 + j], aH[cb][mi], &bF[cb][p][j * 2]);
            #pragma unroll
            for (int mi = 0; mi < 2; mi++)
                #pragma unroll
                for (int p = 0; p < 4; p++)
                    #pragma unroll
                    for (int j = 0; j < 2; j++)
                        mma_fp16(acc[mi][p * 2 + j], aL[cb][mi], &bF[cb][p][j * 2]);
        }

        s_cur = (s_cur == 2) ? 0 : s_cur + 1;
        s_nxt = (s_nxt == 2) ? 0 : s_nxt + 1;
    }

    #pragma unroll
    for (int nj = 0; nj < 8; nj++) {
        const int col = bn + wn + nj * 8 + (lane & 3) * 2;
        const float b0 = bias[col], b1 = bias[col + 1];
        #pragma unroll
        for (int mi = 0; mi < 2; mi++) {
            const int r0 = bm + wm + mi * 16 + (lane >> 2);
            float2 v0 = make_float2(acc[mi][nj][0] + b0, acc[mi][nj][1] + b1);
            float2 v1 = make_float2(acc[mi][nj][2] + b0, acc[mi][nj][3] + b1);
            *(float2*)(C + (size_t)r0 * N + col)       = v0;
            *(float2*)(C + (size_t)(r0 + 8) * N + col) = v1;
        }
    }
}

// ---------------- linear(2048->512) + batchnorm -> bf16 hi/lo ------------
__global__ void linbn_kernel(const float* __restrict__ img,
                             const float* __restrict__ W,
                             const float* __restrict__ bias,
                             const float* __restrict__ gamma,
                             const float* __restrict__ beta,
                             __nv_bfloat16* __restrict__ ah,
                             __nv_bfloat16* __restrict__ al)
{
    const int e   = blockIdx.x;
    const int tid = threadIdx.x;
    __shared__ float wrow[IMGF];
    __shared__ float xv[BATCH];

    {
        const float* wsrc = W + (size_t)e * IMGF;
        #pragma unroll
        for (int i = 0; i < 2; i++) {
            int k = (tid + i * 256) * 4;
            *(float4*)&wrow[k] = *(const float4*)(wsrc + k);
        }
    }
    __syncthreads();

    const int lane = tid & 31, wid = tid >> 5;
    float a0 = 0.f, a1 = 0.f, a2 = 0.f, a3 = 0.f;
    for (int k = lane; k < IMGF; k += 32) {
        float wv = wrow[k];
        a0 += img[(size_t)(wid +  0) * IMGF + k] * wv;
        a1 += img[(size_t)(wid +  8) * IMGF + k] * wv;
        a2 += img[(size_t)(wid + 16) * IMGF + k] * wv;
        a3 += img[(size_t)(wid + 24) * IMGF + k] * wv;
    }
    #pragma unroll
    for (int o = 16; o > 0; o >>= 1) {
        a0 += __shfl_xor_sync(0xffffffffu, a0, o);
        a1 += __shfl_xor_sync(0xffffffffu, a1, o);
        a2 += __shfl_xor_sync(0xffffffffu, a2, o);
        a3 += __shfl_xor_sync(0xffffffffu, a3, o);
    }
    if (lane == 0) {
        float bb = bias[e];
        xv[wid +  0] = a0 + bb;
        xv[wid +  8] = a1 + bb;
        xv[wid + 16] = a2 + bb;
        xv[wid + 24] = a3 + bb;
    }
    __syncthreads();

    if (tid < 32) {
        float x = xv[tid];
        float s = x, q = x * x;
        #pragma unroll
        for (int o = 16; o > 0; o >>= 1) {
            s += __shfl_xor_sync(0xffffffffu, s, o);
            q += __shfl_xor_sync(0xffffffffu, q, o);
        }
        float mu  = s * (1.f / 32.f);
        float var = q * (1.f / 32.f) - mu * mu;
        float inv = rsqrtf(var + 1e-5f);
        float y = gamma[e] * (x - mu) * inv + beta[e];
        __nv_bfloat16 h, l;
        split_hilo(y, h, l);
        size_t idx = ((size_t)tid * TSEQ + 0) * EDIM + e;
        ah[idx] = h;
        al[idx] = l;
    }
}

// ---------------- embedding gather -> bf16 hi/lo rows t>=1 ---------------
__global__ void gather_kernel(const int* __restrict__ cap,
                              const float* __restrict__ emb,
                              __nv_bfloat16* __restrict__ ah,
                              __nv_bfloat16* __restrict__ al)
{
    const int t = blockIdx.x + 1;
    const int b = blockIdx.y;
    const int tok = cap[b * TSEQ + (t - 1)];
    const int k = threadIdx.x * 4;
    float4 v = *(const float4*)(emb + (size_t)tok * EDIM + k);
    __nv_bfloat16 h0, h1, h2, h3, l0, l1, l2, l3;
    split_hilo(v.x, h0, l0); split_hilo(v.y, h1, l1);
    split_hilo(v.z, h2, l2); split_hilo(v.w, h3, l3);
    __nv_bfloat162 ph0; ph0.x = h0; ph0.y = h1;
    __nv_bfloat162 ph1; ph1.x = h2; ph1.y = h3;
    __nv_bfloat162 pl0; pl0.x = l0; pl0.y = l1;
    __nv_bfloat162 pl1; pl1.x = l2; pl1.y = l3;
    size_t row = ((size_t)b * TSEQ + t) * EDIM + k;
    *(__nv_bfloat162*)(ah + row)     = ph0;
    *(__nv_bfloat162*)(ah + row + 2) = ph1;
    *(__nv_bfloat162*)(al + row)     = pl0;
    *(__nv_bfloat162*)(al + row + 2) = pl1;
}

// ---------------- persistent HMMA LSTM layer (R8 + optional fp16 out) -----
__global__ void __launch_bounds__(256, 1)
lstm_persist(const float* __restrict__ pre,   // [T][B][G4]
             const float* __restrict__ Whh,   // [G4][HDIM]
             __nv_bfloat16* __restrict__ ah,  // [b*T+t][HDIM]
             __nv_bfloat16* __restrict__ al,
             __half* __restrict__ ph,         // optional fp16 hi/lo (layer 1)
             __half* __restrict__ pl)
{
    extern __shared__ char sm_raw[];
    uint32_t raw = smem_u32(sm_raw);
    uint32_t sbase = (raw + 127u) & ~127u;
    char* base = sm_raw + (sbase - raw);
    const uint32_t W_HI = 0;
    const uint32_t W_LO = 65536;
    const uint32_t HBUF = 131072;            // 4 stages x 16KB
    float* g_s = (float*)(base + 196608);    // [32][33]

    const int tid  = threadIdx.x;
    const int wid  = tid >> 5;
    const int lane = tid & 31;
    const int u0   = blockIdx.x * 8;

    #pragma unroll
    for (int i = 0; i < 16; i++) {
        int cell = i * 256 + tid;
        int kt = cell >> 8;
        int r  = (cell >> 3) & 31;
        int cc = cell & 7;
        int jrow = (r >> 3) * HDIM + u0 + (r & 7);
        const float* src = Whh + (size_t)jrow * HDIM + kt * 64 + cc * 8;
        float4 v0 = *(const float4*)src;
        float4 v1 = *(const float4*)(src + 4);
        float f[8] = {v0.x, v0.y, v0.z, v0.w, v1.x, v1.y, v1.z, v1.w};
        uint32_t hi4[4], lo4[4];
        #pragma unroll
        for (int q = 0; q < 4; q++) {
            __nv_bfloat16 h0, l0, h1, l1;
            split_hilo(f[2*q],   h0, l0);
            split_hilo(f[2*q+1], h1, l1);
            __nv_bfloat162 hp; hp.x = h0; hp.y = h1;
            __nv_bfloat162 lp; lp.x = l0; lp.y = l1;
            hi4[q] = *(uint32_t*)&hp;
            lo4[q] = *(uint32_t*)&lp;
        }
        uint32_t off = kt * 4096 + SWZ((uint32_t)(r * 128 + cc * 16));
        *(uint4*)(base + W_HI + off) = make_uint4(hi4[0], hi4[1], hi4[2], hi4[3]);
        *(uint4*)(base + W_LO + off) = make_uint4(lo4[0], lo4[1], lo4[2], lo4[3]);
    }
    __syncthreads();

    const int wm = (wid & 1) * 16;
    const int wn = (wid >> 1) * 8;
    const int a_row = wm + (lane & 15);
    const int a_k8  = (lane >> 4) * 8;
    const int b_row = wn + (lane & 7);
    const int b_ku  = (lane >> 3) & 3;

    const int hr = tid >> 3;
    const int hc = tid & 7;
    const uint32_t hswz = SWZ((uint32_t)(hr * 128 + hc * 16));

    const int pb = tid >> 3;
    const int pu = tid & 7;

    const int jloc = wn + (lane & 3) * 2;
    const int jrow_e = (jloc >> 3) * HDIM + u0 + (jloc & 7);
    const int br = wm + (lane >> 2);

    float c_reg = 0.f;
    unsigned gen = 0;

    for (int t = 0; t < TSEQ; t++) {
        float acc[4] = {0.f, 0.f, 0.f, 0.f};

        const float* pt = pre + (size_t)t * BATCH * G4;
        float2 p0 = *(const float2*)(pt + (size_t)br * G4 + jrow_e);
        float2 p1 = *(const float2*)(pt + (size_t)(br + 8) * G4 + jrow_e);

        if (t > 0) {
            const size_t hrow_base = ((size_t)hr * TSEQ + (t - 1)) * HDIM + hc * 8;
            auto issue_chunk = [&](int c) {
                const uint32_t d = sbase + HBUF + (c & 3) * 16384 + hswz;
                const size_t g = hrow_base + (size_t)c * 128;
                cpa16(d,         ah + g);
                cpa16(d + 4096,  ah + g + 64);
                cpa16(d + 8192,  al + g);
                cpa16(d + 12288, al + g + 64);
                CP_COMMIT();
            };
            issue_chunk(0);
            issue_chunk(1);
            issue_chunk(2);
            for (int c = 0; c < 8; c++) {
                if (c < 6) { CP_WAIT2(); }
                else if (c == 6) { CP_WAIT1(); }
                else { CP_WAIT0(); }
                __syncthreads();
                const uint32_t stg = sbase + HBUF + (c & 3) * 16384;
                #pragma unroll
                for (int sub = 0; sub < 2; sub++) {
                    const uint32_t wc = (uint32_t)(2 * c + sub) * 4096;
                    const uint32_t hb_hi = stg + sub * 4096;
                    const uint32_t hb_lo = stg + 8192 + sub * 4096;
                    #pragma unroll
                    for (int kk2 = 0; kk2 < 2; kk2++) {
                        uint32_t bH4[4], bL4[4];
                        uint32_t boff = wc + SWZ((uint32_t)(b_row * 128 + kk2 * 64 + b_ku * 16));
                        ldsm_x4(bH4, sbase + W_HI + boff);
                        ldsm_x4(bL4, sbase + W_LO + boff);
                        #pragma unroll
                        for (int kh = 0; kh < 2; kh++) {
                            const int ks = kk2 * 2 + kh;
                            uint32_t aH4[4], aL4[4];
                            uint32_t aoff = SWZ((uint32_t)(a_row * 128 + ks * 32 + a_k8 * 2));
                            ldsm_x4(aH4, hb_hi + aoff);
                            ldsm_x4(aL4, hb_lo + aoff);
                            mma_bf16(acc, aH4, &bH4[kh * 2]);
                            mma_bf16(acc, aH4, &bL4[kh * 2]);
                            mma_bf16(acc, aL4, &bH4[kh * 2]);
                        }
                    }
                }
                if (c + 3 < 8) issue_chunk(c + 3);
            }
            __syncthreads();
        }

        g_s[jloc * 33 + br]           = acc[0] + p0.x;
        g_s[(jloc + 1) * 33 + br]     = acc[1] + p0.y;
        g_s[jloc * 33 + br + 8]       = acc[2] + p1.x;
        g_s[(jloc + 1) * 33 + br + 8] = acc[3] + p1.y;
        __syncthreads();

        {
            float gi = g_s[pu * 33 + pb];
            float gf = g_s[(8 + pu) * 33 + pb];
            float gg = g_s[(16 + pu) * 33 + pb];
            float go = g_s[(24 + pu) * 33 + pb];
            float si = 1.f / (1.f + expf(-gi));
            float sf = 1.f / (1.f + expf(-gf));
            float so = 1.f / (1.f + expf(-go));
            c_reg = sf * c_reg + si * tanhf(gg);
            float hn = so * tanhf(c_reg);
            __nv_bfloat16 hh, hl;
            split_hilo(hn, hh, hl);
            size_t orow = ((size_t)pb * TSEQ + t) * HDIM + u0 + pu;
            ah[orow] = hh;
            al[orow] = hl;
            if (ph) {
                __half fh, fl;
                split_hilo_f16(hn, fh, fl);
                ph[orow] = fh;
                pl[orow] = fl;
            }
        }
        __syncthreads();

        if (t + 1 < TSEQ) {
            gen++;
            if (tid == 0) {
                asm volatile("red.release.gpu.global.add.u32 [%0], 1;"
                             :: "l"(&g_bar_ctr) : "memory");
                unsigned tgt = gen * NBLK, v;
                do {
                    asm volatile("ld.acquire.gpu.global.u32 %0, [%1];"
                                 : "=r"(v) : "l"(&g_bar_ctr) : "memory");
                } while (v < tgt);
            }
            __syncthreads();
        }
    }
}

// ---------------- host launch --------------------------------------------
extern "C" void kernel_launch(void* const* d_in, const int* in_sizes, int n_in,
                              void* d_out, int out_size)
{
    const float* image = (const float*)d_in[0];
    const int*   caps  = (const int*)  d_in[1];
    const float* lin_W = (const float*)d_in[2];
    const float* lin_b = (const float*)d_in[3];
    const float* bn_g  = (const float*)d_in[4];
    const float* bn_b  = (const float*)d_in[5];
    const float* emb   = (const float*)d_in[6];
    const float* Wih0  = (const float*)d_in[7];
    const float* Whh0  = (const float*)d_in[8];
    const float* bih0  = (const float*)d_in[9];
    const float* bhh0  = (const float*)d_in[10];
    const float* Wih1  = (const float*)d_in[11];
    const float* Whh1  = (const float*)d_in[12];
    const float* bih1  = (const float*)d_in[13];
    const float* bhh1  = (const float*)d_in[14];
    const float* fc_W  = (const float*)d_in[15];
    const float* fc_b  = (const float*)d_in[16];
    float* out = (float*)d_out;

    float *pre;
    __nv_bfloat16 *ah, *al, *w0h, *w0l, *w1h, *w1l;
    __half *ph, *pl, *fw;
    cudaGetSymbolAddress((void**)&pre, g_pre);
    cudaGetSymbolAddress((void**)&ah,  g_ah);
    cudaGetSymbolAddress((void**)&al,  g_al);
    cudaGetSymbolAddress((void**)&w0h, g_w0h);
    cudaGetSymbolAddress((void**)&w0l, g_w0l);
    cudaGetSymbolAddress((void**)&w1h, g_w1h);
    cudaGetSymbolAddress((void**)&w1l, g_w1l);
    cudaGetSymbolAddress((void**)&ph,  g_ph);
    cudaGetSymbolAddress((void**)&pl,  g_pl);
    cudaGetSymbolAddress((void**)&fw,  g_fw);

    static int smem_set = 0;
    const int GEMM_SMEM = 3 * STAGE + 1024;          // ~193KB
    const int FC_SMEM   = 3 * FSTAGE + 1024;         // ~145KB
    const int LSTM_SMEM = 196608 + 32 * 33 * 4 + 256;
    if (!smem_set) {
        cudaFuncSetAttribute(gemm_bf16x3,
                             cudaFuncAttributeMaxDynamicSharedMemorySize, GEMM_SMEM);
        cudaFuncSetAttribute(gemm_fc_f16,
                             cudaFuncAttributeMaxDynamicSharedMemorySize, FC_SMEM);
        cudaFuncSetAttribute(lstm_persist,
                             cudaFuncAttributeMaxDynamicSharedMemorySize, LSTM_SMEM);
        smem_set = 1;
    }

    // inputs -> ah/al rows (K=EDIM layout)
    linbn_kernel<<<EDIM, 256>>>(image, lin_W, lin_b, bn_g, bn_b, ah, al);
    gather_kernel<<<dim3(TSEQ - 1, BATCH), 128>>>(caps, emb, ah, al);

    // layer-0 input weights, then pre0 GEMM (resets bar for lstm0)
    cvt_hilo<<<(G4 * EDIM / 4 + 255) / 256, 256>>>(Wih0, w0h, w0l, G4 * EDIM);
    gemm_bf16x3<<<dim3(MROWS / 128, G4 / 128), 256, GEMM_SMEM>>>(
        ah, al, w0h, w0l, pre, MROWS, G4, EDIM, bih0, bhh0, 1);

    // remaining weight conversions
    cvt_hilo<<<(G4 * HDIM / 4 + 255) / 256, 256>>>(Wih1, w1h, w1l, G4 * HDIM);
    cvt_f16<<<(VOCAB * HDIM / 4 + 255) / 256, 256>>>(fc_W, fw, VOCAB * HDIM);

    // layer-0 recurrence (bf16 out only)
    lstm_persist<<<NBLK, 256, LSTM_SMEM>>>(pre, Whh0, ah, al, nullptr, nullptr);

    // pre1 = hs0 @ Wih1^T + biases (resets bar for lstm1)
    gemm_bf16x3<<<dim3(MROWS / 128, G4 / 128), 256, GEMM_SMEM>>>(
        ah, al, w1h, w1l, pre, MROWS, G4, HDIM, bih1, bhh1, 1);

    // layer-1 recurrence (also emits fp16 hi/lo for FC)
    lstm_persist<<<NBLK, 256, LSTM_SMEM>>>(pre, Whh1, ah, al, ph, pl);

    // logits = (ph+pl) @ fw^T + fc_b  (fp16 2-term)
    gemm_fc_f16<<<dim3(MROWS / 128, VOCAB / 128), 256, FC_SMEM>>>(
        ph, pl, fw, out, MROWS, VOCAB, HDIM, fc_b);
}

// round 12
// speedup vs baseline: 2.5874x; 1.1761x over previous
#include <cuda_runtime.h>
#include <cuda_bf16.h>
#include <cuda_fp16.h>
#include <math.h>
#include <stdint.h>

// Problem dims
#define VOCAB 32000
#define HDIM  1024
#define EDIM  512
#define BATCH 32
#define TSEQ  64
#define IMGF  2048
#define G4    (4*HDIM)          // 4096
#define MROWS (BATCH*TSEQ)      // 2048
#define NBLK  128               // persistent recurrence CTAs

// ---------------- device scratch (no allocation allowed) ----------------
__device__ float g_pre [MROWS * G4];     // time-major: [t][b][G4]
__device__ unsigned g_bar_ctr;

__device__ __nv_bfloat16 g_ah [MROWS * HDIM];
__device__ __nv_bfloat16 g_al [MROWS * HDIM];
__device__ __nv_bfloat16 g_w0h[G4 * EDIM];
__device__ __nv_bfloat16 g_w0l[G4 * EDIM];
__device__ __nv_bfloat16 g_w1h[G4 * HDIM];
__device__ __nv_bfloat16 g_w1l[G4 * HDIM];

// fp16 path for FC: hs1 single + fc_W single
__device__ __half g_ph [MROWS * HDIM];
__device__ __half g_fw [VOCAB * HDIM];

// ======================= helpers =========================================
__device__ __forceinline__ uint32_t smem_u32(const void* p) {
    uint32_t a;
    asm("{ .reg .u64 t; cvta.to.shared.u64 t, %1; cvt.u32.u64 %0, t; }"
        : "=r"(a) : "l"(p));
    return a;
}
#define SWZ(x) ((x) ^ (((x) >> 3) & 0x70))

__device__ __forceinline__ void cpa16(uint32_t dst, const void* src) {
    asm volatile("cp.async.cg.shared.global [%0], [%1], 16;"
                 :: "r"(dst), "l"(src) : "memory");
}
#define CP_COMMIT() asm volatile("cp.async.commit_group;" ::: "memory")
#define CP_WAIT0()  asm volatile("cp.async.wait_group 0;" ::: "memory")
#define CP_WAIT1()  asm volatile("cp.async.wait_group 1;" ::: "memory")
#define CP_WAIT2()  asm volatile("cp.async.wait_group 2;" ::: "memory")

__device__ __forceinline__ void ldsm_x4(uint32_t* r, uint32_t addr) {
    asm volatile("ldmatrix.sync.aligned.m8n8.x4.shared.b16 {%0,%1,%2,%3}, [%4];"
                 : "=r"(r[0]), "=r"(r[1]), "=r"(r[2]), "=r"(r[3]) : "r"(addr));
}
__device__ __forceinline__ void mma_bf16(float* c, const uint32_t* a, const uint32_t* b) {
    asm volatile(
        "mma.sync.aligned.m16n8k16.row.col.f32.bf16.bf16.f32 "
        "{%0,%1,%2,%3}, {%4,%5,%6,%7}, {%8,%9}, {%0,%1,%2,%3};"
        : "+f"(c[0]), "+f"(c[1]), "+f"(c[2]), "+f"(c[3])
        : "r"(a[0]), "r"(a[1]), "r"(a[2]), "r"(a[3]), "r"(b[0]), "r"(b[1]));
}
__device__ __forceinline__ void mma_fp16(float* c, const uint32_t* a, const uint32_t* b) {
    asm volatile(
        "mma.sync.aligned.m16n8k16.row.col.f32.f16.f16.f32 "
        "{%0,%1,%2,%3}, {%4,%5,%6,%7}, {%8,%9}, {%0,%1,%2,%3};"
        : "+f"(c[0]), "+f"(c[1]), "+f"(c[2]), "+f"(c[3])
        : "r"(a[0]), "r"(a[1]), "r"(a[2]), "r"(a[3]), "r"(b[0]), "r"(b[1]));
}
__device__ __forceinline__ void split_hilo(float x, __nv_bfloat16& h, __nv_bfloat16& l) {
    h = __float2bfloat16(x);
    l = __float2bfloat16(x - __bfloat162float(h));
}

// ============== fp32 -> bf16 hi/lo split conversion (weights) ============
__global__ void cvt_hilo(const float* __restrict__ x,
                         __nv_bfloat16* __restrict__ hi,
                         __nv_bfloat16* __restrict__ lo, int n)
{
    int i = (blockIdx.x * 256 + threadIdx.x) * 4;
    if (i >= n) return;
    float4 v = *(const float4*)(x + i);
    __nv_bfloat16 h0, h1, h2, h3, l0, l1, l2, l3;
    split_hilo(v.x, h0, l0); split_hilo(v.y, h1, l1);
    split_hilo(v.z, h2, l2); split_hilo(v.w, h3, l3);
    __nv_bfloat162 ph0; ph0.x = h0; ph0.y = h1;
    __nv_bfloat162 ph1; ph1.x = h2; ph1.y = h3;
    __nv_bfloat162 pl0; pl0.x = l0; pl0.y = l1;
    __nv_bfloat162 pl1; pl1.x = l2; pl1.y = l3;
    *(__nv_bfloat162*)(hi + i)     = ph0;
    *(__nv_bfloat162*)(hi + i + 2) = ph1;
    *(__nv_bfloat162*)(lo + i)     = pl0;
    *(__nv_bfloat162*)(lo + i + 2) = pl1;
}

// ============== fp32 -> fp16 conversion (fc weights) =====================
__global__ void cvt_f16(const float* __restrict__ x, __half* __restrict__ y, int n)
{
    int i = (blockIdx.x * 256 + threadIdx.x) * 4;
    if (i >= n) return;
    float4 v = *(const float4*)(x + i);
    __half2 p0; p0.x = __float2half(v.x); p0.y = __float2half(v.y);
    __half2 p1; p1.x = __float2half(v.z); p1.y = __float2half(v.w);
    *(__half2*)(y + i)     = p0;
    *(__half2*)(y + i + 2) = p1;
}

// ============== HMMA bf16x3 GEMM (pre-GEMMs): C = A*B^T + bias ===========
// 1 CTA/SM: K-chunk 64, 3 stages x 64KB. (R8 proven.)
#define TEN_T 16384
#define STAGE (4*TEN_T)
__global__ void __launch_bounds__(256, 1)
gemm_bf16x3(const __nv_bfloat16* __restrict__ Ah, const __nv_bfloat16* __restrict__ Al,
            const __nv_bfloat16* __restrict__ Bh, const __nv_bfloat16* __restrict__ Bl,
            float* __restrict__ C, int M, int N, int K,
            const float* __restrict__ bias1, const float* __restrict__ bias2,
            int permute)
{
    extern __shared__ char dsm[];
    const int tid  = threadIdx.x;
    const int wid  = tid >> 5;
    const int lane = tid & 31;
    const int bm = blockIdx.x * 128;
    const int bn = blockIdx.y * 128;
    const int wm = (wid & 3) * 32;
    const int wn = (wid >> 2) * 64;
    const int nk = K >> 6;

    if (blockIdx.x == 0 && blockIdx.y == 0 && tid == 0) g_bar_ctr = 0u;

    uint32_t dyn = smem_u32(dsm);
    uint32_t sb0 = (dyn + 1023u) & ~1023u;

    float acc[2][8][4];
    #pragma unroll
    for (int i = 0; i < 2; i++)
        #pragma unroll
        for (int j = 0; j < 8; j++)
            #pragma unroll
            for (int r = 0; r < 4; r++) acc[i][j][r] = 0.f;

    auto issue_load = [&](int kt, int stg) {
        const uint32_t st = sb0 + (uint32_t)stg * STAGE;
        const size_t koff = (size_t)kt * 64;
        #pragma unroll
        for (int i = 0; i < 16; i++) {
            int id = i * 256 + tid;
            int tensor = id >> 10;
            int cid = id & 1023;
            int r = cid >> 3, c = cid & 7;
            uint32_t dst = st + tensor * TEN_T + SWZ((uint32_t)(r * 128 + c * 16));
            const __nv_bfloat16* src;
            if (tensor == 0)      src = Ah + (size_t)(bm + r) * K + koff + c * 8;
            else if (tensor == 1) src = Al + (size_t)(bm + r) * K + koff + c * 8;
            else if (tensor == 2) src = Bh + (size_t)(bn + r) * K + koff + c * 8;
            else                  src = Bl + (size_t)(bn + r) * K + koff + c * 8;
            cpa16(dst, src);
        }
        CP_COMMIT();
    };

    issue_load(0, 0);
    if (nk > 1) issue_load(1, 1);

    const int a_row = wm + (lane & 15);
    const int a_k8  = (lane >> 4) * 8;
    const int b_row = wn + ((lane >> 4) & 1) * 8 + (lane & 7);
    const int b_k8  = ((lane >> 3) & 1) * 8;

    uint32_t aH[2][2][4], aL[2][2][4], bH[2][4][4], bL[2][4][4];

    int s_cur = 0, s_nxt = 2;
    for (int kt = 0; kt < nk; kt++) {
        if (kt + 1 < nk) { CP_WAIT1(); } else { CP_WAIT0(); }
        __syncthreads();
        if (kt + 2 < nk) issue_load(kt + 2, s_nxt);

        const uint32_t st  = sb0 + (uint32_t)s_cur * STAGE;
        const uint32_t sAh = st;
        const uint32_t sAl = st + TEN_T;
        const uint32_t sBh = st + 2 * TEN_T;
        const uint32_t sBl = st + 3 * TEN_T;

        auto load_frags = [&](int buf, int ksv) {
            const int kb = ksv * 16;
            #pragma unroll
            for (int mi = 0; mi < 2; mi++) {
                uint32_t off = SWZ((uint32_t)((a_row + mi * 16) * 128 + (kb + a_k8) * 2));
                ldsm_x4(aH[buf][mi], sAh + off);
                ldsm_x4(aL[buf][mi], sAl + off);
            }
            #pragma unroll
            for (int p = 0; p < 4; p++) {
                uint32_t off = SWZ((uint32_t)((b_row + p * 16) * 128 + (kb + b_k8) * 2));
                ldsm_x4(bH[buf][p], sBh + off);
                ldsm_x4(bL[buf][p], sBl + off);
            }
        };

        load_frags(0, 0);
        #pragma unroll
        for (int ks = 0; ks < 4; ks++) {
            const int cb = ks & 1;
            if (ks < 3) load_frags(cb ^ 1, ks + 1);
            #pragma unroll
            for (int mi = 0; mi < 2; mi++)
                #pragma unroll
                for (int p = 0; p < 4; p++)
                    #pragma unroll
                    for (int j = 0; j < 2; j++)
                        mma_bf16(acc[mi][p * 2 + j], aH[cb][mi], &bH[cb][p][j * 2]);
            #pragma unroll
            for (int mi = 0; mi < 2; mi++)
                #pragma unroll
                for (int p = 0; p < 4; p++)
                    #pragma unroll
                    for (int j = 0; j < 2; j++)
                        mma_bf16(acc[mi][p * 2 + j], aH[cb][mi], &bL[cb][p][j * 2]);
            #pragma unroll
            for (int mi = 0; mi < 2; mi++)
                #pragma unroll
                for (int p = 0; p < 4; p++)
                    #pragma unroll
                    for (int j = 0; j < 2; j++)
                        mma_bf16(acc[mi][p * 2 + j], aL[cb][mi], &bH[cb][p][j * 2]);
        }

        s_cur = (s_cur == 2) ? 0 : s_cur + 1;
        s_nxt = (s_nxt == 2) ? 0 : s_nxt + 1;
    }

    #pragma unroll
    for (int nj = 0; nj < 8; nj++) {
        const int col = bn + wn + nj * 8 + (lane & 3) * 2;
        float b0 = 0.f, b1 = 0.f;
        if (bias1) { b0 += bias1[col]; b1 += bias1[col + 1]; }
        if (bias2) { b0 += bias2[col]; b1 += bias2[col + 1]; }
        #pragma unroll
        for (int mi = 0; mi < 2; mi++) {
            const int r0 = bm + wm + mi * 16 + (lane >> 2);
            const int r1 = r0 + 8;
            int o0 = permute ? ((r0 & 63) * 32 + (r0 >> 6)) : r0;
            int o1 = permute ? ((r1 & 63) * 32 + (r1 >> 6)) : r1;
            float2 v0 = make_float2(acc[mi][nj][0] + b0, acc[mi][nj][1] + b1);
            float2 v1 = make_float2(acc[mi][nj][2] + b0, acc[mi][nj][3] + b1);
            *(float2*)(C + (size_t)o0 * N + col) = v0;
            *(float2*)(C + (size_t)o1 * N + col) = v1;
        }
    }
}

// ============== fp16 1-term FC GEMM: C = A*B^T + bias ====================
// A, B single fp16. K-chunk 64, 2 tensors x 16KB = 32KB/stage, 3 stages.
#define FSTAGE (2*TEN_T)
__global__ void __launch_bounds__(256, 1)
gemm_fc_f16(const __half* __restrict__ A, const __half* __restrict__ B,
            float* __restrict__ C, int M, int N, int K,
            const float* __restrict__ bias)
{
    extern __shared__ char dsm[];
    const int tid  = threadIdx.x;
    const int wid  = tid >> 5;
    const int lane = tid & 31;
    const int bm = blockIdx.x * 128;
    const int bn = blockIdx.y * 128;
    const int wm = (wid & 3) * 32;
    const int wn = (wid >> 2) * 64;
    const int nk = K >> 6;

    uint32_t dyn = smem_u32(dsm);
    uint32_t sb0 = (dyn + 1023u) & ~1023u;

    float acc[2][8][4];
    #pragma unroll
    for (int i = 0; i < 2; i++)
        #pragma unroll
        for (int j = 0; j < 8; j++)
            #pragma unroll
            for (int r = 0; r < 4; r++) acc[i][j][r] = 0.f;

    auto issue_load = [&](int kt, int stg) {
        const uint32_t st = sb0 + (uint32_t)stg * FSTAGE;
        const size_t koff = (size_t)kt * 64;
        #pragma unroll
        for (int i = 0; i < 8; i++) {           // 2 tensors x 1024 chunks
            int id = i * 256 + tid;
            int tensor = id >> 10;
            int cid = id & 1023;
            int r = cid >> 3, c = cid & 7;
            uint32_t dst = st + tensor * TEN_T + SWZ((uint32_t)(r * 128 + c * 16));
            const __half* src;
            if (tensor == 0) src = A + (size_t)(bm + r) * K + koff + c * 8;
            else             src = B + (size_t)(bn + r) * K + koff + c * 8;
            cpa16(dst, src);
        }
        CP_COMMIT();
    };

    issue_load(0, 0);
    if (nk > 1) issue_load(1, 1);

    const int a_row = wm + (lane & 15);
    const int a_k8  = (lane >> 4) * 8;
    const int b_row = wn + ((lane >> 4) & 1) * 8 + (lane & 7);
    const int b_k8  = ((lane >> 3) & 1) * 8;

    uint32_t aF[2][2][4], bF[2][4][4];

    int s_cur = 0, s_nxt = 2;
    for (int kt = 0; kt < nk; kt++) {
        if (kt + 1 < nk) { CP_WAIT1(); } else { CP_WAIT0(); }
        __syncthreads();
        if (kt + 2 < nk) issue_load(kt + 2, s_nxt);

        const uint32_t st = sb0 + (uint32_t)s_cur * FSTAGE;
        const uint32_t sA = st;
        const uint32_t sB = st + TEN_T;

        auto load_frags = [&](int buf, int ksv) {
            const int kb = ksv * 16;
            #pragma unroll
            for (int mi = 0; mi < 2; mi++) {
                uint32_t off = SWZ((uint32_t)((a_row + mi * 16) * 128 + (kb + a_k8) * 2));
                ldsm_x4(aF[buf][mi], sA + off);
            }
            #pragma unroll
            for (int p = 0; p < 4; p++) {
                uint32_t off = SWZ((uint32_t)((b_row + p * 16) * 128 + (kb + b_k8) * 2));
                ldsm_x4(bF[buf][p], sB + off);
            }
        };

        load_frags(0, 0);
        #pragma unroll
        for (int ks = 0; ks < 4; ks++) {
            const int cb = ks & 1;
            if (ks < 3) load_frags(cb ^ 1, ks + 1);
            #pragma unroll
            for (int mi = 0; mi < 2; mi++)
                #pragma unroll
                for (int p = 0; p < 4; p++)
                    #pragma unroll
                    for (int j = 0; j < 2; j++)
                        mma_fp16(acc[mi][p * 2 + j], aF[cb][mi], &bF[cb][p][j * 2]);
        }

        s_cur = (s_cur == 2) ? 0 : s_cur + 1;
        s_nxt = (s_nxt == 2) ? 0 : s_nxt + 1;
    }

    #pragma unroll
    for (int nj = 0; nj < 8; nj++) {
        const int col = bn + wn + nj * 8 + (lane & 3) * 2;
        const float b0 = bias[col], b1 = bias[col + 1];
        #pragma unroll
        for (int mi = 0; mi < 2; mi++) {
            const int r0 = bm + wm + mi * 16 + (lane >> 2);
            float2 v0 = make_float2(acc[mi][nj][0] + b0, acc[mi][nj][1] + b1);
            float2 v1 = make_float2(acc[mi][nj][2] + b0, acc[mi][nj][3] + b1);
            *(float2*)(C + (size_t)r0 * N + col)       = v0;
            *(float2*)(C + (size_t)(r0 + 8) * N + col) = v1;
        }
    }
}

// ---------------- linear(2048->512) + batchnorm -> bf16 hi/lo ------------
__global__ void linbn_kernel(const float* __restrict__ img,
                             const float* __restrict__ W,
                             const float* __restrict__ bias,
                             const float* __restrict__ gamma,
                             const float* __restrict__ beta,
                             __nv_bfloat16* __restrict__ ah,
                             __nv_bfloat16* __restrict__ al)
{
    const int e   = blockIdx.x;
    const int tid = threadIdx.x;
    __shared__ float wrow[IMGF];
    __shared__ float xv[BATCH];

    {
        const float* wsrc = W + (size_t)e * IMGF;
        #pragma unroll
        for (int i = 0; i < 2; i++) {
            int k = (tid + i * 256) * 4;
            *(float4*)&wrow[k] = *(const float4*)(wsrc + k);
        }
    }
    __syncthreads();

    const int lane = tid & 31, wid = tid >> 5;
    float a0 = 0.f, a1 = 0.f, a2 = 0.f, a3 = 0.f;
    for (int k = lane; k < IMGF; k += 32) {
        float wv = wrow[k];
        a0 += img[(size_t)(wid +  0) * IMGF + k] * wv;
        a1 += img[(size_t)(wid +  8) * IMGF + k] * wv;
        a2 += img[(size_t)(wid + 16) * IMGF + k] * wv;
        a3 += img[(size_t)(wid + 24) * IMGF + k] * wv;
    }
    #pragma unroll
    for (int o = 16; o > 0; o >>= 1) {
        a0 += __shfl_xor_sync(0xffffffffu, a0, o);
        a1 += __shfl_xor_sync(0xffffffffu, a1, o);
        a2 += __shfl_xor_sync(0xffffffffu, a2, o);
        a3 += __shfl_xor_sync(0xffffffffu, a3, o);
    }
    if (lane == 0) {
        float bb = bias[e];
        xv[wid +  0] = a0 + bb;
        xv[wid +  8] = a1 + bb;
        xv[wid + 16] = a2 + bb;
        xv[wid + 24] = a3 + bb;
    }
    __syncthreads();

    if (tid < 32) {
        float x = xv[tid];
        float s = x, q = x * x;
        #pragma unroll
        for (int o = 16; o > 0; o >>= 1) {
            s += __shfl_xor_sync(0xffffffffu, s, o);
            q += __shfl_xor_sync(0xffffffffu, q, o);
        }
        float mu  = s * (1.f / 32.f);
        float var = q * (1.f / 32.f) - mu * mu;
        float inv = rsqrtf(var + 1e-5f);
        float y = gamma[e] * (x - mu) * inv + beta[e];
        __nv_bfloat16 h, l;
        split_hilo(y, h, l);
        size_t idx = ((size_t)tid * TSEQ + 0) * EDIM + e;
        ah[idx] = h;
        al[idx] = l;
    }
}

// ---------------- embedding gather -> bf16 hi/lo rows t>=1 ---------------
__global__ void gather_kernel(const int* __restrict__ cap,
                              const float* __restrict__ emb,
                              __nv_bfloat16* __restrict__ ah,
                              __nv_bfloat16* __restrict__ al)
{
    const int t = blockIdx.x + 1;
    const int b = blockIdx.y;
    const int tok = cap[b * TSEQ + (t - 1)];
    const int k = threadIdx.x * 4;
    float4 v = *(const float4*)(emb + (size_t)tok * EDIM + k);
    __nv_bfloat16 h0, h1, h2, h3, l0, l1, l2, l3;
    split_hilo(v.x, h0, l0); split_hilo(v.y, h1, l1);
    split_hilo(v.z, h2, l2); split_hilo(v.w, h3, l3);
    __nv_bfloat162 ph0; ph0.x = h0; ph0.y = h1;
    __nv_bfloat162 ph1; ph1.x = h2; ph1.y = h3;
    __nv_bfloat162 pl0; pl0.x = l0; pl0.y = l1;
    __nv_bfloat162 pl1; pl1.x = l2; pl1.y = l3;
    size_t row = ((size_t)b * TSEQ + t) * EDIM + k;
    *(__nv_bfloat162*)(ah + row)     = ph0;
    *(__nv_bfloat162*)(ah + row + 2) = ph1;
    *(__nv_bfloat162*)(al + row)     = pl0;
    *(__nv_bfloat162*)(al + row + 2) = pl1;
}

// ---------------- persistent HMMA LSTM layer (R8 + optional fp16 out) -----
__global__ void __launch_bounds__(256, 1)
lstm_persist(const float* __restrict__ pre,   // [T][B][G4]
             const float* __restrict__ Whh,   // [G4][HDIM]
             __nv_bfloat16* __restrict__ ah,  // [b*T+t][HDIM]
             __nv_bfloat16* __restrict__ al,
             __half* __restrict__ ph)         // optional fp16 h (layer 1)
{
    extern __shared__ char sm_raw[];
    uint32_t raw = smem_u32(sm_raw);
    uint32_t sbase = (raw + 127u) & ~127u;
    char* base = sm_raw + (sbase - raw);
    const uint32_t W_HI = 0;
    const uint32_t W_LO = 65536;
    const uint32_t HBUF = 131072;            // 4 stages x 16KB
    float* g_s = (float*)(base + 196608);    // [32][33]

    const int tid  = threadIdx.x;
    const int wid  = tid >> 5;
    const int lane = tid & 31;
    const int u0   = blockIdx.x * 8;

    #pragma unroll
    for (int i = 0; i < 16; i++) {
        int cell = i * 256 + tid;
        int kt = cell >> 8;
        int r  = (cell >> 3) & 31;
        int cc = cell & 7;
        int jrow = (r >> 3) * HDIM + u0 + (r & 7);
        const float* src = Whh + (size_t)jrow * HDIM + kt * 64 + cc * 8;
        float4 v0 = *(const float4*)src;
        float4 v1 = *(const float4*)(src + 4);
        float f[8] = {v0.x, v0.y, v0.z, v0.w, v1.x, v1.y, v1.z, v1.w};
        uint32_t hi4[4], lo4[4];
        #pragma unroll
        for (int q = 0; q < 4; q++) {
            __nv_bfloat16 h0, l0, h1, l1;
            split_hilo(f[2*q],   h0, l0);
            split_hilo(f[2*q+1], h1, l1);
            __nv_bfloat162 hp; hp.x = h0; hp.y = h1;
            __nv_bfloat162 lp; lp.x = l0; lp.y = l1;
            hi4[q] = *(uint32_t*)&hp;
            lo4[q] = *(uint32_t*)&lp;
        }
        uint32_t off = kt * 4096 + SWZ((uint32_t)(r * 128 + cc * 16));
        *(uint4*)(base + W_HI + off) = make_uint4(hi4[0], hi4[1], hi4[2], hi4[3]);
        *(uint4*)(base + W_LO + off) = make_uint4(lo4[0], lo4[1], lo4[2], lo4[3]);
    }
    __syncthreads();

    const int wm = (wid & 1) * 16;
    const int wn = (wid >> 1) * 8;
    const int a_row = wm + (lane & 15);
    const int a_k8  = (lane >> 4) * 8;
    const int b_row = wn + (lane & 7);
    const int b_ku  = (lane >> 3) & 3;

    const int hr = tid >> 3;
    const int hc = tid & 7;
    const uint32_t hswz = SWZ((uint32_t)(hr * 128 + hc * 16));

    const int pb = tid >> 3;
    const int pu = tid & 7;

    const int jloc = wn + (lane & 3) * 2;
    const int jrow_e = (jloc >> 3) * HDIM + u0 + (jloc & 7);
    const int br = wm + (lane >> 2);

    float c_reg = 0.f;
    unsigned gen = 0;

    for (int t = 0; t < TSEQ; t++) {
        float acc[4] = {0.f, 0.f, 0.f, 0.f};

        const float* pt = pre + (size_t)t * BATCH * G4;
        float2 p0 = *(const float2*)(pt + (size_t)br * G4 + jrow_e);
        float2 p1 = *(const float2*)(pt + (size_t)(br + 8) * G4 + jrow_e);

        if (t > 0) {
            const size_t hrow_base = ((size_t)hr * TSEQ + (t - 1)) * HDIM + hc * 8;
            auto issue_chunk = [&](int c) {
                const uint32_t d = sbase + HBUF + (c & 3) * 16384 + hswz;
                const size_t g = hrow_base + (size_t)c * 128;
                cpa16(d,         ah + g);
                cpa16(d + 4096,  ah + g + 64);
                cpa16(d + 8192,  al + g);
                cpa16(d + 12288, al + g + 64);
                CP_COMMIT();
            };
            issue_chunk(0);
            issue_chunk(1);
            issue_chunk(2);
            for (int c = 0; c < 8; c++) {
                if (c < 6) { CP_WAIT2(); }
                else if (c == 6) { CP_WAIT1(); }
                else { CP_WAIT0(); }
                __syncthreads();
                const uint32_t stg = sbase + HBUF + (c & 3) * 16384;
                #pragma unroll
                for (int sub = 0; sub < 2; sub++) {
                    const uint32_t wc = (uint32_t)(2 * c + sub) * 4096;
                    const uint32_t hb_hi = stg + sub * 4096;
                    const uint32_t hb_lo = stg + 8192 + sub * 4096;
                    #pragma unroll
                    for (int kk2 = 0; kk2 < 2; kk2++) {
                        uint32_t bH4[4], bL4[4];
                        uint32_t boff = wc + SWZ((uint32_t)(b_row * 128 + kk2 * 64 + b_ku * 16));
                        ldsm_x4(bH4, sbase + W_HI + boff);
                        ldsm_x4(bL4, sbase + W_LO + boff);
                        #pragma unroll
                        for (int kh = 0; kh < 2; kh++) {
                            const int ks = kk2 * 2 + kh;
                            uint32_t aH4[4], aL4[4];
                            uint32_t aoff = SWZ((uint32_t)(a_row * 128 + ks * 32 + a_k8 * 2));
                            ldsm_x4(aH4, hb_hi + aoff);
                            ldsm_x4(aL4, hb_lo + aoff);
                            mma_bf16(acc, aH4, &bH4[kh * 2]);
                            mma_bf16(acc, aH4, &bL4[kh * 2]);
                            mma_bf16(acc, aL4, &bH4[kh * 2]);
                        }
                    }
                }
                if (c + 3 < 8) issue_chunk(c + 3);
            }
            __syncthreads();
        }

        g_s[jloc * 33 + br]           = acc[0] + p0.x;
        g_s[(jloc + 1) * 33 + br]     = acc[1] + p0.y;
        g_s[jloc * 33 + br + 8]       = acc[2] + p1.x;
        g_s[(jloc + 1) * 33 + br + 8] = acc[3] + p1.y;
        __syncthreads();

        {
            float gi = g_s[pu * 33 + pb];
            float gf = g_s[(8 + pu) * 33 + pb];
            float gg = g_s[(16 + pu) * 33 + pb];
            float go = g_s[(24 + pu) * 33 + pb];
            float si = 1.f / (1.f + expf(-gi));
            float sf = 1.f / (1.f + expf(-gf));
            float so = 1.f / (1.f + expf(-go));
            c_reg = sf * c_reg + si * tanhf(gg);
            float hn = so * tanhf(c_reg);
            __nv_bfloat16 hh, hl;
            split_hilo(hn, hh, hl);
            size_t orow = ((size_t)pb * TSEQ + t) * HDIM + u0 + pu;
            ah[orow] = hh;
            al[orow] = hl;
            if (ph) ph[orow] = __float2half(hn);
        }
        __syncthreads();

        if (t + 1 < TSEQ) {
            gen++;
            if (tid == 0) {
                asm volatile("red.release.gpu.global.add.u32 [%0], 1;"
                             :: "l"(&g_bar_ctr) : "memory");
                unsigned tgt = gen * NBLK, v;
                do {
                    asm volatile("ld.acquire.gpu.global.u32 %0, [%1];"
                                 : "=r"(v) : "l"(&g_bar_ctr) : "memory");
                } while (v < tgt);
            }
            __syncthreads();
        }
    }
}

// ---------------- host launch --------------------------------------------
extern "C" void kernel_launch(void* const* d_in, const int* in_sizes, int n_in,
                              void* d_out, int out_size)
{
    const float* image = (const float*)d_in[0];
    const int*   caps  = (const int*)  d_in[1];
    const float* lin_W = (const float*)d_in[2];
    const float* lin_b = (const float*)d_in[3];
    const float* bn_g  = (const float*)d_in[4];
    const float* bn_b  = (const float*)d_in[5];
    const float* emb   = (const float*)d_in[6];
    const float* Wih0  = (const float*)d_in[7];
    const float* Whh0  = (const float*)d_in[8];
    const float* bih0  = (const float*)d_in[9];
    const float* bhh0  = (const float*)d_in[10];
    const float* Wih1  = (const float*)d_in[11];
    const float* Whh1  = (const float*)d_in[12];
    const float* bih1  = (const float*)d_in[13];
    const float* bhh1  = (const float*)d_in[14];
    const float* fc_W  = (const float*)d_in[15];
    const float* fc_b  = (const float*)d_in[16];
    float* out = (float*)d_out;

    float *pre;
    __nv_bfloat16 *ah, *al, *w0h, *w0l, *w1h, *w1l;
    __half *ph, *fw;
    cudaGetSymbolAddress((void**)&pre, g_pre);
    cudaGetSymbolAddress((void**)&ah,  g_ah);
    cudaGetSymbolAddress((void**)&al,  g_al);
    cudaGetSymbolAddress((void**)&w0h, g_w0h);
    cudaGetSymbolAddress((void**)&w0l, g_w0l);
    cudaGetSymbolAddress((void**)&w1h, g_w1h);
    cudaGetSymbolAddress((void**)&w1l, g_w1l);
    cudaGetSymbolAddress((void**)&ph,  g_ph);
    cudaGetSymbolAddress((void**)&fw,  g_fw);

    static int smem_set = 0;
    const int GEMM_SMEM = 3 * STAGE + 1024;          // ~193KB
    const int FC_SMEM   = 3 * FSTAGE + 1024;         // ~97KB
    const int LSTM_SMEM = 196608 + 32 * 33 * 4 + 256;
    if (!smem_set) {
        cudaFuncSetAttribute(gemm_bf16x3,
                             cudaFuncAttributeMaxDynamicSharedMemorySize, GEMM_SMEM);
        cudaFuncSetAttribute(gemm_fc_f16,
                             cudaFuncAttributeMaxDynamicSharedMemorySize, FC_SMEM);
        cudaFuncSetAttribute(lstm_persist,
                             cudaFuncAttributeMaxDynamicSharedMemorySize, LSTM_SMEM);
        smem_set = 1;
    }

    // inputs -> ah/al rows (K=EDIM layout)
    linbn_kernel<<<EDIM, 256>>>(image, lin_W, lin_b, bn_g, bn_b, ah, al);
    gather_kernel<<<dim3(TSEQ - 1, BATCH), 128>>>(caps, emb, ah, al);

    // layer-0 input weights, then pre0 GEMM (resets bar for lstm0)
    cvt_hilo<<<(G4 * EDIM / 4 + 255) / 256, 256>>>(Wih0, w0h, w0l, G4 * EDIM);
    gemm_bf16x3<<<dim3(MROWS / 128, G4 / 128), 256, GEMM_SMEM>>>(
        ah, al, w0h, w0l, pre, MROWS, G4, EDIM, bih0, bhh0, 1);

    // remaining weight conversions
    cvt_hilo<<<(G4 * HDIM / 4 + 255) / 256, 256>>>(Wih1, w1h, w1l, G4 * HDIM);
    cvt_f16<<<(VOCAB * HDIM / 4 + 255) / 256, 256>>>(fc_W, fw, VOCAB * HDIM);

    // layer-0 recurrence (bf16 out only)
    lstm_persist<<<NBLK, 256, LSTM_SMEM>>>(pre, Whh0, ah, al, nullptr);

    // pre1 = hs0 @ Wih1^T + biases (resets bar for lstm1)
    gemm_bf16x3<<<dim3(MROWS / 128, G4 / 128), 256, GEMM_SMEM>>>(
        ah, al, w1h, w1l, pre, MROWS, G4, HDIM, bih1, bhh1, 1);

    // layer-1 recurrence (also emits fp16 h for FC)
    lstm_persist<<<NBLK, 256, LSTM_SMEM>>>(pre, Whh1, ah, al, ph);

    // logits = ph @ fw^T + fc_b  (fp16 1-term)
    gemm_fc_f16<<<dim3(MROWS / 128, VOCAB / 128), 256, FC_SMEM>>>(
        ph, fw, out, MROWS, VOCAB, HDIM, fc_b);
}

// round 13
// speedup vs baseline: 2.6996x; 1.0434x over previous
#include <cuda_runtime.h>
#include <cuda_fp16.h>
#include <math.h>
#include <stdint.h>

// Problem dims
#define VOCAB 32000
#define HDIM  1024
#define EDIM  512
#define BATCH 32
#define TSEQ  64
#define IMGF  2048
#define G4    (4*HDIM)          // 4096
#define MROWS (BATCH*TSEQ)      // 2048
#define NBLK  128               // persistent recurrence CTAs

// ---------------- device scratch (no allocation allowed) ----------------
__device__ float g_pre [MROWS * G4];     // time-major: [t][b][G4]
__device__ unsigned g_bar_ctr;

// fp16 hi/lo activations; fp16 single weights
__device__ __half g_ah [MROWS * HDIM];
__device__ __half g_al [MROWS * HDIM];
__device__ __half g_w0 [G4 * EDIM];
__device__ __half g_w1 [G4 * HDIM];
__device__ __half g_fw [VOCAB * HDIM];

// ======================= helpers =========================================
__device__ __forceinline__ uint32_t smem_u32(const void* p) {
    uint32_t a;
    asm("{ .reg .u64 t; cvta.to.shared.u64 t, %1; cvt.u32.u64 %0, t; }"
        : "=r"(a) : "l"(p));
    return a;
}
#define SWZ(x) ((x) ^ (((x) >> 3) & 0x70))

__device__ __forceinline__ void cpa16(uint32_t dst, const void* src) {
    asm volatile("cp.async.cg.shared.global [%0], [%1], 16;"
                 :: "r"(dst), "l"(src) : "memory");
}
#define CP_COMMIT() asm volatile("cp.async.commit_group;" ::: "memory")
#define CP_WAIT0()  asm volatile("cp.async.wait_group 0;" ::: "memory")
#define CP_WAIT1()  asm volatile("cp.async.wait_group 1;" ::: "memory")
#define CP_WAIT2()  asm volatile("cp.async.wait_group 2;" ::: "memory")

__device__ __forceinline__ void ldsm_x4(uint32_t* r, uint32_t addr) {
    asm volatile("ldmatrix.sync.aligned.m8n8.x4.shared.b16 {%0,%1,%2,%3}, [%4];"
                 : "=r"(r[0]), "=r"(r[1]), "=r"(r[2]), "=r"(r[3]) : "r"(addr));
}
__device__ __forceinline__ void mma_fp16(float* c, const uint32_t* a, const uint32_t* b) {
    asm volatile(
        "mma.sync.aligned.m16n8k16.row.col.f32.f16.f16.f32 "
        "{%0,%1,%2,%3}, {%4,%5,%6,%7}, {%8,%9}, {%0,%1,%2,%3};"
        : "+f"(c[0]), "+f"(c[1]), "+f"(c[2]), "+f"(c[3])
        : "r"(a[0]), "r"(a[1]), "r"(a[2]), "r"(a[3]), "r"(b[0]), "r"(b[1]));
}
__device__ __forceinline__ void split_f16(float x, __half& h, __half& l) {
    h = __float2half(x);
    l = __float2half(x - __half2float(h));
}

// ============== fp32 -> fp16 conversion (weights) ========================
__global__ void cvt_f16(const float* __restrict__ x, __half* __restrict__ y, int n)
{
    int i = (blockIdx.x * 256 + threadIdx.x) * 4;
    if (i >= n) return;
    float4 v = *(const float4*)(x + i);
    __half2 p0; p0.x = __float2half(v.x); p0.y = __float2half(v.y);
    __half2 p1; p1.x = __float2half(v.z); p1.y = __float2half(v.w);
    *(__half2*)(y + i)     = p0;
    *(__half2*)(y + i + 2) = p1;
}

// ============== fp16 2-term pre-GEMM: C = (Ah+Al)*B^T + bias =============
// A fp16 hi/lo, B single fp16. K-chunk 64, 3 tensors x 16KB = 48KB/stage.
#define TEN_T 16384
#define PSTAGE (3*TEN_T)
__global__ void __launch_bounds__(256, 1)
gemm_pre(const __half* __restrict__ Ah, const __half* __restrict__ Al,
         const __half* __restrict__ B,
         float* __restrict__ C, int M, int N, int K,
         const float* __restrict__ bias1, const float* __restrict__ bias2,
         int permute)
{
    extern __shared__ char dsm[];
    const int tid  = threadIdx.x;
    const int wid  = tid >> 5;
    const int lane = tid & 31;
    const int bm = blockIdx.x * 128;
    const int bn = blockIdx.y * 128;
    const int wm = (wid & 3) * 32;
    const int wn = (wid >> 2) * 64;
    const int nk = K >> 6;

    // fold in the grid-barrier reset for the following lstm launch
    if (blockIdx.x == 0 && blockIdx.y == 0 && tid == 0) g_bar_ctr = 0u;

    uint32_t dyn = smem_u32(dsm);
    uint32_t sb0 = (dyn + 1023u) & ~1023u;

    float acc[2][8][4];
    #pragma unroll
    for (int i = 0; i < 2; i++)
        #pragma unroll
        for (int j = 0; j < 8; j++)
            #pragma unroll
            for (int r = 0; r < 4; r++) acc[i][j][r] = 0.f;

    auto issue_load = [&](int kt, int stg) {
        const uint32_t st = sb0 + (uint32_t)stg * PSTAGE;
        const size_t koff = (size_t)kt * 64;
        #pragma unroll
        for (int i = 0; i < 12; i++) {          // 3 tensors x 1024 chunks
            int id = i * 256 + tid;
            int tensor = id >> 10;
            int cid = id & 1023;
            int r = cid >> 3, c = cid & 7;
            uint32_t dst = st + tensor * TEN_T + SWZ((uint32_t)(r * 128 + c * 16));
            const __half* src;
            if (tensor == 0)      src = Ah + (size_t)(bm + r) * K + koff + c * 8;
            else if (tensor == 1) src = Al + (size_t)(bm + r) * K + koff + c * 8;
            else                  src = B  + (size_t)(bn + r) * K + koff + c * 8;
            cpa16(dst, src);
        }
        CP_COMMIT();
    };

    issue_load(0, 0);
    if (nk > 1) issue_load(1, 1);

    const int a_row = wm + (lane & 15);
    const int a_k8  = (lane >> 4) * 8;
    const int b_row = wn + ((lane >> 4) & 1) * 8 + (lane & 7);
    const int b_k8  = ((lane >> 3) & 1) * 8;

    uint32_t aH[2][2][4], aL[2][2][4], bF[2][4][4];

    int s_cur = 0, s_nxt = 2;
    for (int kt = 0; kt < nk; kt++) {
        if (kt + 1 < nk) { CP_WAIT1(); } else { CP_WAIT0(); }
        __syncthreads();
        if (kt + 2 < nk) issue_load(kt + 2, s_nxt);

        const uint32_t st  = sb0 + (uint32_t)s_cur * PSTAGE;
        const uint32_t sAh = st;
        const uint32_t sAl = st + TEN_T;
        const uint32_t sB  = st + 2 * TEN_T;

        auto load_frags = [&](int buf, int ksv) {
            const int kb = ksv * 16;
            #pragma unroll
            for (int mi = 0; mi < 2; mi++) {
                uint32_t off = SWZ((uint32_t)((a_row + mi * 16) * 128 + (kb + a_k8) * 2));
                ldsm_x4(aH[buf][mi], sAh + off);
                ldsm_x4(aL[buf][mi], sAl + off);
            }
            #pragma unroll
            for (int p = 0; p < 4; p++) {
                uint32_t off = SWZ((uint32_t)((b_row + p * 16) * 128 + (kb + b_k8) * 2));
                ldsm_x4(bF[buf][p], sB + off);
            }
        };

        load_frags(0, 0);
        #pragma unroll
        for (int ks = 0; ks < 4; ks++) {
            const int cb = ks & 1;
            if (ks < 3) load_frags(cb ^ 1, ks + 1);
            #pragma unroll
            for (int mi = 0; mi < 2; mi++)
                #pragma unroll
                for (int p = 0; p < 4; p++)
                    #pragma unroll
                    for (int j = 0; j < 2; j++)
                        mma_fp16(acc[mi][p * 2 + j], aH[cb][mi], &bF[cb][p][j * 2]);
            #pragma unroll
            for (int mi = 0; mi < 2; mi++)
                #pragma unroll
                for (int p = 0; p < 4; p++)
                    #pragma unroll
                    for (int j = 0; j < 2; j++)
                        mma_fp16(acc[mi][p * 2 + j], aL[cb][mi], &bF[cb][p][j * 2]);
        }

        s_cur = (s_cur == 2) ? 0 : s_cur + 1;
        s_nxt = (s_nxt == 2) ? 0 : s_nxt + 1;
    }

    #pragma unroll
    for (int nj = 0; nj < 8; nj++) {
        const int col = bn + wn + nj * 8 + (lane & 3) * 2;
        float b0 = bias1[col] + bias2[col];
        float b1 = bias1[col + 1] + bias2[col + 1];
        #pragma unroll
        for (int mi = 0; mi < 2; mi++) {
            const int r0 = bm + wm + mi * 16 + (lane >> 2);
            const int r1 = r0 + 8;
            int o0 = permute ? ((r0 & 63) * 32 + (r0 >> 6)) : r0;
            int o1 = permute ? ((r1 & 63) * 32 + (r1 >> 6)) : r1;
            float2 v0 = make_float2(acc[mi][nj][0] + b0, acc[mi][nj][1] + b1);
            float2 v1 = make_float2(acc[mi][nj][2] + b0, acc[mi][nj][3] + b1);
            *(float2*)(C + (size_t)o0 * N + col) = v0;
            *(float2*)(C + (size_t)o1 * N + col) = v1;
        }
    }
}

// ============== fp16 1-term FC GEMM: C = A*B^T + bias (R12 proven) =======
#define FSTAGE (2*TEN_T)
__global__ void __launch_bounds__(256, 1)
gemm_fc_f16(const __half* __restrict__ A, const __half* __restrict__ B,
            float* __restrict__ C, int M, int N, int K,
            const float* __restrict__ bias)
{
    extern __shared__ char dsm[];
    const int tid  = threadIdx.x;
    const int wid  = tid >> 5;
    const int lane = tid & 31;
    const int bm = blockIdx.x * 128;
    const int bn = blockIdx.y * 128;
    const int wm = (wid & 3) * 32;
    const int wn = (wid >> 2) * 64;
    const int nk = K >> 6;

    uint32_t dyn = smem_u32(dsm);
    uint32_t sb0 = (dyn + 1023u) & ~1023u;

    float acc[2][8][4];
    #pragma unroll
    for (int i = 0; i < 2; i++)
        #pragma unroll
        for (int j = 0; j < 8; j++)
            #pragma unroll
            for (int r = 0; r < 4; r++) acc[i][j][r] = 0.f;

    auto issue_load = [&](int kt, int stg) {
        const uint32_t st = sb0 + (uint32_t)stg * FSTAGE;
        const size_t koff = (size_t)kt * 64;
        #pragma unroll
        for (int i = 0; i < 8; i++) {
            int id = i * 256 + tid;
            int tensor = id >> 10;
            int cid = id & 1023;
            int r = cid >> 3, c = cid & 7;
            uint32_t dst = st + tensor * TEN_T + SWZ((uint32_t)(r * 128 + c * 16));
            const __half* src;
            if (tensor == 0) src = A + (size_t)(bm + r) * K + koff + c * 8;
            else             src = B + (size_t)(bn + r) * K + koff + c * 8;
            cpa16(dst, src);
        }
        CP_COMMIT();
    };

    issue_load(0, 0);
    if (nk > 1) issue_load(1, 1);

    const int a_row = wm + (lane & 15);
    const int a_k8  = (lane >> 4) * 8;
    const int b_row = wn + ((lane >> 4) & 1) * 8 + (lane & 7);
    const int b_k8  = ((lane >> 3) & 1) * 8;

    uint32_t aF[2][2][4], bF[2][4][4];

    int s_cur = 0, s_nxt = 2;
    for (int kt = 0; kt < nk; kt++) {
        if (kt + 1 < nk) { CP_WAIT1(); } else { CP_WAIT0(); }
        __syncthreads();
        if (kt + 2 < nk) issue_load(kt + 2, s_nxt);

        const uint32_t st = sb0 + (uint32_t)s_cur * FSTAGE;
        const uint32_t sA = st;
        const uint32_t sB = st + TEN_T;

        auto load_frags = [&](int buf, int ksv) {
            const int kb = ksv * 16;
            #pragma unroll
            for (int mi = 0; mi < 2; mi++) {
                uint32_t off = SWZ((uint32_t)((a_row + mi * 16) * 128 + (kb + a_k8) * 2));
                ldsm_x4(aF[buf][mi], sA + off);
            }
            #pragma unroll
            for (int p = 0; p < 4; p++) {
                uint32_t off = SWZ((uint32_t)((b_row + p * 16) * 128 + (kb + b_k8) * 2));
                ldsm_x4(bF[buf][p], sB + off);
            }
        };

        load_frags(0, 0);
        #pragma unroll
        for (int ks = 0; ks < 4; ks++) {
            const int cb = ks & 1;
            if (ks < 3) load_frags(cb ^ 1, ks + 1);
            #pragma unroll
            for (int mi = 0; mi < 2; mi++)
                #pragma unroll
                for (int p = 0; p < 4; p++)
                    #pragma unroll
                    for (int j = 0; j < 2; j++)
                        mma_fp16(acc[mi][p * 2 + j], aF[cb][mi], &bF[cb][p][j * 2]);
        }

        s_cur = (s_cur == 2) ? 0 : s_cur + 1;
        s_nxt = (s_nxt == 2) ? 0 : s_nxt + 1;
    }

    #pragma unroll
    for (int nj = 0; nj < 8; nj++) {
        const int col = bn + wn + nj * 8 + (lane & 3) * 2;
        const float b0 = bias[col], b1 = bias[col + 1];
        #pragma unroll
        for (int mi = 0; mi < 2; mi++) {
            const int r0 = bm + wm + mi * 16 + (lane >> 2);
            float2 v0 = make_float2(acc[mi][nj][0] + b0, acc[mi][nj][1] + b1);
            float2 v1 = make_float2(acc[mi][nj][2] + b0, acc[mi][nj][3] + b1);
            *(float2*)(C + (size_t)r0 * N + col)       = v0;
            *(float2*)(C + (size_t)(r0 + 8) * N + col) = v1;
        }
    }
}

// ---------------- linear(2048->512) + batchnorm -> fp16 hi/lo ------------
__global__ void linbn_kernel(const float* __restrict__ img,
                             const float* __restrict__ W,
                             const float* __restrict__ bias,
                             const float* __restrict__ gamma,
                             const float* __restrict__ beta,
                             __half* __restrict__ ah,
                             __half* __restrict__ al)
{
    const int e   = blockIdx.x;
    const int tid = threadIdx.x;
    __shared__ float wrow[IMGF];
    __shared__ float xv[BATCH];

    {
        const float* wsrc = W + (size_t)e * IMGF;
        #pragma unroll
        for (int i = 0; i < 2; i++) {
            int k = (tid + i * 256) * 4;
            *(float4*)&wrow[k] = *(const float4*)(wsrc + k);
        }
    }
    __syncthreads();

    const int lane = tid & 31, wid = tid >> 5;
    float a0 = 0.f, a1 = 0.f, a2 = 0.f, a3 = 0.f;
    for (int k = lane; k < IMGF; k += 32) {
        float wv = wrow[k];
        a0 += img[(size_t)(wid +  0) * IMGF + k] * wv;
        a1 += img[(size_t)(wid +  8) * IMGF + k] * wv;
        a2 += img[(size_t)(wid + 16) * IMGF + k] * wv;
        a3 += img[(size_t)(wid + 24) * IMGF + k] * wv;
    }
    #pragma unroll
    for (int o = 16; o > 0; o >>= 1) {
        a0 += __shfl_xor_sync(0xffffffffu, a0, o);
        a1 += __shfl_xor_sync(0xffffffffu, a1, o);
        a2 += __shfl_xor_sync(0xffffffffu, a2, o);
        a3 += __shfl_xor_sync(0xffffffffu, a3, o);
    }
    if (lane == 0) {
        float bb = bias[e];
        xv[wid +  0] = a0 + bb;
        xv[wid +  8] = a1 + bb;
        xv[wid + 16] = a2 + bb;
        xv[wid + 24] = a3 + bb;
    }
    __syncthreads();

    if (tid < 32) {
        float x = xv[tid];
        float s = x, q = x * x;
        #pragma unroll
        for (int o = 16; o > 0; o >>= 1) {
            s += __shfl_xor_sync(0xffffffffu, s, o);
            q += __shfl_xor_sync(0xffffffffu, q, o);
        }
        float mu  = s * (1.f / 32.f);
        float var = q * (1.f / 32.f) - mu * mu;
        float inv = rsqrtf(var + 1e-5f);
        float y = gamma[e] * (x - mu) * inv + beta[e];
        __half h, l;
        split_f16(y, h, l);
        size_t idx = ((size_t)tid * TSEQ + 0) * EDIM + e;
        ah[idx] = h;
        al[idx] = l;
    }
}

// ---------------- embedding gather -> fp16 hi/lo rows t>=1 ---------------
__global__ void gather_kernel(const int* __restrict__ cap,
                              const float* __restrict__ emb,
                              __half* __restrict__ ah,
                              __half* __restrict__ al)
{
    const int t = blockIdx.x + 1;
    const int b = blockIdx.y;
    const int tok = cap[b * TSEQ + (t - 1)];
    const int k = threadIdx.x * 4;
    float4 v = *(const float4*)(emb + (size_t)tok * EDIM + k);
    __half h0, h1, h2, h3, l0, l1, l2, l3;
    split_f16(v.x, h0, l0); split_f16(v.y, h1, l1);
    split_f16(v.z, h2, l2); split_f16(v.w, h3, l3);
    __half2 ph0; ph0.x = h0; ph0.y = h1;
    __half2 ph1; ph1.x = h2; ph1.y = h3;
    __half2 pl0; pl0.x = l0; pl0.y = l1;
    __half2 pl1; pl1.x = l2; pl1.y = l3;
    size_t row = ((size_t)b * TSEQ + t) * EDIM + k;
    *(__half2*)(ah + row)     = ph0;
    *(__half2*)(ah + row + 2) = ph1;
    *(__half2*)(al + row)     = pl0;
    *(__half2*)(al + row + 2) = pl1;
}

// ---------------- persistent HMMA LSTM layer (fp16 3-term) ----------------
__global__ void __launch_bounds__(256, 1)
lstm_persist(const float* __restrict__ pre,   // [T][B][G4]
             const float* __restrict__ Whh,   // [G4][HDIM]
             __half* __restrict__ ah,         // [b*T+t][HDIM]
             __half* __restrict__ al)
{
    extern __shared__ char sm_raw[];
    uint32_t raw = smem_u32(sm_raw);
    uint32_t sbase = (raw + 127u) & ~127u;
    char* base = sm_raw + (sbase - raw);
    const uint32_t W_HI = 0;
    const uint32_t W_LO = 65536;
    const uint32_t HBUF = 131072;            // 4 stages x 16KB
    float* g_s = (float*)(base + 196608);    // [32][33]

    const int tid  = threadIdx.x;
    const int wid  = tid >> 5;
    const int lane = tid & 31;
    const int u0   = blockIdx.x * 8;

    // one-time: convert Whh slice -> smem fp16 hi/lo (swizzled, 64k tiles)
    #pragma unroll
    for (int i = 0; i < 16; i++) {
        int cell = i * 256 + tid;
        int kt = cell >> 8;
        int r  = (cell >> 3) & 31;
        int cc = cell & 7;
        int jrow = (r >> 3) * HDIM + u0 + (r & 7);
        const float* src = Whh + (size_t)jrow * HDIM + kt * 64 + cc * 8;
        float4 v0 = *(const float4*)src;
        float4 v1 = *(const float4*)(src + 4);
        float f[8] = {v0.x, v0.y, v0.z, v0.w, v1.x, v1.y, v1.z, v1.w};
        uint32_t hi4[4], lo4[4];
        #pragma unroll
        for (int q = 0; q < 4; q++) {
            __half h0, l0, h1, l1;
            split_f16(f[2*q],   h0, l0);
            split_f16(f[2*q+1], h1, l1);
            __half2 hp; hp.x = h0; hp.y = h1;
            __half2 lp; lp.x = l0; lp.y = l1;
            hi4[q] = *(uint32_t*)&hp;
            lo4[q] = *(uint32_t*)&lp;
        }
        uint32_t off = kt * 4096 + SWZ((uint32_t)(r * 128 + cc * 16));
        *(uint4*)(base + W_HI + off) = make_uint4(hi4[0], hi4[1], hi4[2], hi4[3]);
        *(uint4*)(base + W_LO + off) = make_uint4(lo4[0], lo4[1], lo4[2], lo4[3]);
    }
    __syncthreads();

    const int wm = (wid & 1) * 16;
    const int wn = (wid >> 1) * 8;
    const int a_row = wm + (lane & 15);
    const int a_k8  = (lane >> 4) * 8;
    const int b_row = wn + (lane & 7);
    const int b_ku  = (lane >> 3) & 3;

    const int hr = tid >> 3;
    const int hc = tid & 7;
    const uint32_t hswz = SWZ((uint32_t)(hr * 128 + hc * 16));

    const int pb = tid >> 3;
    const int pu = tid & 7;

    const int jloc = wn + (lane & 3) * 2;
    const int jrow_e = (jloc >> 3) * HDIM + u0 + (jloc & 7);
    const int br = wm + (lane >> 2);

    float c_reg = 0.f;
    unsigned gen = 0;

    for (int t = 0; t < TSEQ; t++) {
        float acc[4] = {0.f, 0.f, 0.f, 0.f};

        const float* pt = pre + (size_t)t * BATCH * G4;
        float2 p0 = *(const float2*)(pt + (size_t)br * G4 + jrow_e);
        float2 p1 = *(const float2*)(pt + (size_t)(br + 8) * G4 + jrow_e);

        if (t > 0) {
            const size_t hrow_base = ((size_t)hr * TSEQ + (t - 1)) * HDIM + hc * 8;
            auto issue_chunk = [&](int c) {
                const uint32_t d = sbase + HBUF + (c & 3) * 16384 + hswz;
                const size_t g = hrow_base + (size_t)c * 128;
                cpa16(d,         ah + g);
                cpa16(d + 4096,  ah + g + 64);
                cpa16(d + 8192,  al + g);
                cpa16(d + 12288, al + g + 64);
                CP_COMMIT();
            };
            issue_chunk(0);
            issue_chunk(1);
            issue_chunk(2);
            for (int c = 0; c < 8; c++) {
                if (c < 6) { CP_WAIT2(); }
                else if (c == 6) { CP_WAIT1(); }
                else { CP_WAIT0(); }
                __syncthreads();
                const uint32_t stg = sbase + HBUF + (c & 3) * 16384;
                #pragma unroll
                for (int sub = 0; sub < 2; sub++) {
                    const uint32_t wc = (uint32_t)(2 * c + sub) * 4096;
                    const uint32_t hb_hi = stg + sub * 4096;
                    const uint32_t hb_lo = stg + 8192 + sub * 4096;
                    #pragma unroll
                    for (int kk2 = 0; kk2 < 2; kk2++) {
                        uint32_t bH4[4], bL4[4];
                        uint32_t boff = wc + SWZ((uint32_t)(b_row * 128 + kk2 * 64 + b_ku * 16));
                        ldsm_x4(bH4, sbase + W_HI + boff);
                        ldsm_x4(bL4, sbase + W_LO + boff);
                        #pragma unroll
                        for (int kh = 0; kh < 2; kh++) {
                            const int ks = kk2 * 2 + kh;
                            uint32_t aH4[4], aL4[4];
                            uint32_t aoff = SWZ((uint32_t)(a_row * 128 + ks * 32 + a_k8 * 2));
                            ldsm_x4(aH4, hb_hi + aoff);
                            ldsm_x4(aL4, hb_lo + aoff);
                            mma_fp16(acc, aH4, &bH4[kh * 2]);
                            mma_fp16(acc, aH4, &bL4[kh * 2]);
                            mma_fp16(acc, aL4, &bH4[kh * 2]);
                        }
                    }
                }
                if (c + 3 < 8) issue_chunk(c + 3);
            }
            __syncthreads();
        }

        g_s[jloc * 33 + br]           = acc[0] + p0.x;
        g_s[(jloc + 1) * 33 + br]     = acc[1] + p0.y;
        g_s[jloc * 33 + br + 8]       = acc[2] + p1.x;
        g_s[(jloc + 1) * 33 + br + 8] = acc[3] + p1.y;
        __syncthreads();

        {
            float gi = g_s[pu * 33 + pb];
            float gf = g_s[(8 + pu) * 33 + pb];
            float gg = g_s[(16 + pu) * 33 + pb];
            float go = g_s[(24 + pu) * 33 + pb];
            float si = 1.f / (1.f + expf(-gi));
            float sf = 1.f / (1.f + expf(-gf));
            float so = 1.f / (1.f + expf(-go));
            c_reg = sf * c_reg + si * tanhf(gg);
            float hn = so * tanhf(c_reg);
            __half hh, hl;
            split_f16(hn, hh, hl);
            size_t orow = ((size_t)pb * TSEQ + t) * HDIM + u0 + pu;
            ah[orow] = hh;
            al[orow] = hl;
        }
        __syncthreads();

        if (t + 1 < TSEQ) {
            gen++;
            if (tid == 0) {
                asm volatile("red.release.gpu.global.add.u32 [%0], 1;"
                             :: "l"(&g_bar_ctr) : "memory");
                unsigned tgt = gen * NBLK, v;
                do {
                    asm volatile("ld.acquire.gpu.global.u32 %0, [%1];"
                                 : "=r"(v) : "l"(&g_bar_ctr) : "memory");
                } while (v < tgt);
            }
            __syncthreads();
        }
    }
}

// ---------------- host launch --------------------------------------------
extern "C" void kernel_launch(void* const* d_in, const int* in_sizes, int n_in,
                              void* d_out, int out_size)
{
    const float* image = (const float*)d_in[0];
    const int*   caps  = (const int*)  d_in[1];
    const float* lin_W = (const float*)d_in[2];
    const float* lin_b = (const float*)d_in[3];
    const float* bn_g  = (const float*)d_in[4];
    const float* bn_b  = (const float*)d_in[5];
    const float* emb   = (const float*)d_in[6];
    const float* Wih0  = (const float*)d_in[7];
    const float* Whh0  = (const float*)d_in[8];
    const float* bih0  = (const float*)d_in[9];
    const float* bhh0  = (const float*)d_in[10];
    const float* Wih1  = (const float*)d_in[11];
    const float* Whh1  = (const float*)d_in[12];
    const float* bih1  = (const float*)d_in[13];
    const float* bhh1  = (const float*)d_in[14];
    const float* fc_W  = (const float*)d_in[15];
    const float* fc_b  = (const float*)d_in[16];
    float* out = (float*)d_out;

    float *pre;
    __half *ah, *al, *w0, *w1, *fw;
    cudaGetSymbolAddress((void**)&pre, g_pre);
    cudaGetSymbolAddress((void**)&ah,  g_ah);
    cudaGetSymbolAddress((void**)&al,  g_al);
    cudaGetSymbolAddress((void**)&w0,  g_w0);
    cudaGetSymbolAddress((void**)&w1,  g_w1);
    cudaGetSymbolAddress((void**)&fw,  g_fw);

    static int smem_set = 0;
    const int PRE_SMEM  = 3 * PSTAGE + 1024;         // ~145KB
    const int FC_SMEM   = 3 * FSTAGE + 1024;         // ~97KB
    const int LSTM_SMEM = 196608 + 32 * 33 * 4 + 256;
    if (!smem_set) {
        cudaFuncSetAttribute(gemm_pre,
                             cudaFuncAttributeMaxDynamicSharedMemorySize, PRE_SMEM);
        cudaFuncSetAttribute(gemm_fc_f16,
                             cudaFuncAttributeMaxDynamicSharedMemorySize, FC_SMEM);
        cudaFuncSetAttribute(lstm_persist,
                             cudaFuncAttributeMaxDynamicSharedMemorySize, LSTM_SMEM);
        smem_set = 1;
    }

    // inputs -> ah/al rows (K=EDIM layout)
    linbn_kernel<<<EDIM, 256>>>(image, lin_W, lin_b, bn_g, bn_b, ah, al);
    gather_kernel<<<dim3(TSEQ - 1, BATCH), 128>>>(caps, emb, ah, al);

    // layer-0 input weights, then pre0 GEMM (resets bar for lstm0)
    cvt_f16<<<(G4 * EDIM / 4 + 255) / 256, 256>>>(Wih0, w0, G4 * EDIM);
    gemm_pre<<<dim3(MROWS / 128, G4 / 128), 256, PRE_SMEM>>>(
        ah, al, w0, pre, MROWS, G4, EDIM, bih0, bhh0, 1);

    // remaining weight conversions
    cvt_f16<<<(G4 * HDIM / 4 + 255) / 256, 256>>>(Wih1, w1, G4 * HDIM);
    cvt_f16<<<(VOCAB * HDIM / 4 + 255) / 256, 256>>>(fc_W, fw, VOCAB * HDIM);

    // layer-0 recurrence
    lstm_persist<<<NBLK, 256, LSTM_SMEM>>>(pre, Whh0, ah, al);

    // pre1 = hs0 @ Wih1^T + biases (resets bar for lstm1)
    gemm_pre<<<dim3(MROWS / 128, G4 / 128), 256, PRE_SMEM>>>(
        ah, al, w1, pre, MROWS, G4, HDIM, bih1, bhh1, 1);

    // layer-1 recurrence
    lstm_persist<<<NBLK, 256, LSTM_SMEM>>>(pre, Whh1, ah, al);

    // logits = ah @ fw^T + fc_b  (fp16 1-term; ah is the fp16 h hi-part)
    gemm_fc_f16<<<dim3(MROWS / 128, VOCAB / 128), 256, FC_SMEM>>>(
        ah, fw, out, MROWS, VOCAB, HDIM, fc_b);
}

// round 14
// speedup vs baseline: 2.7051x; 1.0020x over previous
#include <cuda_runtime.h>
#include <cuda_fp16.h>
#include <math.h>
#include <stdint.h>

// Problem dims
#define VOCAB 32000
#define HDIM  1024
#define EDIM  512
#define BATCH 32
#define TSEQ  64
#define IMGF  2048
#define G4    (4*HDIM)          // 4096
#define MROWS (BATCH*TSEQ)      // 2048
#define NBLK  128               // persistent recurrence CTAs

// ---------------- device scratch (no allocation allowed) ----------------
__device__ float g_pre [MROWS * G4];     // time-major: [t][b][G4]
__device__ unsigned g_bar_ctr;

// fp16 hi/lo activations; fp16 single weights
__device__ __half g_ah [MROWS * HDIM];
__device__ __half g_al [MROWS * HDIM];
__device__ __half g_w0 [G4 * EDIM];
__device__ __half g_w1 [G4 * HDIM];
__device__ __half g_fw [VOCAB * HDIM];

// ======================= helpers =========================================
__device__ __forceinline__ uint32_t smem_u32(const void* p) {
    uint32_t a;
    asm("{ .reg .u64 t; cvta.to.shared.u64 t, %1; cvt.u32.u64 %0, t; }"
        : "=r"(a) : "l"(p));
    return a;
}
#define SWZ(x) ((x) ^ (((x) >> 3) & 0x70))

__device__ __forceinline__ void cpa16(uint32_t dst, const void* src) {
    asm volatile("cp.async.cg.shared.global [%0], [%1], 16;"
                 :: "r"(dst), "l"(src) : "memory");
}
#define CP_COMMIT() asm volatile("cp.async.commit_group;" ::: "memory")
#define CP_WAIT0()  asm volatile("cp.async.wait_group 0;" ::: "memory")
#define CP_WAIT1()  asm volatile("cp.async.wait_group 1;" ::: "memory")

__device__ __forceinline__ void ldsm_x4(uint32_t* r, uint32_t addr) {
    asm volatile("ldmatrix.sync.aligned.m8n8.x4.shared.b16 {%0,%1,%2,%3}, [%4];"
                 : "=r"(r[0]), "=r"(r[1]), "=r"(r[2]), "=r"(r[3]) : "r"(addr));
}
__device__ __forceinline__ void mma_fp16(float* c, const uint32_t* a, const uint32_t* b) {
    asm volatile(
        "mma.sync.aligned.m16n8k16.row.col.f32.f16.f16.f32 "
        "{%0,%1,%2,%3}, {%4,%5,%6,%7}, {%8,%9}, {%0,%1,%2,%3};"
        : "+f"(c[0]), "+f"(c[1]), "+f"(c[2]), "+f"(c[3])
        : "r"(a[0]), "r"(a[1]), "r"(a[2]), "r"(a[3]), "r"(b[0]), "r"(b[1]));
}
__device__ __forceinline__ void split_f16(float x, __half& h, __half& l) {
    h = __float2half(x);
    l = __float2half(x - __half2float(h));
}

// ============== fp32 -> fp16 conversion (weights) ========================
__global__ void cvt_f16(const float* __restrict__ x, __half* __restrict__ y, int n)
{
    int i = (blockIdx.x * 256 + threadIdx.x) * 4;
    if (i >= n) return;
    float4 v = *(const float4*)(x + i);
    __half2 p0; p0.x = __float2half(v.x); p0.y = __float2half(v.y);
    __half2 p1; p1.x = __float2half(v.z); p1.y = __float2half(v.w);
    *(__half2*)(y + i)     = p0;
    *(__half2*)(y + i + 2) = p1;
}

// ============== fp16 2-term pre-GEMM: C = (Ah+Al)*B^T + bias =============
#define TEN_T 16384
#define PSTAGE (3*TEN_T)
__global__ void __launch_bounds__(256, 1)
gemm_pre(const __half* __restrict__ Ah, const __half* __restrict__ Al,
         const __half* __restrict__ B,
         float* __restrict__ C, int M, int N, int K,
         const float* __restrict__ bias1, const float* __restrict__ bias2,
         int permute)
{
    extern __shared__ char dsm[];
    const int tid  = threadIdx.x;
    const int wid  = tid >> 5;
    const int lane = tid & 31;
    const int bm = blockIdx.x * 128;
    const int bn = blockIdx.y * 128;
    const int wm = (wid & 3) * 32;
    const int wn = (wid >> 2) * 64;
    const int nk = K >> 6;

    if (blockIdx.x == 0 && blockIdx.y == 0 && tid == 0) g_bar_ctr = 0u;

    uint32_t dyn = smem_u32(dsm);
    uint32_t sb0 = (dyn + 1023u) & ~1023u;

    float acc[2][8][4];
    #pragma unroll
    for (int i = 0; i < 2; i++)
        #pragma unroll
        for (int j = 0; j < 8; j++)
            #pragma unroll
            for (int r = 0; r < 4; r++) acc[i][j][r] = 0.f;

    auto issue_load = [&](int kt, int stg) {
        const uint32_t st = sb0 + (uint32_t)stg * PSTAGE;
        const size_t koff = (size_t)kt * 64;
        #pragma unroll
        for (int i = 0; i < 12; i++) {
            int id = i * 256 + tid;
            int tensor = id >> 10;
            int cid = id & 1023;
            int r = cid >> 3, c = cid & 7;
            uint32_t dst = st + tensor * TEN_T + SWZ((uint32_t)(r * 128 + c * 16));
            const __half* src;
            if (tensor == 0)      src = Ah + (size_t)(bm + r) * K + koff + c * 8;
            else if (tensor == 1) src = Al + (size_t)(bm + r) * K + koff + c * 8;
            else                  src = B  + (size_t)(bn + r) * K + koff + c * 8;
            cpa16(dst, src);
        }
        CP_COMMIT();
    };

    issue_load(0, 0);
    if (nk > 1) issue_load(1, 1);

    const int a_row = wm + (lane & 15);
    const int a_k8  = (lane >> 4) * 8;
    const int b_row = wn + ((lane >> 4) & 1) * 8 + (lane & 7);
    const int b_k8  = ((lane >> 3) & 1) * 8;

    uint32_t aH[2][2][4], aL[2][2][4], bF[2][4][4];

    int s_cur = 0, s_nxt = 2;
    for (int kt = 0; kt < nk; kt++) {
        if (kt + 1 < nk) { CP_WAIT1(); } else { CP_WAIT0(); }
        __syncthreads();
        if (kt + 2 < nk) issue_load(kt + 2, s_nxt);

        const uint32_t st  = sb0 + (uint32_t)s_cur * PSTAGE;
        const uint32_t sAh = st;
        const uint32_t sAl = st + TEN_T;
        const uint32_t sB  = st + 2 * TEN_T;

        auto load_frags = [&](int buf, int ksv) {
            const int kb = ksv * 16;
            #pragma unroll
            for (int mi = 0; mi < 2; mi++) {
                uint32_t off = SWZ((uint32_t)((a_row + mi * 16) * 128 + (kb + a_k8) * 2));
                ldsm_x4(aH[buf][mi], sAh + off);
                ldsm_x4(aL[buf][mi], sAl + off);
            }
            #pragma unroll
            for (int p = 0; p < 4; p++) {
                uint32_t off = SWZ((uint32_t)((b_row + p * 16) * 128 + (kb + b_k8) * 2));
                ldsm_x4(bF[buf][p], sB + off);
            }
        };

        load_frags(0, 0);
        #pragma unroll
        for (int ks = 0; ks < 4; ks++) {
            const int cb = ks & 1;
            if (ks < 3) load_frags(cb ^ 1, ks + 1);
            #pragma unroll
            for (int mi = 0; mi < 2; mi++)
                #pragma unroll
                for (int p = 0; p < 4; p++)
                    #pragma unroll
                    for (int j = 0; j < 2; j++)
                        mma_fp16(acc[mi][p * 2 + j], aH[cb][mi], &bF[cb][p][j * 2]);
            #pragma unroll
            for (int mi = 0; mi < 2; mi++)
                #pragma unroll
                for (int p = 0; p < 4; p++)
                    #pragma unroll
                    for (int j = 0; j < 2; j++)
                        mma_fp16(acc[mi][p * 2 + j], aL[cb][mi], &bF[cb][p][j * 2]);
        }

        s_cur = (s_cur == 2) ? 0 : s_cur + 1;
        s_nxt = (s_nxt == 2) ? 0 : s_nxt + 1;
    }

    #pragma unroll
    for (int nj = 0; nj < 8; nj++) {
        const int col = bn + wn + nj * 8 + (lane & 3) * 2;
        float b0 = bias1[col] + bias2[col];
        float b1 = bias1[col + 1] + bias2[col + 1];
        #pragma unroll
        for (int mi = 0; mi < 2; mi++) {
            const int r0 = bm + wm + mi * 16 + (lane >> 2);
            const int r1 = r0 + 8;
            int o0 = permute ? ((r0 & 63) * 32 + (r0 >> 6)) : r0;
            int o1 = permute ? ((r1 & 63) * 32 + (r1 >> 6)) : r1;
            float2 v0 = make_float2(acc[mi][nj][0] + b0, acc[mi][nj][1] + b1);
            float2 v1 = make_float2(acc[mi][nj][2] + b0, acc[mi][nj][3] + b1);
            *(float2*)(C + (size_t)o0 * N + col) = v0;
            *(float2*)(C + (size_t)o1 * N + col) = v1;
        }
    }
}

// ============== fp16 1-term FC GEMM: C = A*B^T + bias ====================
#define FSTAGE (2*TEN_T)
__global__ void __launch_bounds__(256, 1)
gemm_fc_f16(const __half* __restrict__ A, const __half* __restrict__ B,
            float* __restrict__ C, int M, int N, int K,
            const float* __restrict__ bias)
{
    extern __shared__ char dsm[];
    const int tid  = threadIdx.x;
    const int wid  = tid >> 5;
    const int lane = tid & 31;
    const int bm = blockIdx.x * 128;
    const int bn = blockIdx.y * 128;
    const int wm = (wid & 3) * 32;
    const int wn = (wid >> 2) * 64;
    const int nk = K >> 6;

    uint32_t dyn = smem_u32(dsm);
    uint32_t sb0 = (dyn + 1023u) & ~1023u;

    float acc[2][8][4];
    #pragma unroll
    for (int i = 0; i < 2; i++)
        #pragma unroll
        for (int j = 0; j < 8; j++)
            #pragma unroll
            for (int r = 0; r < 4; r++) acc[i][j][r] = 0.f;

    auto issue_load = [&](int kt, int stg) {
        const uint32_t st = sb0 + (uint32_t)stg * FSTAGE;
        const size_t koff = (size_t)kt * 64;
        #pragma unroll
        for (int i = 0; i < 8; i++) {
            int id = i * 256 + tid;
            int tensor = id >> 10;
            int cid = id & 1023;
            int r = cid >> 3, c = cid & 7;
            uint32_t dst = st + tensor * TEN_T + SWZ((uint32_t)(r * 128 + c * 16));
            const __half* src;
            if (tensor == 0) src = A + (size_t)(bm + r) * K + koff + c * 8;
            else             src = B + (size_t)(bn + r) * K + koff + c * 8;
            cpa16(dst, src);
        }
        CP_COMMIT();
    };

    issue_load(0, 0);
    if (nk > 1) issue_load(1, 1);

    const int a_row = wm + (lane & 15);
    const int a_k8  = (lane >> 4) * 8;
    const int b_row = wn + ((lane >> 4) & 1) * 8 + (lane & 7);
    const int b_k8  = ((lane >> 3) & 1) * 8;

    uint32_t aF[2][2][4], bF[2][4][4];

    int s_cur = 0, s_nxt = 2;
    for (int kt = 0; kt < nk; kt++) {
        if (kt + 1 < nk) { CP_WAIT1(); } else { CP_WAIT0(); }
        __syncthreads();
        if (kt + 2 < nk) issue_load(kt + 2, s_nxt);

        const uint32_t st = sb0 + (uint32_t)s_cur * FSTAGE;
        const uint32_t sA = st;
        const uint32_t sB = st + TEN_T;

        auto load_frags = [&](int buf, int ksv) {
            const int kb = ksv * 16;
            #pragma unroll
            for (int mi = 0; mi < 2; mi++) {
                uint32_t off = SWZ((uint32_t)((a_row + mi * 16) * 128 + (kb + a_k8) * 2));
                ldsm_x4(aF[buf][mi], sA + off);
            }
            #pragma unroll
            for (int p = 0; p < 4; p++) {
                uint32_t off = SWZ((uint32_t)((b_row + p * 16) * 128 + (kb + b_k8) * 2));
                ldsm_x4(bF[buf][p], sB + off);
            }
        };

        load_frags(0, 0);
        #pragma unroll
        for (int ks = 0; ks < 4; ks++) {
            const int cb = ks & 1;
            if (ks < 3) load_frags(cb ^ 1, ks + 1);
            #pragma unroll
            for (int mi = 0; mi < 2; mi++)
                #pragma unroll
                for (int p = 0; p < 4; p++)
                    #pragma unroll
                    for (int j = 0; j < 2; j++)
                        mma_fp16(acc[mi][p * 2 + j], aF[cb][mi], &bF[cb][p][j * 2]);
        }

        s_cur = (s_cur == 2) ? 0 : s_cur + 1;
        s_nxt = (s_nxt == 2) ? 0 : s_nxt + 1;
    }

    #pragma unroll
    for (int nj = 0; nj < 8; nj++) {
        const int col = bn + wn + nj * 8 + (lane & 3) * 2;
        const float b0 = bias[col], b1 = bias[col + 1];
        #pragma unroll
        for (int mi = 0; mi < 2; mi++) {
            const int r0 = bm + wm + mi * 16 + (lane >> 2);
            float2 v0 = make_float2(acc[mi][nj][0] + b0, acc[mi][nj][1] + b1);
            float2 v1 = make_float2(acc[mi][nj][2] + b0, acc[mi][nj][3] + b1);
            *(float2*)(C + (size_t)r0 * N + col)       = v0;
            *(float2*)(C + (size_t)(r0 + 8) * N + col) = v1;
        }
    }
}

// ---------------- linear(2048->512) + batchnorm -> fp16 hi/lo ------------
__global__ void linbn_kernel(const float* __restrict__ img,
                             const float* __restrict__ W,
                             const float* __restrict__ bias,
                             const float* __restrict__ gamma,
                             const float* __restrict__ beta,
                             __half* __restrict__ ah,
                             __half* __restrict__ al)
{
    const int e   = blockIdx.x;
    const int tid = threadIdx.x;
    __shared__ float wrow[IMGF];
    __shared__ float xv[BATCH];

    {
        const float* wsrc = W + (size_t)e * IMGF;
        #pragma unroll
        for (int i = 0; i < 2; i++) {
            int k = (tid + i * 256) * 4;
            *(float4*)&wrow[k] = *(const float4*)(wsrc + k);
        }
    }
    __syncthreads();

    const int lane = tid & 31, wid = tid >> 5;
    float a0 = 0.f, a1 = 0.f, a2 = 0.f, a3 = 0.f;
    for (int k = lane; k < IMGF; k += 32) {
        float wv = wrow[k];
        a0 += img[(size_t)(wid +  0) * IMGF + k] * wv;
        a1 += img[(size_t)(wid +  8) * IMGF + k] * wv;
        a2 += img[(size_t)(wid + 16) * IMGF + k] * wv;
        a3 += img[(size_t)(wid + 24) * IMGF + k] * wv;
    }
    #pragma unroll
    for (int o = 16; o > 0; o >>= 1) {
        a0 += __shfl_xor_sync(0xffffffffu, a0, o);
        a1 += __shfl_xor_sync(0xffffffffu, a1, o);
        a2 += __shfl_xor_sync(0xffffffffu, a2, o);
        a3 += __shfl_xor_sync(0xffffffffu, a3, o);
    }
    if (lane == 0) {
        float bb = bias[e];
        xv[wid +  0] = a0 + bb;
        xv[wid +  8] = a1 + bb;
        xv[wid + 16] = a2 + bb;
        xv[wid + 24] = a3 + bb;
    }
    __syncthreads();

    if (tid < 32) {
        float x = xv[tid];
        float s = x, q = x * x;
        #pragma unroll
        for (int o = 16; o > 0; o >>= 1) {
            s += __shfl_xor_sync(0xffffffffu, s, o);
            q += __shfl_xor_sync(0xffffffffu, q, o);
        }
        float mu  = s * (1.f / 32.f);
        float var = q * (1.f / 32.f) - mu * mu;
        float inv = rsqrtf(var + 1e-5f);
        float y = gamma[e] * (x - mu) * inv + beta[e];
        __half h, l;
        split_f16(y, h, l);
        size_t idx = ((size_t)tid * TSEQ + 0) * EDIM + e;
        ah[idx] = h;
        al[idx] = l;
    }
}

// ---------------- embedding gather -> fp16 hi/lo rows t>=1 ---------------
__global__ void gather_kernel(const int* __restrict__ cap,
                              const float* __restrict__ emb,
                              __half* __restrict__ ah,
                              __half* __restrict__ al)
{
    const int t = blockIdx.x + 1;
    const int b = blockIdx.y;
    const int tok = cap[b * TSEQ + (t - 1)];
    const int k = threadIdx.x * 4;
    float4 v = *(const float4*)(emb + (size_t)tok * EDIM + k);
    __half h0, h1, h2, h3, l0, l1, l2, l3;
    split_f16(v.x, h0, l0); split_f16(v.y, h1, l1);
    split_f16(v.z, h2, l2); split_f16(v.w, h3, l3);
    __half2 ph0; ph0.x = h0; ph0.y = h1;
    __half2 ph1; ph1.x = h2; ph1.y = h3;
    __half2 pl0; pl0.x = l0; pl0.y = l1;
    __half2 pl1; pl1.x = l2; pl1.y = l3;
    size_t row = ((size_t)b * TSEQ + t) * EDIM + k;
    *(__half2*)(ah + row)     = ph0;
    *(__half2*)(ah + row + 2) = ph1;
    *(__half2*)(al + row)     = pl0;
    *(__half2*)(al + row + 2) = pl1;
}

// ---------------- persistent HMMA LSTM layer (paired chunks) --------------
// h staged in 4 pairs of k256 (32KB each), 3 pair-buffers; g_s aliases
// HBUF buffer 0 (only live after the trailing h-loop sync).
__global__ void __launch_bounds__(256, 1)
lstm_persist(const float* __restrict__ pre,   // [T][B][G4]
             const float* __restrict__ Whh,   // [G4][HDIM]
             __half* __restrict__ ah,         // [b*T+t][HDIM]
             __half* __restrict__ al)
{
    extern __shared__ char sm_raw[];
    uint32_t raw = smem_u32(sm_raw);
    uint32_t sbase = (raw + 127u) & ~127u;
    char* base = sm_raw + (sbase - raw);
    const uint32_t W_HI = 0;
    const uint32_t W_LO = 65536;
    const uint32_t HBUF = 131072;            // 3 pair-buffers x 32KB
    float* g_s = (float*)(base + HBUF);      // aliases pair-buffer 0

    const int tid  = threadIdx.x;
    const int wid  = tid >> 5;
    const int lane = tid & 31;
    const int u0   = blockIdx.x * 8;

    // one-time: convert Whh slice -> smem fp16 hi/lo (swizzled, 64k tiles)
    #pragma unroll
    for (int i = 0; i < 16; i++) {
        int cell = i * 256 + tid;
        int kt = cell >> 8;
        int r  = (cell >> 3) & 31;
        int cc = cell & 7;
        int jrow = (r >> 3) * HDIM + u0 + (r & 7);
        const float* src = Whh + (size_t)jrow * HDIM + kt * 64 + cc * 8;
        float4 v0 = *(const float4*)src;
        float4 v1 = *(const float4*)(src + 4);
        float f[8] = {v0.x, v0.y, v0.z, v0.w, v1.x, v1.y, v1.z, v1.w};
        uint32_t hi4[4], lo4[4];
        #pragma unroll
        for (int q = 0; q < 4; q++) {
            __half h0, l0, h1, l1;
            split_f16(f[2*q],   h0, l0);
            split_f16(f[2*q+1], h1, l1);
            __half2 hp; hp.x = h0; hp.y = h1;
            __half2 lp; lp.x = l0; lp.y = l1;
            hi4[q] = *(uint32_t*)&hp;
            lo4[q] = *(uint32_t*)&lp;
        }
        uint32_t off = kt * 4096 + SWZ((uint32_t)(r * 128 + cc * 16));
        *(uint4*)(base + W_HI + off) = make_uint4(hi4[0], hi4[1], hi4[2], hi4[3]);
        *(uint4*)(base + W_LO + off) = make_uint4(lo4[0], lo4[1], lo4[2], lo4[3]);
    }
    __syncthreads();

    const int wm = (wid & 1) * 16;
    const int wn = (wid >> 1) * 8;
    const int a_row = wm + (lane & 15);
    const int a_k8  = (lane >> 4) * 8;
    const int b_row = wn + (lane & 7);
    const int b_ku  = (lane >> 3) & 3;

    const int hr = tid >> 3;
    const int hc = tid & 7;
    const uint32_t hswz = SWZ((uint32_t)(hr * 128 + hc * 16));

    const int pb = tid >> 3;
    const int pu = tid & 7;

    const int jloc = wn + (lane & 3) * 2;
    const int jrow_e = (jloc >> 3) * HDIM + u0 + (jloc & 7);
    const int br = wm + (lane >> 2);

    float c_reg = 0.f;
    unsigned gen = 0;

    // prefetch pre[0]
    float2 p0v = *(const float2*)(pre + (size_t)br * G4 + jrow_e);
    float2 p1v = *(const float2*)(pre + (size_t)(br + 8) * G4 + jrow_e);

    for (int t = 0; t < TSEQ; t++) {
        float acc[4] = {0.f, 0.f, 0.f, 0.f};

        if (t > 0) {
            const size_t hrow_base = ((size_t)hr * TSEQ + (t - 1)) * HDIM + hc * 8;
            // pair p: 32KB = hi 4x4KB | lo 4x4KB, k-range 256
            auto issue_pair = [&](int p) {
                const uint32_t d = sbase + HBUF + (uint32_t)(p % 3) * 32768 + hswz;
                const size_t g = hrow_base + (size_t)p * 256;
                cpa16(d,         ah + g);
                cpa16(d + 4096,  ah + g + 64);
                cpa16(d + 8192,  ah + g + 128);
                cpa16(d + 12288, ah + g + 192);
                cpa16(d + 16384, al + g);
                cpa16(d + 20480, al + g + 64);
                cpa16(d + 24576, al + g + 128);
                cpa16(d + 28672, al + g + 192);
                CP_COMMIT();
            };
            issue_pair(0);
            issue_pair(1);
            for (int p = 0; p < 4; p++) {
                if (p < 3) { CP_WAIT1(); } else { CP_WAIT0(); }
                __syncthreads();
                if (p + 2 < 4) issue_pair(p + 2);
                const uint32_t stg = sbase + HBUF + (uint32_t)(p % 3) * 32768;
                #pragma unroll
                for (int sub = 0; sub < 4; sub++) {
                    const uint32_t wc = (uint32_t)(4 * p + sub) * 4096;
                    const uint32_t hb_hi = stg + sub * 4096;
                    const uint32_t hb_lo = stg + 16384 + sub * 4096;
                    #pragma unroll
                    for (int kk2 = 0; kk2 < 2; kk2++) {
                        uint32_t bH4[4], bL4[4];
                        uint32_t boff = wc + SWZ((uint32_t)(b_row * 128 + kk2 * 64 + b_ku * 16));
                        ldsm_x4(bH4, sbase + W_HI + boff);
                        ldsm_x4(bL4, sbase + W_LO + boff);
                        #pragma unroll
                        for (int kh = 0; kh < 2; kh++) {
                            const int ks = kk2 * 2 + kh;
                            uint32_t aH4[4], aL4[4];
                            uint32_t aoff = SWZ((uint32_t)(a_row * 128 + ks * 32 + a_k8 * 2));
                            ldsm_x4(aH4, hb_hi + aoff);
                            ldsm_x4(aL4, hb_lo + aoff);
                            mma_fp16(acc, aH4, &bH4[kh * 2]);
                            mma_fp16(acc, aH4, &bL4[kh * 2]);
                            mma_fp16(acc, aL4, &bH4[kh * 2]);
                        }
                    }
                }
            }
            __syncthreads();   // all warps done reading buffer 0 before g_s write
        }

        // epilogue: g = acc + pre[t] (prefetched)
        g_s[jloc * 33 + br]           = acc[0] + p0v.x;
        g_s[(jloc + 1) * 33 + br]     = acc[1] + p0v.y;
        g_s[jloc * 33 + br + 8]       = acc[2] + p1v.x;
        g_s[(jloc + 1) * 33 + br + 8] = acc[3] + p1v.y;
        __syncthreads();

        // pointwise
        {
            float gi = g_s[pu * 33 + pb];
            float gf = g_s[(8 + pu) * 33 + pb];
            float gg = g_s[(16 + pu) * 33 + pb];
            float go = g_s[(24 + pu) * 33 + pb];
            float si = 1.f / (1.f + expf(-gi));
            float sf = 1.f / (1.f + expf(-gf));
            float so = 1.f / (1.f + expf(-go));
            c_reg = sf * c_reg + si * tanhf(gg);
            float hn = so * tanhf(c_reg);
            __half hh, hl;
            split_f16(hn, hh, hl);
            size_t orow = ((size_t)pb * TSEQ + t) * HDIM + u0 + pu;
            ah[orow] = hh;
            al[orow] = hl;
        }
        __syncthreads();

        if (t + 1 < TSEQ) {
            // prefetch pre[t+1] before the barrier (latency hidden behind it)
            const float* pt = pre + (size_t)(t + 1) * BATCH * G4;
            p0v = *(const float2*)(pt + (size_t)br * G4 + jrow_e);
            p1v = *(const float2*)(pt + (size_t)(br + 8) * G4 + jrow_e);

            gen++;
            if (tid == 0) {
                asm volatile("red.release.gpu.global.add.u32 [%0], 1;"
                             :: "l"(&g_bar_ctr) : "memory");
                unsigned tgt = gen * NBLK, v;
                do {
                    asm volatile("ld.acquire.gpu.global.u32 %0, [%1];"
                                 : "=r"(v) : "l"(&g_bar_ctr) : "memory");
                } while (v < tgt);
            }
            __syncthreads();
        }
    }
}

// ---------------- host launch --------------------------------------------
extern "C" void kernel_launch(void* const* d_in, const int* in_sizes, int n_in,
                              void* d_out, int out_size)
{
    const float* image = (const float*)d_in[0];
    const int*   caps  = (const int*)  d_in[1];
    const float* lin_W = (const float*)d_in[2];
    const float* lin_b = (const float*)d_in[3];
    const float* bn_g  = (const float*)d_in[4];
    const float* bn_b  = (const float*)d_in[5];
    const float* emb   = (const float*)d_in[6];
    const float* Wih0  = (const float*)d_in[7];
    const float* Whh0  = (const float*)d_in[8];
    const float* bih0  = (const float*)d_in[9];
    const float* bhh0  = (const float*)d_in[10];
    const float* Wih1  = (const float*)d_in[11];
    const float* Whh1  = (const float*)d_in[12];
    const float* bih1  = (const float*)d_in[13];
    const float* bhh1  = (const float*)d_in[14];
    const float* fc_W  = (const float*)d_in[15];
    const float* fc_b  = (const float*)d_in[16];
    float* out = (float*)d_out;

    float *pre;
    __half *ah, *al, *w0, *w1, *fw;
    cudaGetSymbolAddress((void**)&pre, g_pre);
    cudaGetSymbolAddress((void**)&ah,  g_ah);
    cudaGetSymbolAddress((void**)&al,  g_al);
    cudaGetSymbolAddress((void**)&w0,  g_w0);
    cudaGetSymbolAddress((void**)&w1,  g_w1);
    cudaGetSymbolAddress((void**)&fw,  g_fw);

    static int smem_set = 0;
    const int PRE_SMEM  = 3 * PSTAGE + 1024;         // ~145KB
    const int FC_SMEM   = 3 * FSTAGE + 1024;         // ~97KB
    const int LSTM_SMEM = 131072 + 3 * 32768 + 256;  // ~224.3KB
    if (!smem_set) {
        cudaFuncSetAttribute(gemm_pre,
                             cudaFuncAttributeMaxDynamicSharedMemorySize, PRE_SMEM);
        cudaFuncSetAttribute(gemm_fc_f16,
                             cudaFuncAttributeMaxDynamicSharedMemorySize, FC_SMEM);
        cudaFuncSetAttribute(lstm_persist,
                             cudaFuncAttributeMaxDynamicSharedMemorySize, LSTM_SMEM);
        smem_set = 1;
    }

    // inputs -> ah/al rows (K=EDIM layout)
    linbn_kernel<<<EDIM, 256>>>(image, lin_W, lin_b, bn_g, bn_b, ah, al);
    gather_kernel<<<dim3(TSEQ - 1, BATCH), 128>>>(caps, emb, ah, al);

    // layer-0 input weights, then pre0 GEMM (resets bar for lstm0)
    cvt_f16<<<(G4 * EDIM / 4 + 255) / 256, 256>>>(Wih0, w0, G4 * EDIM);
    gemm_pre<<<dim3(MROWS / 128, G4 / 128), 256, PRE_SMEM>>>(
        ah, al, w0, pre, MROWS, G4, EDIM, bih0, bhh0, 1);

    // remaining weight conversions
    cvt_f16<<<(G4 * HDIM / 4 + 255) / 256, 256>>>(Wih1, w1, G4 * HDIM);
    cvt_f16<<<(VOCAB * HDIM / 4 + 255) / 256, 256>>>(fc_W, fw, VOCAB * HDIM);

    // layer-0 recurrence
    lstm_persist<<<NBLK, 256, LSTM_SMEM>>>(pre, Whh0, ah, al);

    // pre1 = hs0 @ Wih1^T + biases (resets bar for lstm1)
    gemm_pre<<<dim3(MROWS / 128, G4 / 128), 256, PRE_SMEM>>>(
        ah, al, w1, pre, MROWS, G4, HDIM, bih1, bhh1, 1);

    // layer-1 recurrence
    lstm_persist<<<NBLK, 256, LSTM_SMEM>>>(pre, Whh1, ah, al);

    // logits = ah @ fw^T + fc_b  (fp16 1-term; ah is the fp16 h hi-part)
    gemm_fc_f16<<<dim3(MROWS / 128, VOCAB / 128), 256, FC_SMEM>>>(
        ah, fw, out, MROWS, VOCAB, HDIM, fc_b);
}

// round 15
// speedup vs baseline: 3.0583x; 1.1306x over previous
#include <cuda_runtime.h>
#include <cuda_fp16.h>
#include <math.h>
#include <stdint.h>

// Problem dims
#define VOCAB 32000
#define HDIM  1024
#define EDIM  512
#define BATCH 32
#define TSEQ  64
#define IMGF  2048
#define G4    (4*HDIM)          // 4096
#define MROWS (BATCH*TSEQ)      // 2048
#define NBLK  128               // persistent recurrence CTAs

// ---------------- device scratch (no allocation allowed) ----------------
__device__ float g_pre [MROWS * G4];     // time-major: [t][b][G4]
__device__ unsigned g_bar_ctr;

// fp16 hi/lo activations; fp16 single weights
__device__ __half g_ah [MROWS * HDIM];
__device__ __half g_al [MROWS * HDIM];
__device__ __half g_w0 [G4 * EDIM];
__device__ __half g_w1 [G4 * HDIM];
__device__ __half g_fw [VOCAB * HDIM];

// ======================= helpers =========================================
__device__ __forceinline__ uint32_t smem_u32(const void* p) {
    uint32_t a;
    asm("{ .reg .u64 t; cvta.to.shared.u64 t, %1; cvt.u32.u64 %0, t; }"
        : "=r"(a) : "l"(p));
    return a;
}
#define SWZ(x) ((x) ^ (((x) >> 3) & 0x70))

__device__ __forceinline__ void cpa16(uint32_t dst, const void* src) {
    asm volatile("cp.async.cg.shared.global [%0], [%1], 16;"
                 :: "r"(dst), "l"(src) : "memory");
}
#define CP_COMMIT() asm volatile("cp.async.commit_group;" ::: "memory")
#define CP_WAIT0()  asm volatile("cp.async.wait_group 0;" ::: "memory")
#define CP_WAIT1()  asm volatile("cp.async.wait_group 1;" ::: "memory")

__device__ __forceinline__ void ldsm_x4(uint32_t* r, uint32_t addr) {
    asm volatile("ldmatrix.sync.aligned.m8n8.x4.shared.b16 {%0,%1,%2,%3}, [%4];"
                 : "=r"(r[0]), "=r"(r[1]), "=r"(r[2]), "=r"(r[3]) : "r"(addr));
}
__device__ __forceinline__ void mma_fp16(float* c, const uint32_t* a, const uint32_t* b) {
    asm volatile(
        "mma.sync.aligned.m16n8k16.row.col.f32.f16.f16.f32 "
        "{%0,%1,%2,%3}, {%4,%5,%6,%7}, {%8,%9}, {%0,%1,%2,%3};"
        : "+f"(c[0]), "+f"(c[1]), "+f"(c[2]), "+f"(c[3])
        : "r"(a[0]), "r"(a[1]), "r"(a[2]), "r"(a[3]), "r"(b[0]), "r"(b[1]));
}
__device__ __forceinline__ void split_f16(float x, __half& h, __half& l) {
    h = __float2half(x);
    l = __float2half(x - __half2float(h));
}

// ============== fp32 -> fp16 conversion (weights) ========================
__global__ void cvt_f16(const float* __restrict__ x, __half* __restrict__ y, int n)
{
    int i = (blockIdx.x * 256 + threadIdx.x) * 4;
    if (i >= n) return;
    float4 v = *(const float4*)(x + i);
    __half2 p0; p0.x = __float2half(v.x); p0.y = __float2half(v.y);
    __half2 p1; p1.x = __float2half(v.z); p1.y = __float2half(v.w);
    *(__half2*)(y + i)     = p0;
    *(__half2*)(y + i + 2) = p1;
}

// ============== fp16 2-term pre-GEMM: C = (Ah+Al)*B^T + bias =============
#define TEN_T 16384
#define PSTAGE (3*TEN_T)
__global__ void __launch_bounds__(256, 1)
gemm_pre(const __half* __restrict__ Ah, const __half* __restrict__ Al,
         const __half* __restrict__ B,
         float* __restrict__ C, int M, int N, int K,
         const float* __restrict__ bias1, const float* __restrict__ bias2,
         int permute)
{
    extern __shared__ char dsm[];
    const int tid  = threadIdx.x;
    const int wid  = tid >> 5;
    const int lane = tid & 31;
    const int bm = blockIdx.x * 128;
    const int bn = blockIdx.y * 128;
    const int wm = (wid & 3) * 32;
    const int wn = (wid >> 2) * 64;
    const int nk = K >> 6;

    if (blockIdx.x == 0 && blockIdx.y == 0 && tid == 0) g_bar_ctr = 0u;

    uint32_t dyn = smem_u32(dsm);
    uint32_t sb0 = (dyn + 1023u) & ~1023u;

    float acc[2][8][4];
    #pragma unroll
    for (int i = 0; i < 2; i++)
        #pragma unroll
        for (int j = 0; j < 8; j++)
            #pragma unroll
            for (int r = 0; r < 4; r++) acc[i][j][r] = 0.f;

    auto issue_load = [&](int kt, int stg) {
        const uint32_t st = sb0 + (uint32_t)stg * PSTAGE;
        const size_t koff = (size_t)kt * 64;
        #pragma unroll
        for (int i = 0; i < 12; i++) {
            int id = i * 256 + tid;
            int tensor = id >> 10;
            int cid = id & 1023;
            int r = cid >> 3, c = cid & 7;
            uint32_t dst = st + tensor * TEN_T + SWZ((uint32_t)(r * 128 + c * 16));
            const __half* src;
            if (tensor == 0)      src = Ah + (size_t)(bm + r) * K + koff + c * 8;
            else if (tensor == 1) src = Al + (size_t)(bm + r) * K + koff + c * 8;
            else                  src = B  + (size_t)(bn + r) * K + koff + c * 8;
            cpa16(dst, src);
        }
        CP_COMMIT();
    };

    issue_load(0, 0);
    if (nk > 1) issue_load(1, 1);

    const int a_row = wm + (lane & 15);
    const int a_k8  = (lane >> 4) * 8;
    const int b_row = wn + ((lane >> 4) & 1) * 8 + (lane & 7);
    const int b_k8  = ((lane >> 3) & 1) * 8;

    uint32_t aH[2][2][4], aL[2][2][4], bF[2][4][4];

    int s_cur = 0, s_nxt = 2;
    for (int kt = 0; kt < nk; kt++) {
        if (kt + 1 < nk) { CP_WAIT1(); } else { CP_WAIT0(); }
        __syncthreads();
        if (kt + 2 < nk) issue_load(kt + 2, s_nxt);

        const uint32_t st  = sb0 + (uint32_t)s_cur * PSTAGE;
        const uint32_t sAh = st;
        const uint32_t sAl = st + TEN_T;
        const uint32_t sB  = st + 2 * TEN_T;

        auto load_frags = [&](int buf, int ksv) {
            const int kb = ksv * 16;
            #pragma unroll
            for (int mi = 0; mi < 2; mi++) {
                uint32_t off = SWZ((uint32_t)((a_row + mi * 16) * 128 + (kb + a_k8) * 2));
                ldsm_x4(aH[buf][mi], sAh + off);
                ldsm_x4(aL[buf][mi], sAl + off);
            }
            #pragma unroll
            for (int p = 0; p < 4; p++) {
                uint32_t off = SWZ((uint32_t)((b_row + p * 16) * 128 + (kb + b_k8) * 2));
                ldsm_x4(bF[buf][p], sB + off);
            }
        };

        load_frags(0, 0);
        #pragma unroll
        for (int ks = 0; ks < 4; ks++) {
            const int cb = ks & 1;
            if (ks < 3) load_frags(cb ^ 1, ks + 1);
            #pragma unroll
            for (int mi = 0; mi < 2; mi++)
                #pragma unroll
                for (int p = 0; p < 4; p++)
                    #pragma unroll
                    for (int j = 0; j < 2; j++)
                        mma_fp16(acc[mi][p * 2 + j], aH[cb][mi], &bF[cb][p][j * 2]);
            #pragma unroll
            for (int mi = 0; mi < 2; mi++)
                #pragma unroll
                for (int p = 0; p < 4; p++)
                    #pragma unroll
                    for (int j = 0; j < 2; j++)
                        mma_fp16(acc[mi][p * 2 + j], aL[cb][mi], &bF[cb][p][j * 2]);
        }

        s_cur = (s_cur == 2) ? 0 : s_cur + 1;
        s_nxt = (s_nxt == 2) ? 0 : s_nxt + 1;
    }

    #pragma unroll
    for (int nj = 0; nj < 8; nj++) {
        const int col = bn + wn + nj * 8 + (lane & 3) * 2;
        float b0 = bias1[col] + bias2[col];
        float b1 = bias1[col + 1] + bias2[col + 1];
        #pragma unroll
        for (int mi = 0; mi < 2; mi++) {
            const int r0 = bm + wm + mi * 16 + (lane >> 2);
            const int r1 = r0 + 8;
            int o0 = permute ? ((r0 & 63) * 32 + (r0 >> 6)) : r0;
            int o1 = permute ? ((r1 & 63) * 32 + (r1 >> 6)) : r1;
            float2 v0 = make_float2(acc[mi][nj][0] + b0, acc[mi][nj][1] + b1);
            float2 v1 = make_float2(acc[mi][nj][2] + b0, acc[mi][nj][3] + b1);
            *(float2*)(C + (size_t)o0 * N + col) = v0;
            *(float2*)(C + (size_t)o1 * N + col) = v1;
        }
    }
}

// ============== fp16 1-term FC GEMM: C = A*B^T + bias ====================
#define FSTAGE (2*TEN_T)
__global__ void __launch_bounds__(256, 1)
gemm_fc_f16(const __half* __restrict__ A, const __half* __restrict__ B,
            float* __restrict__ C, int M, int N, int K,
            const float* __restrict__ bias)
{
    extern __shared__ char dsm[];
    const int tid  = threadIdx.x;
    const int wid  = tid >> 5;
    const int lane = tid & 31;
    const int bm = blockIdx.x * 128;
    const int bn = blockIdx.y * 128;
    const int wm = (wid & 3) * 32;
    const int wn = (wid >> 2) * 64;
    const int nk = K >> 6;

    uint32_t dyn = smem_u32(dsm);
    uint32_t sb0 = (dyn + 1023u) & ~1023u;

    float acc[2][8][4];
    #pragma unroll
    for (int i = 0; i < 2; i++)
        #pragma unroll
        for (int j = 0; j < 8; j++)
            #pragma unroll
            for (int r = 0; r < 4; r++) acc[i][j][r] = 0.f;

    auto issue_load = [&](int kt, int stg) {
        const uint32_t st = sb0 + (uint32_t)stg * FSTAGE;
        const size_t koff = (size_t)kt * 64;
        #pragma unroll
        for (int i = 0; i < 8; i++) {
            int id = i * 256 + tid;
            int tensor = id >> 10;
            int cid = id & 1023;
            int r = cid >> 3, c = cid & 7;
            uint32_t dst = st + tensor * TEN_T + SWZ((uint32_t)(r * 128 + c * 16));
            const __half* src;
            if (tensor == 0) src = A + (size_t)(bm + r) * K + koff + c * 8;
            else             src = B + (size_t)(bn + r) * K + koff + c * 8;
            cpa16(dst, src);
        }
        CP_COMMIT();
    };

    issue_load(0, 0);
    if (nk > 1) issue_load(1, 1);

    const int a_row = wm + (lane & 15);
    const int a_k8  = (lane >> 4) * 8;
    const int b_row = wn + ((lane >> 4) & 1) * 8 + (lane & 7);
    const int b_k8  = ((lane >> 3) & 1) * 8;

    uint32_t aF[2][2][4], bF[2][4][4];

    int s_cur = 0, s_nxt = 2;
    for (int kt = 0; kt < nk; kt++) {
        if (kt + 1 < nk) { CP_WAIT1(); } else { CP_WAIT0(); }
        __syncthreads();
        if (kt + 2 < nk) issue_load(kt + 2, s_nxt);

        const uint32_t st = sb0 + (uint32_t)s_cur * FSTAGE;
        const uint32_t sA = st;
        const uint32_t sB = st + TEN_T;

        auto load_frags = [&](int buf, int ksv) {
            const int kb = ksv * 16;
            #pragma unroll
            for (int mi = 0; mi < 2; mi++) {
                uint32_t off = SWZ((uint32_t)((a_row + mi * 16) * 128 + (kb + a_k8) * 2));
                ldsm_x4(aF[buf][mi], sA + off);
            }
            #pragma unroll
            for (int p = 0; p < 4; p++) {
                uint32_t off = SWZ((uint32_t)((b_row + p * 16) * 128 + (kb + b_k8) * 2));
                ldsm_x4(bF[buf][p], sB + off);
            }
        };

        load_frags(0, 0);
        #pragma unroll
        for (int ks = 0; ks < 4; ks++) {
            const int cb = ks & 1;
            if (ks < 3) load_frags(cb ^ 1, ks + 1);
            #pragma unroll
            for (int mi = 0; mi < 2; mi++)
                #pragma unroll
                for (int p = 0; p < 4; p++)
                    #pragma unroll
                    for (int j = 0; j < 2; j++)
                        mma_fp16(acc[mi][p * 2 + j], aF[cb][mi], &bF[cb][p][j * 2]);
        }

        s_cur = (s_cur == 2) ? 0 : s_cur + 1;
        s_nxt = (s_nxt == 2) ? 0 : s_nxt + 1;
    }

    #pragma unroll
    for (int nj = 0; nj < 8; nj++) {
        const int col = bn + wn + nj * 8 + (lane & 3) * 2;
        const float b0 = bias[col], b1 = bias[col + 1];
        #pragma unroll
        for (int mi = 0; mi < 2; mi++) {
            const int r0 = bm + wm + mi * 16 + (lane >> 2);
            float2 v0 = make_float2(acc[mi][nj][0] + b0, acc[mi][nj][1] + b1);
            float2 v1 = make_float2(acc[mi][nj][2] + b0, acc[mi][nj][3] + b1);
            *(float2*)(C + (size_t)r0 * N + col)       = v0;
            *(float2*)(C + (size_t)(r0 + 8) * N + col) = v1;
        }
    }
}

// ---------------- linear(2048->512) + batchnorm -> fp16 hi/lo ------------
__global__ void linbn_kernel(const float* __restrict__ img,
                             const float* __restrict__ W,
                             const float* __restrict__ bias,
                             const float* __restrict__ gamma,
                             const float* __restrict__ beta,
                             __half* __restrict__ ah,
                             __half* __restrict__ al)
{
    const int e   = blockIdx.x;
    const int tid = threadIdx.x;
    __shared__ float wrow[IMGF];
    __shared__ float xv[BATCH];

    {
        const float* wsrc = W + (size_t)e * IMGF;
        #pragma unroll
        for (int i = 0; i < 2; i++) {
            int k = (tid + i * 256) * 4;
            *(float4*)&wrow[k] = *(const float4*)(wsrc + k);
        }
    }
    __syncthreads();

    const int lane = tid & 31, wid = tid >> 5;
    float a0 = 0.f, a1 = 0.f, a2 = 0.f, a3 = 0.f;
    for (int k = lane; k < IMGF; k += 32) {
        float wv = wrow[k];
        a0 += img[(size_t)(wid +  0) * IMGF + k] * wv;
        a1 += img[(size_t)(wid +  8) * IMGF + k] * wv;
        a2 += img[(size_t)(wid + 16) * IMGF + k] * wv;
        a3 += img[(size_t)(wid + 24) * IMGF + k] * wv;
    }
    #pragma unroll
    for (int o = 16; o > 0; o >>= 1) {
        a0 += __shfl_xor_sync(0xffffffffu, a0, o);
        a1 += __shfl_xor_sync(0xffffffffu, a1, o);
        a2 += __shfl_xor_sync(0xffffffffu, a2, o);
        a3 += __shfl_xor_sync(0xffffffffu, a3, o);
    }
    if (lane == 0) {
        float bb = bias[e];
        xv[wid +  0] = a0 + bb;
        xv[wid +  8] = a1 + bb;
        xv[wid + 16] = a2 + bb;
        xv[wid + 24] = a3 + bb;
    }
    __syncthreads();

    if (tid < 32) {
        float x = xv[tid];
        float s = x, q = x * x;
        #pragma unroll
        for (int o = 16; o > 0; o >>= 1) {
            s += __shfl_xor_sync(0xffffffffu, s, o);
            q += __shfl_xor_sync(0xffffffffu, q, o);
        }
        float mu  = s * (1.f / 32.f);
        float var = q * (1.f / 32.f) - mu * mu;
        float inv = rsqrtf(var + 1e-5f);
        float y = gamma[e] * (x - mu) * inv + beta[e];
        __half h, l;
        split_f16(y, h, l);
        size_t idx = ((size_t)tid * TSEQ + 0) * EDIM + e;
        ah[idx] = h;
        al[idx] = l;
    }
}

// ---------------- embedding gather -> fp16 hi/lo rows t>=1 ---------------
__global__ void gather_kernel(const int* __restrict__ cap,
                              const float* __restrict__ emb,
                              __half* __restrict__ ah,
                              __half* __restrict__ al)
{
    const int t = blockIdx.x + 1;
    const int b = blockIdx.y;
    const int tok = cap[b * TSEQ + (t - 1)];
    const int k = threadIdx.x * 4;
    float4 v = *(const float4*)(emb + (size_t)tok * EDIM + k);
    __half h0, h1, h2, h3, l0, l1, l2, l3;
    split_f16(v.x, h0, l0); split_f16(v.y, h1, l1);
    split_f16(v.z, h2, l2); split_f16(v.w, h3, l3);
    __half2 ph0; ph0.x = h0; ph0.y = h1;
    __half2 ph1; ph1.x = h2; ph1.y = h3;
    __half2 pl0; pl0.x = l0; pl0.y = l1;
    __half2 pl1; pl1.x = l2; pl1.y = l3;
    size_t row = ((size_t)b * TSEQ + t) * EDIM + k;
    *(__half2*)(ah + row)     = ph0;
    *(__half2*)(ah + row + 2) = ph1;
    *(__half2*)(al + row)     = pl0;
    *(__half2*)(al + row + 2) = pl1;
}

// ---------------- persistent HMMA LSTM layer (2-term: hH x (WH+WL)) -------
// h-hi only staged: 4 pairs of k256 (16KB each), 3 pair-buffers.
__global__ void __launch_bounds__(256, 1)
lstm_persist(const float* __restrict__ pre,   // [T][B][G4]
             const float* __restrict__ Whh,   // [G4][HDIM]
             __half* __restrict__ ah,         // [b*T+t][HDIM]
             __half* __restrict__ al)
{
    extern __shared__ char sm_raw[];
    uint32_t raw = smem_u32(sm_raw);
    uint32_t sbase = (raw + 127u) & ~127u;
    char* base = sm_raw + (sbase - raw);
    const uint32_t W_HI = 0;
    const uint32_t W_LO = 65536;
    const uint32_t HBUF = 131072;                 // 3 pair-buffers x 16KB
    float* g_s = (float*)(base + HBUF + 49152);   // [32][33]

    const int tid  = threadIdx.x;
    const int wid  = tid >> 5;
    const int lane = tid & 31;
    const int u0   = blockIdx.x * 8;

    // one-time: convert Whh slice -> smem fp16 hi/lo (swizzled, 64k tiles)
    #pragma unroll
    for (int i = 0; i < 16; i++) {
        int cell = i * 256 + tid;
        int kt = cell >> 8;
        int r  = (cell >> 3) & 31;
        int cc = cell & 7;
        int jrow = (r >> 3) * HDIM + u0 + (r & 7);
        const float* src = Whh + (size_t)jrow * HDIM + kt * 64 + cc * 8;
        float4 v0 = *(const float4*)src;
        float4 v1 = *(const float4*)(src + 4);
        float f[8] = {v0.x, v0.y, v0.z, v0.w, v1.x, v1.y, v1.z, v1.w};
        uint32_t hi4[4], lo4[4];
        #pragma unroll
        for (int q = 0; q < 4; q++) {
            __half h0, l0, h1, l1;
            split_f16(f[2*q],   h0, l0);
            split_f16(f[2*q+1], h1, l1);
            __half2 hp; hp.x = h0; hp.y = h1;
            __half2 lp; lp.x = l0; lp.y = l1;
            hi4[q] = *(uint32_t*)&hp;
            lo4[q] = *(uint32_t*)&lp;
        }
        uint32_t off = kt * 4096 + SWZ((uint32_t)(r * 128 + cc * 16));
        *(uint4*)(base + W_HI + off) = make_uint4(hi4[0], hi4[1], hi4[2], hi4[3]);
        *(uint4*)(base + W_LO + off) = make_uint4(lo4[0], lo4[1], lo4[2], lo4[3]);
    }
    __syncthreads();

    const int wm = (wid & 1) * 16;
    const int wn = (wid >> 1) * 8;
    const int a_row = wm + (lane & 15);
    const int a_k8  = (lane >> 4) * 8;
    const int b_row = wn + (lane & 7);
    const int b_ku  = (lane >> 3) & 3;

    const int hr = tid >> 3;
    const int hc = tid & 7;
    const uint32_t hswz = SWZ((uint32_t)(hr * 128 + hc * 16));

    const int pb = tid >> 3;
    const int pu = tid & 7;

    const int jloc = wn + (lane & 3) * 2;
    const int jrow_e = (jloc >> 3) * HDIM + u0 + (jloc & 7);
    const int br = wm + (lane >> 2);

    float c_reg = 0.f;
    unsigned gen = 0;

    // prefetch pre[0]
    float2 p0v = *(const float2*)(pre + (size_t)br * G4 + jrow_e);
    float2 p1v = *(const float2*)(pre + (size_t)(br + 8) * G4 + jrow_e);

    for (int t = 0; t < TSEQ; t++) {
        float acc[4] = {0.f, 0.f, 0.f, 0.f};

        if (t > 0) {
            const size_t hrow_base = ((size_t)hr * TSEQ + (t - 1)) * HDIM + hc * 8;
            // pair p: 16KB = 4 x 4KB subtiles of h-hi, k-range 256
            auto issue_pair = [&](int p) {
                const uint32_t d = sbase + HBUF + (uint32_t)(p % 3) * 16384 + hswz;
                const size_t g = hrow_base + (size_t)p * 256;
                cpa16(d,         ah + g);
                cpa16(d + 4096,  ah + g + 64);
                cpa16(d + 8192,  ah + g + 128);
                cpa16(d + 12288, ah + g + 192);
                CP_COMMIT();
            };
            issue_pair(0);
            issue_pair(1);
            for (int p = 0; p < 4; p++) {
                if (p < 3) { CP_WAIT1(); } else { CP_WAIT0(); }
                __syncthreads();
                if (p + 2 < 4) issue_pair(p + 2);
                const uint32_t stg = sbase + HBUF + (uint32_t)(p % 3) * 16384;
                #pragma unroll
                for (int sub = 0; sub < 4; sub++) {
                    const uint32_t wc = (uint32_t)(4 * p + sub) * 4096;
                    const uint32_t hb = stg + sub * 4096;
                    #pragma unroll
                    for (int kk2 = 0; kk2 < 2; kk2++) {
                        uint32_t bH4[4], bL4[4];
                        uint32_t boff = wc + SWZ((uint32_t)(b_row * 128 + kk2 * 64 + b_ku * 16));
                        ldsm_x4(bH4, sbase + W_HI + boff);
                        ldsm_x4(bL4, sbase + W_LO + boff);
                        #pragma unroll
                        for (int kh = 0; kh < 2; kh++) {
                            const int ks = kk2 * 2 + kh;
                            uint32_t aH4[4];
                            uint32_t aoff = SWZ((uint32_t)(a_row * 128 + ks * 32 + a_k8 * 2));
                            ldsm_x4(aH4, hb + aoff);
                            mma_fp16(acc, aH4, &bH4[kh * 2]);
                            mma_fp16(acc, aH4, &bL4[kh * 2]);
                        }
                    }
                }
            }
            __syncthreads();
        }

        // epilogue: g = acc + pre[t] (prefetched)
        g_s[jloc * 33 + br]           = acc[0] + p0v.x;
        g_s[(jloc + 1) * 33 + br]     = acc[1] + p0v.y;
        g_s[jloc * 33 + br + 8]       = acc[2] + p1v.x;
        g_s[(jloc + 1) * 33 + br + 8] = acc[3] + p1v.y;
        __syncthreads();

        // pointwise
        {
            float gi = g_s[pu * 33 + pb];
            float gf = g_s[(8 + pu) * 33 + pb];
            float gg = g_s[(16 + pu) * 33 + pb];
            float go = g_s[(24 + pu) * 33 + pb];
            float si = 1.f / (1.f + expf(-gi));
            float sf = 1.f / (1.f + expf(-gf));
            float so = 1.f / (1.f + expf(-go));
            c_reg = sf * c_reg + si * tanhf(gg);
            float hn = so * tanhf(c_reg);
            __half hh, hl;
            split_f16(hn, hh, hl);
            size_t orow = ((size_t)pb * TSEQ + t) * HDIM + u0 + pu;
            ah[orow] = hh;
            al[orow] = hl;     // kept: feeds the 2-term pre1 GEMM
        }
        __syncthreads();

        if (t + 1 < TSEQ) {
            // prefetch pre[t+1] before the barrier (latency hidden behind it)
            const float* pt = pre + (size_t)(t + 1) * BATCH * G4;
            p0v = *(const float2*)(pt + (size_t)br * G4 + jrow_e);
            p1v = *(const float2*)(pt + (size_t)(br + 8) * G4 + jrow_e);

            gen++;
            if (tid == 0) {
                asm volatile("red.release.gpu.global.add.u32 [%0], 1;"
                             :: "l"(&g_bar_ctr) : "memory");
                unsigned tgt = gen * NBLK, v;
                do {
                    asm volatile("ld.acquire.gpu.global.u32 %0, [%1];"
                                 : "=r"(v) : "l"(&g_bar_ctr) : "memory");
                } while (v < tgt);
            }
            __syncthreads();
        }
    }
}

// ---------------- host launch --------------------------------------------
extern "C" void kernel_launch(void* const* d_in, const int* in_sizes, int n_in,
                              void* d_out, int out_size)
{
    const float* image = (const float*)d_in[0];
    const int*   caps  = (const int*)  d_in[1];
    const float* lin_W = (const float*)d_in[2];
    const float* lin_b = (const float*)d_in[3];
    const float* bn_g  = (const float*)d_in[4];
    const float* bn_b  = (const float*)d_in[5];
    const float* emb   = (const float*)d_in[6];
    const float* Wih0  = (const float*)d_in[7];
    const float* Whh0  = (const float*)d_in[8];
    const float* bih0  = (const float*)d_in[9];
    const float* bhh0  = (const float*)d_in[10];
    const float* Wih1  = (const float*)d_in[11];
    const float* Whh1  = (const float*)d_in[12];
    const float* bih1  = (const float*)d_in[13];
    const float* bhh1  = (const float*)d_in[14];
    const float* fc_W  = (const float*)d_in[15];
    const float* fc_b  = (const float*)d_in[16];
    float* out = (float*)d_out;

    float *pre;
    __half *ah, *al, *w0, *w1, *fw;
    cudaGetSymbolAddress((void**)&pre, g_pre);
    cudaGetSymbolAddress((void**)&ah,  g_ah);
    cudaGetSymbolAddress((void**)&al,  g_al);
    cudaGetSymbolAddress((void**)&w0,  g_w0);
    cudaGetSymbolAddress((void**)&w1,  g_w1);
    cudaGetSymbolAddress((void**)&fw,  g_fw);

    static int smem_set = 0;
    const int PRE_SMEM  = 3 * PSTAGE + 1024;               // ~145KB
    const int FC_SMEM   = 3 * FSTAGE + 1024;               // ~97KB
    const int LSTM_SMEM = 131072 + 49152 + 4224 + 256;     // ~180.5KB
    if (!smem_set) {
        cudaFuncSetAttribute(gemm_pre,
                             cudaFuncAttributeMaxDynamicSharedMemorySize, PRE_SMEM);
        cudaFuncSetAttribute(gemm_fc_f16,
                             cudaFuncAttributeMaxDynamicSharedMemorySize, FC_SMEM);
        cudaFuncSetAttribute(lstm_persist,
                             cudaFuncAttributeMaxDynamicSharedMemorySize, LSTM_SMEM);
        smem_set = 1;
    }

    // inputs -> ah/al rows (K=EDIM layout)
    linbn_kernel<<<EDIM, 256>>>(image, lin_W, lin_b, bn_g, bn_b, ah, al);
    gather_kernel<<<dim3(TSEQ - 1, BATCH), 128>>>(caps, emb, ah, al);

    // layer-0 input weights, then pre0 GEMM (resets bar for lstm0)
    cvt_f16<<<(G4 * EDIM / 4 + 255) / 256, 256>>>(Wih0, w0, G4 * EDIM);
    gemm_pre<<<dim3(MROWS / 128, G4 / 128), 256, PRE_SMEM>>>(
        ah, al, w0, pre, MROWS, G4, EDIM, bih0, bhh0, 1);

    // remaining weight conversions
    cvt_f16<<<(G4 * HDIM / 4 + 255) / 256, 256>>>(Wih1, w1, G4 * HDIM);
    cvt_f16<<<(VOCAB * HDIM / 4 + 255) / 256, 256>>>(fc_W, fw, VOCAB * HDIM);

    // layer-0 recurrence
    lstm_persist<<<NBLK, 256, LSTM_SMEM>>>(pre, Whh0, ah, al);

    // pre1 = hs0 @ Wih1^T + biases (2-term; resets bar for lstm1)
    gemm_pre<<<dim3(MROWS / 128, G4 / 128), 256, PRE_SMEM>>>(
        ah, al, w1, pre, MROWS, G4, HDIM, bih1, bhh1, 1);

    // layer-1 recurrence
    lstm_persist<<<NBLK, 256, LSTM_SMEM>>>(pre, Whh1, ah, al);

    // logits = ah @ fw^T + fc_b  (fp16 1-term)
    gemm_fc_f16<<<dim3(MROWS / 128, VOCAB / 128), 256, FC_SMEM>>>(
        ah, fw, out, MROWS, VOCAB, HDIM, fc_b);
}

// round 16
// speedup vs baseline: 3.1780x; 1.0391x over previous
#include <cuda_runtime.h>
#include <cuda_fp16.h>
#include <math.h>
#include <stdint.h>

// Problem dims
#define VOCAB 32000
#define HDIM  1024
#define EDIM  512
#define BATCH 32
#define TSEQ  64
#define IMGF  2048
#define G4    (4*HDIM)          // 4096
#define MROWS (BATCH*TSEQ)      // 2048
#define NBLK  128               // persistent recurrence CTAs

// ---------------- device scratch (no allocation allowed) ----------------
__device__ float g_pre [MROWS * G4];     // time-major: [t][b][G4]
__device__ unsigned g_bar_ctr;

// fp16 activations (single) ; fp16 single weights
__device__ __half g_ah [MROWS * HDIM];
__device__ __half g_w0 [G4 * EDIM];
__device__ __half g_w1 [G4 * HDIM];
__device__ __half g_fw [VOCAB * HDIM];

// ======================= helpers =========================================
__device__ __forceinline__ uint32_t smem_u32(const void* p) {
    uint32_t a;
    asm("{ .reg .u64 t; cvta.to.shared.u64 t, %1; cvt.u32.u64 %0, t; }"
        : "=r"(a) : "l"(p));
    return a;
}
#define SWZ(x) ((x) ^ (((x) >> 3) & 0x70))

__device__ __forceinline__ void cpa16(uint32_t dst, const void* src) {
    asm volatile("cp.async.cg.shared.global [%0], [%1], 16;"
                 :: "r"(dst), "l"(src) : "memory");
}
#define CP_COMMIT() asm volatile("cp.async.commit_group;" ::: "memory")
#define CP_WAIT0()  asm volatile("cp.async.wait_group 0;" ::: "memory")
#define CP_WAIT1()  asm volatile("cp.async.wait_group 1;" ::: "memory")

__device__ __forceinline__ void ldsm_x4(uint32_t* r, uint32_t addr) {
    asm volatile("ldmatrix.sync.aligned.m8n8.x4.shared.b16 {%0,%1,%2,%3}, [%4];"
                 : "=r"(r[0]), "=r"(r[1]), "=r"(r[2]), "=r"(r[3]) : "r"(addr));
}
__device__ __forceinline__ void mma_fp16(float* c, const uint32_t* a, const uint32_t* b) {
    asm volatile(
        "mma.sync.aligned.m16n8k16.row.col.f32.f16.f16.f32 "
        "{%0,%1,%2,%3}, {%4,%5,%6,%7}, {%8,%9}, {%0,%1,%2,%3};"
        : "+f"(c[0]), "+f"(c[1]), "+f"(c[2]), "+f"(c[3])
        : "r"(a[0]), "r"(a[1]), "r"(a[2]), "r"(a[3]), "r"(b[0]), "r"(b[1]));
}
__device__ __forceinline__ void split_f16(float x, __half& h, __half& l) {
    h = __float2half(x);
    l = __float2half(x - __half2float(h));
}

// ============== fp32 -> fp16 conversion (weights) ========================
__global__ void cvt_f16(const float* __restrict__ x, __half* __restrict__ y, int n)
{
    int i = (blockIdx.x * 256 + threadIdx.x) * 4;
    if (i >= n) return;
    float4 v = *(const float4*)(x + i);
    __half2 p0; p0.x = __float2half(v.x); p0.y = __float2half(v.y);
    __half2 p1; p1.x = __float2half(v.z); p1.y = __float2half(v.w);
    *(__half2*)(y + i)     = p0;
    *(__half2*)(y + i + 2) = p1;
}

// ============== unified fp16 1-term GEMM: C = A*B^T + bias(es) ===========
// A[M,K], B[N,K] fp16. K-chunk 64, 2 tensors x 16KB = 32KB/stage, 3 stages.
// permute: out row m -> (m%64)*32 + m/64 (time-major for pre buffers).
#define TEN_T 16384
#define GSTAGE (2*TEN_T)
__global__ void __launch_bounds__(256, 1)
gemm_f16(const __half* __restrict__ A, const __half* __restrict__ B,
         float* __restrict__ C, int M, int N, int K,
         const float* __restrict__ bias1, const float* __restrict__ bias2,
         int permute)
{
    extern __shared__ char dsm[];
    const int tid  = threadIdx.x;
    const int wid  = tid >> 5;
    const int lane = tid & 31;
    const int bm = blockIdx.x * 128;
    const int bn = blockIdx.y * 128;
    const int wm = (wid & 3) * 32;
    const int wn = (wid >> 2) * 64;
    const int nk = K >> 6;

    // fold in the grid-barrier reset for a following lstm launch
    if (blockIdx.x == 0 && blockIdx.y == 0 && tid == 0) g_bar_ctr = 0u;

    uint32_t dyn = smem_u32(dsm);
    uint32_t sb0 = (dyn + 1023u) & ~1023u;

    float acc[2][8][4];
    #pragma unroll
    for (int i = 0; i < 2; i++)
        #pragma unroll
        for (int j = 0; j < 8; j++)
            #pragma unroll
            for (int r = 0; r < 4; r++) acc[i][j][r] = 0.f;

    auto issue_load = [&](int kt, int stg) {
        const uint32_t st = sb0 + (uint32_t)stg * GSTAGE;
        const size_t koff = (size_t)kt * 64;
        #pragma unroll
        for (int i = 0; i < 8; i++) {
            int id = i * 256 + tid;
            int tensor = id >> 10;
            int cid = id & 1023;
            int r = cid >> 3, c = cid & 7;
            uint32_t dst = st + tensor * TEN_T + SWZ((uint32_t)(r * 128 + c * 16));
            const __half* src;
            if (tensor == 0) src = A + (size_t)(bm + r) * K + koff + c * 8;
            else             src = B + (size_t)(bn + r) * K + koff + c * 8;
            cpa16(dst, src);
        }
        CP_COMMIT();
    };

    issue_load(0, 0);
    if (nk > 1) issue_load(1, 1);

    const int a_row = wm + (lane & 15);
    const int a_k8  = (lane >> 4) * 8;
    const int b_row = wn + ((lane >> 4) & 1) * 8 + (lane & 7);
    const int b_k8  = ((lane >> 3) & 1) * 8;

    uint32_t aF[2][2][4], bF[2][4][4];

    int s_cur = 0, s_nxt = 2;
    for (int kt = 0; kt < nk; kt++) {
        if (kt + 1 < nk) { CP_WAIT1(); } else { CP_WAIT0(); }
        __syncthreads();
        if (kt + 2 < nk) issue_load(kt + 2, s_nxt);

        const uint32_t st = sb0 + (uint32_t)s_cur * GSTAGE;
        const uint32_t sA = st;
        const uint32_t sB = st + TEN_T;

        auto load_frags = [&](int buf, int ksv) {
            const int kb = ksv * 16;
            #pragma unroll
            for (int mi = 0; mi < 2; mi++) {
                uint32_t off = SWZ((uint32_t)((a_row + mi * 16) * 128 + (kb + a_k8) * 2));
                ldsm_x4(aF[buf][mi], sA + off);
            }
            #pragma unroll
            for (int p = 0; p < 4; p++) {
                uint32_t off = SWZ((uint32_t)((b_row + p * 16) * 128 + (kb + b_k8) * 2));
                ldsm_x4(bF[buf][p], sB + off);
            }
        };

        load_frags(0, 0);
        #pragma unroll
        for (int ks = 0; ks < 4; ks++) {
            const int cb = ks & 1;
            if (ks < 3) load_frags(cb ^ 1, ks + 1);
            #pragma unroll
            for (int mi = 0; mi < 2; mi++)
                #pragma unroll
                for (int p = 0; p < 4; p++)
                    #pragma unroll
                    for (int j = 0; j < 2; j++)
                        mma_fp16(acc[mi][p * 2 + j], aF[cb][mi], &bF[cb][p][j * 2]);
        }

        s_cur = (s_cur == 2) ? 0 : s_cur + 1;
        s_nxt = (s_nxt == 2) ? 0 : s_nxt + 1;
    }

    #pragma unroll
    for (int nj = 0; nj < 8; nj++) {
        const int col = bn + wn + nj * 8 + (lane & 3) * 2;
        float b0 = bias1 ? bias1[col] : 0.f;
        float b1 = bias1 ? bias1[col + 1] : 0.f;
        if (bias2) { b0 += bias2[col]; b1 += bias2[col + 1]; }
        #pragma unroll
        for (int mi = 0; mi < 2; mi++) {
            const int r0 = bm + wm + mi * 16 + (lane >> 2);
            const int r1 = r0 + 8;
            int o0 = permute ? ((r0 & 63) * 32 + (r0 >> 6)) : r0;
            int o1 = permute ? ((r1 & 63) * 32 + (r1 >> 6)) : r1;
            float2 v0 = make_float2(acc[mi][nj][0] + b0, acc[mi][nj][1] + b1);
            float2 v1 = make_float2(acc[mi][nj][2] + b0, acc[mi][nj][3] + b1);
            *(float2*)(C + (size_t)o0 * N + col) = v0;
            *(float2*)(C + (size_t)o1 * N + col) = v1;
        }
    }
}

// ---------------- linear(2048->512) + batchnorm -> fp16 ------------------
__global__ void linbn_kernel(const float* __restrict__ img,
                             const float* __restrict__ W,
                             const float* __restrict__ bias,
                             const float* __restrict__ gamma,
                             const float* __restrict__ beta,
                             __half* __restrict__ ah)
{
    const int e   = blockIdx.x;
    const int tid = threadIdx.x;
    __shared__ float wrow[IMGF];
    __shared__ float xv[BATCH];

    {
        const float* wsrc = W + (size_t)e * IMGF;
        #pragma unroll
        for (int i = 0; i < 2; i++) {
            int k = (tid + i * 256) * 4;
            *(float4*)&wrow[k] = *(const float4*)(wsrc + k);
        }
    }
    __syncthreads();

    const int lane = tid & 31, wid = tid >> 5;
    float a0 = 0.f, a1 = 0.f, a2 = 0.f, a3 = 0.f;
    for (int k = lane; k < IMGF; k += 32) {
        float wv = wrow[k];
        a0 += img[(size_t)(wid +  0) * IMGF + k] * wv;
        a1 += img[(size_t)(wid +  8) * IMGF + k] * wv;
        a2 += img[(size_t)(wid + 16) * IMGF + k] * wv;
        a3 += img[(size_t)(wid + 24) * IMGF + k] * wv;
    }
    #pragma unroll
    for (int o = 16; o > 0; o >>= 1) {
        a0 += __shfl_xor_sync(0xffffffffu, a0, o);
        a1 += __shfl_xor_sync(0xffffffffu, a1, o);
        a2 += __shfl_xor_sync(0xffffffffu, a2, o);
        a3 += __shfl_xor_sync(0xffffffffu, a3, o);
    }
    if (lane == 0) {
        float bb = bias[e];
        xv[wid +  0] = a0 + bb;
        xv[wid +  8] = a1 + bb;
        xv[wid + 16] = a2 + bb;
        xv[wid + 24] = a3 + bb;
    }
    __syncthreads();

    if (tid < 32) {
        float x = xv[tid];
        float s = x, q = x * x;
        #pragma unroll
        for (int o = 16; o > 0; o >>= 1) {
            s += __shfl_xor_sync(0xffffffffu, s, o);
            q += __shfl_xor_sync(0xffffffffu, q, o);
        }
        float mu  = s * (1.f / 32.f);
        float var = q * (1.f / 32.f) - mu * mu;
        float inv = rsqrtf(var + 1e-5f);
        float y = gamma[e] * (x - mu) * inv + beta[e];
        ah[((size_t)tid * TSEQ + 0) * EDIM + e] = __float2half(y);
    }
}

// ---------------- embedding gather -> fp16 rows t>=1 ---------------------
__global__ void gather_kernel(const int* __restrict__ cap,
                              const float* __restrict__ emb,
                              __half* __restrict__ ah)
{
    const int t = blockIdx.x + 1;
    const int b = blockIdx.y;
    const int tok = cap[b * TSEQ + (t - 1)];
    const int k = threadIdx.x * 4;
    float4 v = *(const float4*)(emb + (size_t)tok * EDIM + k);
    __half2 p0; p0.x = __float2half(v.x); p0.y = __float2half(v.y);
    __half2 p1; p1.x = __float2half(v.z); p1.y = __float2half(v.w);
    size_t row = ((size_t)b * TSEQ + t) * EDIM + k;
    *(__half2*)(ah + row)     = p0;
    *(__half2*)(ah + row + 2) = p1;
}

// ---------------- persistent HMMA LSTM layer (2-term: hH x (WH+WL)) -------
// h fp16 single staged: 4 pairs of k256 (16KB each), 3 pair-buffers.
__global__ void __launch_bounds__(256, 1)
lstm_persist(const float* __restrict__ pre,   // [T][B][G4]
             const float* __restrict__ Whh,   // [G4][HDIM]
             __half* __restrict__ ah)         // [b*T+t][HDIM]
{
    extern __shared__ char sm_raw[];
    uint32_t raw = smem_u32(sm_raw);
    uint32_t sbase = (raw + 127u) & ~127u;
    char* base = sm_raw + (sbase - raw);
    const uint32_t W_HI = 0;
    const uint32_t W_LO = 65536;
    const uint32_t HBUF = 131072;                 // 3 pair-buffers x 16KB
    float* g_s = (float*)(base + HBUF + 49152);   // [32][33]

    const int tid  = threadIdx.x;
    const int wid  = tid >> 5;
    const int lane = tid & 31;
    const int u0   = blockIdx.x * 8;

    // one-time: convert Whh slice -> smem fp16 hi/lo (swizzled, 64k tiles)
    #pragma unroll
    for (int i = 0; i < 16; i++) {
        int cell = i * 256 + tid;
        int kt = cell >> 8;
        int r  = (cell >> 3) & 31;
        int cc = cell & 7;
        int jrow = (r >> 3) * HDIM + u0 + (r & 7);
        const float* src = Whh + (size_t)jrow * HDIM + kt * 64 + cc * 8;
        float4 v0 = *(const float4*)src;
        float4 v1 = *(const float4*)(src + 4);
        float f[8] = {v0.x, v0.y, v0.z, v0.w, v1.x, v1.y, v1.z, v1.w};
        uint32_t hi4[4], lo4[4];
        #pragma unroll
        for (int q = 0; q < 4; q++) {
            __half h0, l0, h1, l1;
            split_f16(f[2*q],   h0, l0);
            split_f16(f[2*q+1], h1, l1);
            __half2 hp; hp.x = h0; hp.y = h1;
            __half2 lp; lp.x = l0; lp.y = l1;
            hi4[q] = *(uint32_t*)&hp;
            lo4[q] = *(uint32_t*)&lp;
        }
        uint32_t off = kt * 4096 + SWZ((uint32_t)(r * 128 + cc * 16));
        *(uint4*)(base + W_HI + off) = make_uint4(hi4[0], hi4[1], hi4[2], hi4[3]);
        *(uint4*)(base + W_LO + off) = make_uint4(lo4[0], lo4[1], lo4[2], lo4[3]);
    }
    __syncthreads();

    const int wm = (wid & 1) * 16;
    const int wn = (wid >> 1) * 8;
    const int a_row = wm + (lane & 15);
    const int a_k8  = (lane >> 4) * 8;
    const int b_row = wn + (lane & 7);
    const int b_ku  = (lane >> 3) & 3;

    const int hr = tid >> 3;
    const int hc = tid & 7;
    const uint32_t hswz = SWZ((uint32_t)(hr * 128 + hc * 16));

    const int pb = tid >> 3;
    const int pu = tid & 7;

    const int jloc = wn + (lane & 3) * 2;
    const int jrow_e = (jloc >> 3) * HDIM + u0 + (jloc & 7);
    const int br = wm + (lane >> 2);

    float c_reg = 0.f;
    unsigned gen = 0;

    // prefetch pre[0]
    float2 p0v = *(const float2*)(pre + (size_t)br * G4 + jrow_e);
    float2 p1v = *(const float2*)(pre + (size_t)(br + 8) * G4 + jrow_e);

    for (int t = 0; t < TSEQ; t++) {
        float acc[4] = {0.f, 0.f, 0.f, 0.f};

        if (t > 0) {
            const size_t hrow_base = ((size_t)hr * TSEQ + (t - 1)) * HDIM + hc * 8;
            auto issue_pair = [&](int p) {
                const uint32_t d = sbase + HBUF + (uint32_t)(p % 3) * 16384 + hswz;
                const size_t g = hrow_base + (size_t)p * 256;
                cpa16(d,         ah + g);
                cpa16(d + 4096,  ah + g + 64);
                cpa16(d + 8192,  ah + g + 128);
                cpa16(d + 12288, ah + g + 192);
                CP_COMMIT();
            };
            issue_pair(0);
            issue_pair(1);
            for (int p = 0; p < 4; p++) {
                if (p < 3) { CP_WAIT1(); } else { CP_WAIT0(); }
                __syncthreads();
                if (p + 2 < 4) issue_pair(p + 2);
                const uint32_t stg = sbase + HBUF + (uint32_t)(p % 3) * 16384;
                #pragma unroll
                for (int sub = 0; sub < 4; sub++) {
                    const uint32_t wc = (uint32_t)(4 * p + sub) * 4096;
                    const uint32_t hb = stg + sub * 4096;
                    #pragma unroll
                    for (int kk2 = 0; kk2 < 2; kk2++) {
                        uint32_t bH4[4], bL4[4];
                        uint32_t boff = wc + SWZ((uint32_t)(b_row * 128 + kk2 * 64 + b_ku * 16));
                        ldsm_x4(bH4, sbase + W_HI + boff);
                        ldsm_x4(bL4, sbase + W_LO + boff);
                        #pragma unroll
                        for (int kh = 0; kh < 2; kh++) {
                            const int ks = kk2 * 2 + kh;
                            uint32_t aH4[4];
                            uint32_t aoff = SWZ((uint32_t)(a_row * 128 + ks * 32 + a_k8 * 2));
                            ldsm_x4(aH4, hb + aoff);
                            mma_fp16(acc, aH4, &bH4[kh * 2]);
                            mma_fp16(acc, aH4, &bL4[kh * 2]);
                        }
                    }
                }
            }
            __syncthreads();
        }

        // epilogue: g = acc + pre[t] (prefetched)
        g_s[jloc * 33 + br]           = acc[0] + p0v.x;
        g_s[(jloc + 1) * 33 + br]     = acc[1] + p0v.y;
        g_s[jloc * 33 + br + 8]       = acc[2] + p1v.x;
        g_s[(jloc + 1) * 33 + br + 8] = acc[3] + p1v.y;
        __syncthreads();

        // pointwise
        {
            float gi = g_s[pu * 33 + pb];
            float gf = g_s[(8 + pu) * 33 + pb];
            float gg = g_s[(16 + pu) * 33 + pb];
            float go = g_s[(24 + pu) * 33 + pb];
            float si = 1.f / (1.f + expf(-gi));
            float sf = 1.f / (1.f + expf(-gf));
            float so = 1.f / (1.f + expf(-go));
            c_reg = sf * c_reg + si * tanhf(gg);
            float hn = so * tanhf(c_reg);
            ah[((size_t)pb * TSEQ + t) * HDIM + u0 + pu] = __float2half(hn);
        }
        __syncthreads();

        if (t + 1 < TSEQ) {
            // prefetch pre[t+1] before the barrier (latency hidden behind it)
            const float* pt = pre + (size_t)(t + 1) * BATCH * G4;
            p0v = *(const float2*)(pt + (size_t)br * G4 + jrow_e);
            p1v = *(const float2*)(pt + (size_t)(br + 8) * G4 + jrow_e);

            gen++;
            if (tid == 0) {
                asm volatile("red.release.gpu.global.add.u32 [%0], 1;"
                             :: "l"(&g_bar_ctr) : "memory");
                unsigned tgt = gen * NBLK, v;
                do {
                    asm volatile("ld.acquire.gpu.global.u32 %0, [%1];"
                                 : "=r"(v) : "l"(&g_bar_ctr) : "memory");
                } while (v < tgt);
            }
            __syncthreads();
        }
    }
}

// ---------------- host launch --------------------------------------------
extern "C" void kernel_launch(void* const* d_in, const int* in_sizes, int n_in,
                              void* d_out, int out_size)
{
    const float* image = (const float*)d_in[0];
    const int*   caps  = (const int*)  d_in[1];
    const float* lin_W = (const float*)d_in[2];
    const float* lin_b = (const float*)d_in[3];
    const float* bn_g  = (const float*)d_in[4];
    const float* bn_b  = (const float*)d_in[5];
    const float* emb   = (const float*)d_in[6];
    const float* Wih0  = (const float*)d_in[7];
    const float* Whh0  = (const float*)d_in[8];
    const float* bih0  = (const float*)d_in[9];
    const float* bhh0  = (const float*)d_in[10];
    const float* Wih1  = (const float*)d_in[11];
    const float* Whh1  = (const float*)d_in[12];
    const float* bih1  = (const float*)d_in[13];
    const float* bhh1  = (const float*)d_in[14];
    const float* fc_W  = (const float*)d_in[15];
    const float* fc_b  = (const float*)d_in[16];
    float* out = (float*)d_out;

    float *pre;
    __half *ah, *w0, *w1, *fw;
    cudaGetSymbolAddress((void**)&pre, g_pre);
    cudaGetSymbolAddress((void**)&ah,  g_ah);
    cudaGetSymbolAddress((void**)&w0,  g_w0);
    cudaGetSymbolAddress((void**)&w1,  g_w1);
    cudaGetSymbolAddress((void**)&fw,  g_fw);

    static int smem_set = 0;
    const int GEMM_SMEM = 3 * GSTAGE + 1024;               // ~97KB
    const int LSTM_SMEM = 131072 + 49152 + 4224 + 256;     // ~180.5KB
    if (!smem_set) {
        cudaFuncSetAttribute(gemm_f16,
                             cudaFuncAttributeMaxDynamicSharedMemorySize, GEMM_SMEM);
        cudaFuncSetAttribute(lstm_persist,
                             cudaFuncAttributeMaxDynamicSharedMemorySize, LSTM_SMEM);
        smem_set = 1;
    }

    // inputs -> ah rows (K=EDIM layout, single fp16)
    linbn_kernel<<<EDIM, 256>>>(image, lin_W, lin_b, bn_g, bn_b, ah);
    gather_kernel<<<dim3(TSEQ - 1, BATCH), 128>>>(caps, emb, ah);

    // layer-0 input weights, then pre0 GEMM (resets bar for lstm0)
    cvt_f16<<<(G4 * EDIM / 4 + 255) / 256, 256>>>(Wih0, w0, G4 * EDIM);
    gemm_f16<<<dim3(MROWS / 128, G4 / 128), 256, GEMM_SMEM>>>(
        ah, w0, pre, MROWS, G4, EDIM, bih0, bhh0, 1);

    // remaining weight conversions
    cvt_f16<<<(G4 * HDIM / 4 + 255) / 256, 256>>>(Wih1, w1, G4 * HDIM);
    cvt_f16<<<(VOCAB * HDIM / 4 + 255) / 256, 256>>>(fc_W, fw, VOCAB * HDIM);

    // layer-0 recurrence
    lstm_persist<<<NBLK, 256, LSTM_SMEM>>>(pre, Whh0, ah);

    // pre1 = hs0 @ Wih1^T + biases (1-term; resets bar for lstm1)
    gemm_f16<<<dim3(MROWS / 128, G4 / 128), 256, GEMM_SMEM>>>(
        ah, w1, pre, MROWS, G4, HDIM, bih1, bhh1, 1);

    // layer-1 recurrence
    lstm_persist<<<NBLK, 256, LSTM_SMEM>>>(pre, Whh1, ah);

    // logits = ah @ fw^T + fc_b
    gemm_f16<<<dim3(MROWS / 128, VOCAB / 128), 256, GEMM_SMEM>>>(
        ah, fw, out, MROWS, VOCAB, HDIM, fc_b, nullptr, 0);
}

// round 17
// speedup vs baseline: 3.3966x; 1.0688x over previous
#include <cuda_runtime.h>
#include <cuda_fp16.h>
#include <math.h>
#include <stdint.h>

// Problem dims
#define VOCAB 32000
#define HDIM  1024
#define EDIM  512
#define BATCH 32
#define TSEQ  64
#define IMGF  2048
#define G4    (4*HDIM)          // 4096
#define MROWS (BATCH*TSEQ)      // 2048
#define NBLK  128               // persistent recurrence CTAs

// ---------------- device scratch (no allocation allowed) ----------------
__device__ float g_pre [MROWS * G4];     // time-major: [t][b][G4]
__device__ unsigned g_bar_ctr;

// fp16 activations (single) ; fp16 single weights
__device__ __half g_ah [MROWS * HDIM];
__device__ __half g_w0 [G4 * EDIM];
__device__ __half g_w1 [G4 * HDIM];
__device__ __half g_fw [VOCAB * HDIM];

// ======================= helpers =========================================
__device__ __forceinline__ uint32_t smem_u32(const void* p) {
    uint32_t a;
    asm("{ .reg .u64 t; cvta.to.shared.u64 t, %1; cvt.u32.u64 %0, t; }"
        : "=r"(a) : "l"(p));
    return a;
}
#define SWZ(x) ((x) ^ (((x) >> 3) & 0x70))

__device__ __forceinline__ void cpa16(uint32_t dst, const void* src) {
    asm volatile("cp.async.cg.shared.global [%0], [%1], 16;"
                 :: "r"(dst), "l"(src) : "memory");
}
#define CP_COMMIT() asm volatile("cp.async.commit_group;" ::: "memory")
#define CP_WAIT0()  asm volatile("cp.async.wait_group 0;" ::: "memory")
#define CP_WAIT1()  asm volatile("cp.async.wait_group 1;" ::: "memory")

__device__ __forceinline__ void ldsm_x4(uint32_t* r, uint32_t addr) {
    asm volatile("ldmatrix.sync.aligned.m8n8.x4.shared.b16 {%0,%1,%2,%3}, [%4];"
                 : "=r"(r[0]), "=r"(r[1]), "=r"(r[2]), "=r"(r[3]) : "r"(addr));
}
__device__ __forceinline__ void mma_fp16(float* c, const uint32_t* a, const uint32_t* b) {
    asm volatile(
        "mma.sync.aligned.m16n8k16.row.col.f32.f16.f16.f32 "
        "{%0,%1,%2,%3}, {%4,%5,%6,%7}, {%8,%9}, {%0,%1,%2,%3};"
        : "+f"(c[0]), "+f"(c[1]), "+f"(c[2]), "+f"(c[3])
        : "r"(a[0]), "r"(a[1]), "r"(a[2]), "r"(a[3]), "r"(b[0]), "r"(b[1]));
}
__device__ __forceinline__ void split_f16(float x, __half& h, __half& l) {
    h = __float2half(x);
    l = __float2half(x - __half2float(h));
}

// ============== fp32 -> fp16 conversion (weights) ========================
__global__ void cvt_f16(const float* __restrict__ x, __half* __restrict__ y, int n)
{
    int i = (blockIdx.x * 256 + threadIdx.x) * 4;
    if (i >= n) return;
    float4 v = *(const float4*)(x + i);
    __half2 p0; p0.x = __float2half(v.x); p0.y = __float2half(v.y);
    __half2 p1; p1.x = __float2half(v.z); p1.y = __float2half(v.w);
    *(__half2*)(y + i)     = p0;
    *(__half2*)(y + i + 2) = p1;
}

// ============== unified fp16 1-term GEMM: C = A*B^T + bias(es) ===========
// CTA tile 128M x 256N, warp tile 32x128 (8 warps 4x2). K-chunk 64.
// stage = A 16KB + B 32KB = 48KB; 3 stages. N%256==0, M%128==0, K%64==0.
#define TEN_A 16384
#define TEN_B 32768
#define GSTAGE (TEN_A + TEN_B)
__global__ void __launch_bounds__(256, 1)
gemm_f16(const __half* __restrict__ A, const __half* __restrict__ B,
         float* __restrict__ C, int M, int N, int K,
         const float* __restrict__ bias1, const float* __restrict__ bias2,
         int permute)
{
    extern __shared__ char dsm[];
    const int tid  = threadIdx.x;
    const int wid  = tid >> 5;
    const int lane = tid & 31;
    const int bm = blockIdx.x * 128;
    const int bn = blockIdx.y * 256;
    const int wm = (wid & 3) * 32;      // 4 warp-rows
    const int wn = (wid >> 2) * 128;    // 2 warp-cols
    const int nk = K >> 6;

    // fold in the grid-barrier reset for a following lstm launch
    if (blockIdx.x == 0 && blockIdx.y == 0 && tid == 0) g_bar_ctr = 0u;

    uint32_t dyn = smem_u32(dsm);
    uint32_t sb0 = (dyn + 1023u) & ~1023u;

    float acc[2][16][4];
    #pragma unroll
    for (int i = 0; i < 2; i++)
        #pragma unroll
        for (int j = 0; j < 16; j++)
            #pragma unroll
            for (int r = 0; r < 4; r++) acc[i][j][r] = 0.f;

    auto issue_load = [&](int kt, int stg) {
        const uint32_t st = sb0 + (uint32_t)stg * GSTAGE;
        const size_t koff = (size_t)kt * 64;
        #pragma unroll
        for (int i = 0; i < 12; i++) {          // 3072 chunks: A 1024 | B 2048
            int id = i * 256 + tid;
            if (id < 1024) {
                int r = id >> 3, c = id & 7;
                uint32_t dst = st + SWZ((uint32_t)(r * 128 + c * 16));
                cpa16(dst, A + (size_t)(bm + r) * K + koff + c * 8);
            } else {
                int cid = id - 1024;
                int r = cid >> 3, c = cid & 7;
                uint32_t dst = st + TEN_A + SWZ((uint32_t)(r * 128 + c * 16));
                cpa16(dst, B + (size_t)(bn + r) * K + koff + c * 8);
            }
        }
        CP_COMMIT();
    };

    issue_load(0, 0);
    if (nk > 1) issue_load(1, 1);

    const int a_row = wm + (lane & 15);
    const int a_k8  = (lane >> 4) * 8;
    const int b_row = wn + ((lane >> 4) & 1) * 8 + (lane & 7);
    const int b_k8  = ((lane >> 3) & 1) * 8;

    uint32_t aF[2][2][4];

    int s_cur = 0, s_nxt = 2;
    for (int kt = 0; kt < nk; kt++) {
        if (kt + 1 < nk) { CP_WAIT1(); } else { CP_WAIT0(); }
        __syncthreads();
        if (kt + 2 < nk) issue_load(kt + 2, s_nxt);

        const uint32_t st = sb0 + (uint32_t)s_cur * GSTAGE;
        const uint32_t sA = st;
        const uint32_t sB = st + TEN_A;

        auto load_afrags = [&](int buf, int ksv) {
            const int kb = ksv * 16;
            #pragma unroll
            for (int mi = 0; mi < 2; mi++) {
                uint32_t off = SWZ((uint32_t)((a_row + mi * 16) * 128 + (kb + a_k8) * 2));
                ldsm_x4(aF[buf][mi], sA + off);
            }
        };

        load_afrags(0, 0);
        #pragma unroll
        for (int ks = 0; ks < 4; ks++) {
            const int cb = ks & 1;
            if (ks < 3) load_afrags(cb ^ 1, ks + 1);
            const int kb = ks * 16;
            #pragma unroll
            for (int p = 0; p < 8; p++) {
                uint32_t bF[4];
                uint32_t off = SWZ((uint32_t)((b_row + p * 16) * 128 + (kb + b_k8) * 2));
                ldsm_x4(bF, sB + off);
                #pragma unroll
                for (int mi = 0; mi < 2; mi++)
                    #pragma unroll
                    for (int j = 0; j < 2; j++)
                        mma_fp16(acc[mi][p * 2 + j], aF[cb][mi], &bF[j * 2]);
            }
        }

        s_cur = (s_cur == 2) ? 0 : s_cur + 1;
        s_nxt = (s_nxt == 2) ? 0 : s_nxt + 1;
    }

    #pragma unroll
    for (int nj = 0; nj < 16; nj++) {
        const int col = bn + wn + nj * 8 + (lane & 3) * 2;
        float b0 = bias1 ? bias1[col] : 0.f;
        float b1 = bias1 ? bias1[col + 1] : 0.f;
        if (bias2) { b0 += bias2[col]; b1 += bias2[col + 1]; }
        #pragma unroll
        for (int mi = 0; mi < 2; mi++) {
            const int r0 = bm + wm + mi * 16 + (lane >> 2);
            const int r1 = r0 + 8;
            int o0 = permute ? ((r0 & 63) * 32 + (r0 >> 6)) : r0;
            int o1 = permute ? ((r1 & 63) * 32 + (r1 >> 6)) : r1;
            float2 v0 = make_float2(acc[mi][nj][0] + b0, acc[mi][nj][1] + b1);
            float2 v1 = make_float2(acc[mi][nj][2] + b0, acc[mi][nj][3] + b1);
            *(float2*)(C + (size_t)o0 * N + col) = v0;
            *(float2*)(C + (size_t)o1 * N + col) = v1;
        }
    }
}

// ---------------- linear(2048->512) + batchnorm -> fp16 ------------------
__global__ void linbn_kernel(const float* __restrict__ img,
                             const float* __restrict__ W,
                             const float* __restrict__ bias,
                             const float* __restrict__ gamma,
                             const float* __restrict__ beta,
                             __half* __restrict__ ah)
{
    const int e   = blockIdx.x;
    const int tid = threadIdx.x;
    __shared__ float wrow[IMGF];
    __shared__ float xv[BATCH];

    {
        const float* wsrc = W + (size_t)e * IMGF;
        #pragma unroll
        for (int i = 0; i < 2; i++) {
            int k = (tid + i * 256) * 4;
            *(float4*)&wrow[k] = *(const float4*)(wsrc + k);
        }
    }
    __syncthreads();

    const int lane = tid & 31, wid = tid >> 5;
    float a0 = 0.f, a1 = 0.f, a2 = 0.f, a3 = 0.f;
    for (int k = lane; k < IMGF; k += 32) {
        float wv = wrow[k];
        a0 += img[(size_t)(wid +  0) * IMGF + k] * wv;
        a1 += img[(size_t)(wid +  8) * IMGF + k] * wv;
        a2 += img[(size_t)(wid + 16) * IMGF + k] * wv;
        a3 += img[(size_t)(wid + 24) * IMGF + k] * wv;
    }
    #pragma unroll
    for (int o = 16; o > 0; o >>= 1) {
        a0 += __shfl_xor_sync(0xffffffffu, a0, o);
        a1 += __shfl_xor_sync(0xffffffffu, a1, o);
        a2 += __shfl_xor_sync(0xffffffffu, a2, o);
        a3 += __shfl_xor_sync(0xffffffffu, a3, o);
    }
    if (lane == 0) {
        float bb = bias[e];
        xv[wid +  0] = a0 + bb;
        xv[wid +  8] = a1 + bb;
        xv[wid + 16] = a2 + bb;
        xv[wid + 24] = a3 + bb;
    }
    __syncthreads();

    if (tid < 32) {
        float x = xv[tid];
        float s = x, q = x * x;
        #pragma unroll
        for (int o = 16; o > 0; o >>= 1) {
            s += __shfl_xor_sync(0xffffffffu, s, o);
            q += __shfl_xor_sync(0xffffffffu, q, o);
        }
        float mu  = s * (1.f / 32.f);
        float var = q * (1.f / 32.f) - mu * mu;
        float inv = rsqrtf(var + 1e-5f);
        float y = gamma[e] * (x - mu) * inv + beta[e];
        ah[((size_t)tid * TSEQ + 0) * EDIM + e] = __float2half(y);
    }
}

// ---------------- embedding gather -> fp16 rows t>=1 ---------------------
__global__ void gather_kernel(const int* __restrict__ cap,
                              const float* __restrict__ emb,
                              __half* __restrict__ ah)
{
    const int t = blockIdx.x + 1;
    const int b = blockIdx.y;
    const int tok = cap[b * TSEQ + (t - 1)];
    const int k = threadIdx.x * 4;
    float4 v = *(const float4*)(emb + (size_t)tok * EDIM + k);
    __half2 p0; p0.x = __float2half(v.x); p0.y = __float2half(v.y);
    __half2 p1; p1.x = __float2half(v.z); p1.y = __float2half(v.w);
    size_t row = ((size_t)b * TSEQ + t) * EDIM + k;
    *(__half2*)(ah + row)     = p0;
    *(__half2*)(ah + row + 2) = p1;
}

// ---------------- persistent HMMA LSTM layer (2-term: hH x (WH+WL)) -------
__global__ void __launch_bounds__(256, 1)
lstm_persist(const float* __restrict__ pre,   // [T][B][G4]
             const float* __restrict__ Whh,   // [G4][HDIM]
             __half* __restrict__ ah)         // [b*T+t][HDIM]
{
    extern __shared__ char sm_raw[];
    uint32_t raw = smem_u32(sm_raw);
    uint32_t sbase = (raw + 127u) & ~127u;
    char* base = sm_raw + (sbase - raw);
    const uint32_t W_HI = 0;
    const uint32_t W_LO = 65536;
    const uint32_t HBUF = 131072;                 // 3 pair-buffers x 16KB
    float* g_s = (float*)(base + HBUF + 49152);   // [32][33]

    const int tid  = threadIdx.x;
    const int wid  = tid >> 5;
    const int lane = tid & 31;
    const int u0   = blockIdx.x * 8;

    // one-time: convert Whh slice -> smem fp16 hi/lo (swizzled, 64k tiles)
    #pragma unroll
    for (int i = 0; i < 16; i++) {
        int cell = i * 256 + tid;
        int kt = cell >> 8;
        int r  = (cell >> 3) & 31;
        int cc = cell & 7;
        int jrow = (r >> 3) * HDIM + u0 + (r & 7);
        const float* src = Whh + (size_t)jrow * HDIM + kt * 64 + cc * 8;
        float4 v0 = *(const float4*)src;
        float4 v1 = *(const float4*)(src + 4);
        float f[8] = {v0.x, v0.y, v0.z, v0.w, v1.x, v1.y, v1.z, v1.w};
        uint32_t hi4[4], lo4[4];
        #pragma unroll
        for (int q = 0; q < 4; q++) {
            __half h0, l0, h1, l1;
            split_f16(f[2*q],   h0, l0);
            split_f16(f[2*q+1], h1, l1);
            __half2 hp; hp.x = h0; hp.y = h1;
            __half2 lp; lp.x = l0; lp.y = l1;
            hi4[q] = *(uint32_t*)&hp;
            lo4[q] = *(uint32_t*)&lp;
        }
        uint32_t off = kt * 4096 + SWZ((uint32_t)(r * 128 + cc * 16));
        *(uint4*)(base + W_HI + off) = make_uint4(hi4[0], hi4[1], hi4[2], hi4[3]);
        *(uint4*)(base + W_LO + off) = make_uint4(lo4[0], lo4[1], lo4[2], lo4[3]);
    }
    __syncthreads();

    const int wm = (wid & 1) * 16;
    const int wn = (wid >> 1) * 8;
    const int a_row = wm + (lane & 15);
    const int a_k8  = (lane >> 4) * 8;
    const int b_row = wn + (lane & 7);
    const int b_ku  = (lane >> 3) & 3;

    const int hr = tid >> 3;
    const int hc = tid & 7;
    const uint32_t hswz = SWZ((uint32_t)(hr * 128 + hc * 16));

    const int pb = tid >> 3;
    const int pu = tid & 7;

    const int jloc = wn + (lane & 3) * 2;
    const int jrow_e = (jloc >> 3) * HDIM + u0 + (jloc & 7);
    const int br = wm + (lane >> 2);

    float c_reg = 0.f;
    unsigned gen = 0;

    // prefetch pre[0]
    float2 p0v = *(const float2*)(pre + (size_t)br * G4 + jrow_e);
    float2 p1v = *(const float2*)(pre + (size_t)(br + 8) * G4 + jrow_e);

    for (int t = 0; t < TSEQ; t++) {
        float acc[4] = {0.f, 0.f, 0.f, 0.f};

        if (t > 0) {
            const size_t hrow_base = ((size_t)hr * TSEQ + (t - 1)) * HDIM + hc * 8;
            auto issue_pair = [&](int p) {
                const uint32_t d = sbase + HBUF + (uint32_t)(p % 3) * 16384 + hswz;
                const size_t g = hrow_base + (size_t)p * 256;
                cpa16(d,         ah + g);
                cpa16(d + 4096,  ah + g + 64);
                cpa16(d + 8192,  ah + g + 128);
                cpa16(d + 12288, ah + g + 192);
                CP_COMMIT();
            };
            issue_pair(0);
            issue_pair(1);
            for (int p = 0; p < 4; p++) {
                if (p < 3) { CP_WAIT1(); } else { CP_WAIT0(); }
                __syncthreads();
                if (p + 2 < 4) issue_pair(p + 2);
                const uint32_t stg = sbase + HBUF + (uint32_t)(p % 3) * 16384;
                #pragma unroll
                for (int sub = 0; sub < 4; sub++) {
                    const uint32_t wc = (uint32_t)(4 * p + sub) * 4096;
                    const uint32_t hb = stg + sub * 4096;
                    #pragma unroll
                    for (int kk2 = 0; kk2 < 2; kk2++) {
                        uint32_t bH4[4], bL4[4];
                        uint32_t boff = wc + SWZ((uint32_t)(b_row * 128 + kk2 * 64 + b_ku * 16));
                        ldsm_x4(bH4, sbase + W_HI + boff);
                        ldsm_x4(bL4, sbase + W_LO + boff);
                        #pragma unroll
                        for (int kh = 0; kh < 2; kh++) {
                            const int ks = kk2 * 2 + kh;
                            uint32_t aH4[4];
                            uint32_t aoff = SWZ((uint32_t)(a_row * 128 + ks * 32 + a_k8 * 2));
                            ldsm_x4(aH4, hb + aoff);
                            mma_fp16(acc, aH4, &bH4[kh * 2]);
                            mma_fp16(acc, aH4, &bL4[kh * 2]);
                        }
                    }
                }
            }
            __syncthreads();
        }

        // epilogue: g = acc + pre[t] (prefetched)
        g_s[jloc * 33 + br]           = acc[0] + p0v.x;
        g_s[(jloc + 1) * 33 + br]     = acc[1] + p0v.y;
        g_s[jloc * 33 + br + 8]       = acc[2] + p1v.x;
        g_s[(jloc + 1) * 33 + br + 8] = acc[3] + p1v.y;
        __syncthreads();

        // pointwise
        {
            float gi = g_s[pu * 33 + pb];
            float gf = g_s[(8 + pu) * 33 + pb];
            float gg = g_s[(16 + pu) * 33 + pb];
            float go = g_s[(24 + pu) * 33 + pb];
            float si = 1.f / (1.f + expf(-gi));
            float sf = 1.f / (1.f + expf(-gf));
            float so = 1.f / (1.f + expf(-go));
            c_reg = sf * c_reg + si * tanhf(gg);
            float hn = so * tanhf(c_reg);
            ah[((size_t)pb * TSEQ + t) * HDIM + u0 + pu] = __float2half(hn);
        }
        __syncthreads();

        if (t + 1 < TSEQ) {
            const float* pt = pre + (size_t)(t + 1) * BATCH * G4;
            p0v = *(const float2*)(pt + (size_t)br * G4 + jrow_e);
            p1v = *(const float2*)(pt + (size_t)(br + 8) * G4 + jrow_e);

            gen++;
            if (tid == 0) {
                asm volatile("red.release.gpu.global.add.u32 [%0], 1;"
                             :: "l"(&g_bar_ctr) : "memory");
                unsigned tgt = gen * NBLK, v;
                do {
                    asm volatile("ld.acquire.gpu.global.u32 %0, [%1];"
                                 : "=r"(v) : "l"(&g_bar_ctr) : "memory");
                } while (v < tgt);
            }
            __syncthreads();
        }
    }
}

// ---------------- host launch --------------------------------------------
extern "C" void kernel_launch(void* const* d_in, const int* in_sizes, int n_in,
                              void* d_out, int out_size)
{
    const float* image = (const float*)d_in[0];
    const int*   caps  = (const int*)  d_in[1];
    const float* lin_W = (const float*)d_in[2];
    const float* lin_b = (const float*)d_in[3];
    const float* bn_g  = (const float*)d_in[4];
    const float* bn_b  = (const float*)d_in[5];
    const float* emb   = (const float*)d_in[6];
    const float* Wih0  = (const float*)d_in[7];
    const float* Whh0  = (const float*)d_in[8];
    const float* bih0  = (const float*)d_in[9];
    const float* bhh0  = (const float*)d_in[10];
    const float* Wih1  = (const float*)d_in[11];
    const float* Whh1  = (const float*)d_in[12];
    const float* bih1  = (const float*)d_in[13];
    const float* bhh1  = (const float*)d_in[14];
    const float* fc_W  = (const float*)d_in[15];
    const float* fc_b  = (const float*)d_in[16];
    float* out = (float*)d_out;

    float *pre;
    __half *ah, *w0, *w1, *fw;
    cudaGetSymbolAddress((void**)&pre, g_pre);
    cudaGetSymbolAddress((void**)&ah,  g_ah);
    cudaGetSymbolAddress((void**)&w0,  g_w0);
    cudaGetSymbolAddress((void**)&w1,  g_w1);
    cudaGetSymbolAddress((void**)&fw,  g_fw);

    static int smem_set = 0;
    const int GEMM_SMEM = 3 * GSTAGE + 1024;               // ~145KB
    const int LSTM_SMEM = 131072 + 49152 + 4224 + 256;     // ~180.5KB
    if (!smem_set) {
        cudaFuncSetAttribute(gemm_f16,
                             cudaFuncAttributeMaxDynamicSharedMemorySize, GEMM_SMEM);
        cudaFuncSetAttribute(lstm_persist,
                             cudaFuncAttributeMaxDynamicSharedMemorySize, LSTM_SMEM);
        smem_set = 1;
    }

    // inputs -> ah rows (K=EDIM layout, single fp16)
    linbn_kernel<<<EDIM, 256>>>(image, lin_W, lin_b, bn_g, bn_b, ah);
    gather_kernel<<<dim3(TSEQ - 1, BATCH), 128>>>(caps, emb, ah);

    // layer-0 input weights, then pre0 GEMM (resets bar for lstm0)
    cvt_f16<<<(G4 * EDIM / 4 + 255) / 256, 256>>>(Wih0, w0, G4 * EDIM);
    gemm_f16<<<dim3(MROWS / 128, G4 / 256), 256, GEMM_SMEM>>>(
        ah, w0, pre, MROWS, G4, EDIM, bih0, bhh0, 1);

    // remaining weight conversions
    cvt_f16<<<(G4 * HDIM / 4 + 255) / 256, 256>>>(Wih1, w1, G4 * HDIM);
    cvt_f16<<<(VOCAB * HDIM / 4 + 255) / 256, 256>>>(fc_W, fw, VOCAB * HDIM);

    // layer-0 recurrence
    lstm_persist<<<NBLK, 256, LSTM_SMEM>>>(pre, Whh0, ah);

    // pre1 = hs0 @ Wih1^T + biases (resets bar for lstm1)
    gemm_f16<<<dim3(MROWS / 128, G4 / 256), 256, GEMM_SMEM>>>(
        ah, w1, pre, MROWS, G4, HDIM, bih1, bhh1, 1);

    // layer-1 recurrence
    lstm_persist<<<NBLK, 256, LSTM_SMEM>>>(pre, Whh1, ah);

    // logits = ah @ fw^T + fc_b
    gemm_f16<<<dim3(MROWS / 128, VOCAB / 256), 256, GEMM_SMEM>>>(
        ah, fw, out, MROWS, VOCAB, HDIM, fc_b, nullptr, 0);
}